// round 7
// baseline (speedup 1.0000x reference)
#include <cuda_runtime.h>
#include <math.h>

#define NB 64
#define NS 50
#define NT 50
#define NR 2
#define NV 32000
#define NH 256
#define G3 768
#define NA 51

// output offsets (floats)
#define O_CTXOUT  0
#define O_CTXHID  819200
#define O_RESPOUT 835584
#define O_RESPHID 2473984
#define O_SPKEMB  2506752
#define O_SPKMASK 3342336

// ------------- device scratch (static globals; no runtime allocation) -------------
__device__ float g_tables[NB*NA*NH];
__device__ float g_TG[NV*G3];
__device__ float g_Hu0[NB*NS*NH];
__device__ float g_Hu1[NB*NS*NH];
__device__ float g_CIN[NS*NB*2*NH];
__device__ float g_CGI[NS*NB*G3];
__device__ float g_SGI[NS*NB*G3];
__device__ float g_RGI[NT*NB*NR*G3];
__device__ float g_Htab[NB*NA*NH];

// ------------- host: exact numpy legacy MT19937 agent tables (pure CPU) -------------
static float h_tables[NB*NA*NH];
namespace {
struct MT { 
    unsigned mt[624]; int mti;
    void seed(unsigned s){ mt[0]=s; for(int i=1;i<624;i++) mt[i]=1812433253u*(mt[i-1]^(mt[i-1]>>30))+(unsigned)i; mti=624; }
    unsigned next(){
        if(mti>=624){ for(int i=0;i<624;i++){ unsigned y=(mt[i]&0x80000000u)|(mt[(i+1)%624]&0x7fffffffu);
            mt[i]=mt[(i+397)%624]^(y>>1)^((y&1u)?0x9908b0dfu:0u);} mti=0; }
        unsigned y=mt[mti++]; y^=y>>11; y^=(y<<7)&0x9d2c5680u; y^=(y<<15)&0xefc60000u; y^=y>>18; return y;
    }
};
struct TabInit {
    TabInit(){
        MT m; m.seed(1u);
        for(long i=0;i<(long)NB*NA*NH;i++){
            unsigned a=m.next()>>5, b=m.next()>>6;
            h_tables[i]=(float)(((double)a*67108864.0+(double)b)*(1.0/9007199254740992.0));
        }
    }
} g_tabinit;
}

// ------------- generic SGEMM: C[M][768] = gather(A) @ W^T + bias -------------
// W [768][K] row-major. map!=0: row i -> map[(i&127)*NT + (i>>7)] (resp gather).
// grid (M/64, 12), block 256, 64x64 tile, BK=16, 4x4/thread.
__global__ __launch_bounds__(256) void k_sgemm(
    const float* __restrict__ A, const int* __restrict__ map, int K,
    const float* __restrict__ W, const float* __restrict__ bias, float* __restrict__ C)
{
    __shared__ float As[16][68];
    __shared__ float Bs[16][68];
    int tx = threadIdx.x & 15, ty = threadIdx.x >> 4;
    int m0 = blockIdx.x * 64, n0 = blockIdx.y * 64;
    int e = threadIdx.x * 4, lr = e >> 4, lk = e & 15;
    int arow = m0 + lr;
    int row = map ? map[(arow & 127) * NT + (arow >> 7)] : arow;
    const float* ap = A + (long)row * K + lk;
    const float* wp = W + (long)(n0 + lr) * K + lk;
    float acc[4][4] = {};
    for (int k0 = 0; k0 < K; k0 += 16) {
        float4 av = *(const float4*)(ap + k0);
        float4 wv = *(const float4*)(wp + k0);
        As[lk+0][lr]=av.x; As[lk+1][lr]=av.y; As[lk+2][lr]=av.z; As[lk+3][lr]=av.w;
        Bs[lk+0][lr]=wv.x; Bs[lk+1][lr]=wv.y; Bs[lk+2][lr]=wv.z; Bs[lk+3][lr]=wv.w;
        __syncthreads();
        #pragma unroll
        for (int k = 0; k < 16; k++) {
            float4 a = *(const float4*)&As[k][ty*4];
            float4 b = *(const float4*)&Bs[k][tx*4];
            float ar[4]={a.x,a.y,a.z,a.w}, br[4]={b.x,b.y,b.z,b.w};
            #pragma unroll
            for (int i=0;i<4;i++)
                #pragma unroll
                for (int j=0;j<4;j++) acc[i][j] += ar[i]*br[j];
        }
        __syncthreads();
    }
    float4 bs = *(const float4*)(bias + n0 + tx*4);
    #pragma unroll
    for (int i=0;i<4;i++) {
        float4 o; o.x=acc[i][0]+bs.x; o.y=acc[i][1]+bs.y; o.z=acc[i][2]+bs.z; o.w=acc[i][3]+bs.w;
        *(float4*)(C + (long)(m0+ty*4+i)*G3 + n0 + tx*4) = o;
    }
}

// ------------- fused utterance GRU step: gh = Hin@Whh^T, gi gathered from g_TG -------------
// grid (50, 8): 64 rows x 32 j (x3 gates) per block, block 256.
__global__ __launch_bounds__(256) void k_ustep(
    const float* __restrict__ Whh, const float* __restrict__ bhh,
    const int* __restrict__ tokens, int t, int swap)
{
    __shared__ float As[16][68];
    __shared__ float Ws[3][16][36];
    const float* Hin  = swap ? g_Hu1 : g_Hu0;
    float*       Hout = swap ? g_Hu0 : g_Hu1;
    int tx = threadIdx.x & 15, ty = threadIdx.x >> 4;
    int m0 = blockIdx.x * 64, j0 = blockIdx.y * 32;
    int ea = threadIdx.x * 4, lra = ea >> 4, lka = ea & 15;
    int ew = threadIdx.x * 2, nw = ew >> 4, kw = ew & 15;
    float acc[3][4][2] = {};
    for (int k0 = 0; k0 < NH; k0 += 16) {
        float4 av = *(const float4*)(Hin + (m0+lra)*NH + k0 + lka);
        As[lka+0][lra]=av.x; As[lka+1][lra]=av.y; As[lka+2][lra]=av.z; As[lka+3][lra]=av.w;
        #pragma unroll
        for (int g=0; g<3; g++) {
            float2 wv = *(const float2*)(Whh + (g*NH + j0 + nw)*NH + k0 + kw);
            Ws[g][kw][nw]=wv.x; Ws[g][kw+1][nw]=wv.y;
        }
        __syncthreads();
        #pragma unroll
        for (int k=0;k<16;k++) {
            float4 a = *(const float4*)&As[k][ty*4];
            float ar[4]={a.x,a.y,a.z,a.w};
            #pragma unroll
            for (int g=0;g<3;g++) {
                float2 w = *(const float2*)&Ws[g][k][tx*2];
                #pragma unroll
                for (int i=0;i<4;i++) { acc[g][i][0]+=ar[i]*w.x; acc[g][i][1]+=ar[i]*w.y; }
            }
        }
        __syncthreads();
    }
    #pragma unroll
    for (int i=0;i<4;i++) {
        int m = m0 + ty*4 + i;
        const float* gi = g_TG + (long)tokens[m*NT + t] * G3;
        #pragma unroll
        for (int jj=0;jj<2;jj++) {
            int j = j0 + tx*2 + jj;
            float r = 1.f/(1.f+expf(-(gi[j]      + acc[0][i][jj] + bhh[j])));
            float z = 1.f/(1.f+expf(-(gi[NH+j]   + acc[1][i][jj] + bhh[NH+j])));
            float n = tanhf(gi[2*NH+j] + r*(acc[2][i][jj] + bhh[2*NH+j]));
            Hout[m*NH + j] = (1.f - z)*n + z*Hin[m*NH + j];
        }
    }
}

// ------------- persistent GRU helpers -------------
__device__ __forceinline__ float dot8(const float* w, int lane, float4 a, float4 b) {
    float4 x = *(const float4*)(w + lane*4);
    float4 y = *(const float4*)(w + 128 + lane*4);
    return x.x*a.x + x.y*a.y + x.z*a.z + x.w*a.w
         + y.x*b.x + y.y*b.y + y.z*b.z + y.w*b.w;
}
__device__ __forceinline__ float wsum(float v) {
    #pragma unroll
    for (int m=16; m; m>>=1) v += __shfl_xor_sync(0xffffffffu, v, m);
    return v;
}
__device__ __forceinline__ float gru_j(
    const float* __restrict__ Whh, const float* __restrict__ bhh,
    const float* __restrict__ gi, int j, int lane, float4 h0, float4 h1, float hold)
{
    float s0 = wsum(dot8(Whh + j*NH,        lane, h0, h1));
    float s1 = wsum(dot8(Whh + (NH+j)*NH,   lane, h0, h1));
    float s2 = wsum(dot8(Whh + (2*NH+j)*NH, lane, h0, h1));
    float r = 1.f/(1.f+expf(-(gi[j]    + s0 + bhh[j])));
    float z = 1.f/(1.f+expf(-(gi[NH+j] + s1 + bhh[NH+j])));
    float n = tanhf(gi[2*NH+j] + r*(s2 + bhh[2*NH+j]));
    return (1.f - z)*n + z*hold;
}

// ------------- unified ctx (mode 0, grid 64) / resp (mode 1, grid 128) GRU -------------
__global__ __launch_bounds__(256) void k_rnn(
    const float* __restrict__ Whh, const float* __restrict__ bhh,
    const float* __restrict__ GI, float* __restrict__ out, int mode)
{
    __shared__ float H[NH];
    int m = blockIdx.x, tid = threadIdx.x, lane = tid & 31, w = tid >> 5;
    H[tid] = 0.f;
    for (int t=0; t<NS; t++) {
        __syncthreads();
        float4 h0 = *(const float4*)&H[lane*4];
        float4 h1 = *(const float4*)&H[128 + lane*4];
        const float* gi = GI + (long)(mode ? (t*128+m) : (t*64+m)) * G3;
        float* po = mode ? out + O_RESPOUT + (long)(((m&1)*NT+t)*64 + (m>>1))*NH
                         : out + O_CTXOUT  + (long)(t*64 + m)*NH;
        __syncthreads();
        for (int jj=0; jj<32; jj++) {
            int j = w*32 + jj;
            float hn = gru_j(Whh, bhh, gi, j, lane, h0, h1, H[j]);
            if (lane == 0) { H[j] = hn; po[j] = hn; }
        }
    }
    __syncthreads();
    float* pf = mode ? out + O_RESPHID + (long)((m&1)*64 + (m>>1))*NH
                     : out + O_CTXHID  + (long)m*NH;
    pf[tid] = H[tid];
}

// ------------- speaker GRU: one block per b; only the active speaker row updates -------------
__global__ __launch_bounds__(256) void k_spk(
    const float* __restrict__ Whh, const float* __restrict__ bhh,
    const int* __restrict__ spk, float* __restrict__ out)
{
    __shared__ int flag[NA];
    int b = blockIdx.x, tid = threadIdx.x, lane = tid & 31, w = tid >> 5;
    float* tab = g_Htab + (long)b*NA*NH;
    for (int i=tid; i<NA*NH; i+=256) tab[i] = 0.f;
    if (tid < NA) flag[tid] = 0;
    for (int s=0; s<NS; s++) {
        __syncthreads();
        int a = spk[b*NS + s];
        if (tid == 0) flag[a] = 1;
        const float* hr = tab + a*NH;
        float4 h0 = *(const float4*)(hr + lane*4);
        float4 h1 = *(const float4*)(hr + 128 + lane*4);
        const float* gi = g_SGI + (long)(s*64 + b) * G3;
        __syncthreads();
        for (int jj=0; jj<32; jj++) {
            int j = w*32 + jj;
            float hn = gru_j(Whh, bhh, gi, j, lane, h0, h1, hr[j]);
            if (lane == 0) tab[a*NH + j] = hn;
        }
    }
    __syncthreads();
    for (int i=tid; i<NA*NH; i+=256)
        out[O_SPKEMB + (long)b*NA*NH + i] = flag[i>>8] ? tab[i] : 0.f;
    if (tid < NA) out[O_SPKMASK + b*NA + tid] = (flag[tid] && tid > 0) ? 1.f : 0.f;
}

// ------------- ctx GRU input: concat(utter_hidden, agent_emb) -------------
__global__ void k_cin(const int* __restrict__ spk) {
    int idx = blockIdx.x * 256 + threadIdx.x;     // < 3200*512
    int c = idx & 511, mr = idx >> 9;             // mr = s*64 + b
    int s = mr >> 6, b = mr & 63;
    float v;
    if (c < NH) v = g_Hu0[(b*NS + s)*NH + c];
    else        v = g_tables[(b*NA + spk[b*NS + s])*NH + (c - NH)];
    g_CIN[idx] = v;
}

// ------------- launch -------------
extern "C" void kernel_launch(void* const* d_in, const int* in_sizes, int n_in,
                              void* d_out, int out_size) {
    (void)in_sizes; (void)n_in; (void)out_size;
    const int*   context = (const int*)d_in[0];
    const int*   response= (const int*)d_in[1];
    const int*   spk     = (const int*)d_in[2];
    const float* emb_u   = (const float*)d_in[3];
    const float* emb_r   = (const float*)d_in[4];
    const float* uWih=(const float*)d_in[5],  *uWhh=(const float*)d_in[6];
    const float* ubih=(const float*)d_in[7],  *ubhh=(const float*)d_in[8];
    const float* cWih=(const float*)d_in[9],  *cWhh=(const float*)d_in[10];
    const float* cbih=(const float*)d_in[11], *cbhh=(const float*)d_in[12];
    const float* rWih=(const float*)d_in[13], *rWhh=(const float*)d_in[14];
    const float* rbih=(const float*)d_in[15], *rbhh=(const float*)d_in[16];
    const float* sWih=(const float*)d_in[17], *sWhh=(const float*)d_in[18];
    const float* sbih=(const float*)d_in[19], *sbhh=(const float*)d_in[20];
    float* out = (float*)d_out;

    void *pTab, *pTG, *pHu0, *pCIN, *pCGI, *pSGI, *pRGI;
    cudaGetSymbolAddress(&pTab, g_tables);
    cudaGetSymbolAddress(&pTG,  g_TG);
    cudaGetSymbolAddress(&pHu0, g_Hu0);
    cudaGetSymbolAddress(&pCIN, g_CIN);
    cudaGetSymbolAddress(&pCGI, g_CGI);
    cudaGetSymbolAddress(&pSGI, g_SGI);
    cudaGetSymbolAddress(&pRGI, g_RGI);

    cudaMemcpyAsync(pTab, h_tables, sizeof(h_tables), cudaMemcpyHostToDevice, 0);
    cudaMemsetAsync(pHu0, 0, (size_t)NB*NS*NH*sizeof(float), 0);

    // utterance token-gate table + recurrence
    k_sgemm<<<dim3(NV/64, 12), 256>>>(emb_u, nullptr, NH, uWih, ubih, (float*)pTG);
    for (int t=0; t<NT; t++)
        k_ustep<<<dim3(50, 8), 256>>>(uWhh, ubhh, context, t, t & 1);

    // context GRU
    k_cin<<<6400, 256>>>(spk);
    k_sgemm<<<dim3(50, 12), 256>>>((const float*)pCIN, nullptr, 2*NH, cWih, cbih, (float*)pCGI);
    k_rnn<<<64, 256>>>(cWhh, cbhh, (const float*)pCGI, out, 0);

    // speaker GRU (input = context_output)
    k_sgemm<<<dim3(50, 12), 256>>>(out + O_CTXOUT, nullptr, NH, sWih, sbih, (float*)pSGI);
    k_spk<<<64, 256>>>(sWhh, sbhh, spk, out);

    // response GRU
    k_sgemm<<<dim3(100, 12), 256>>>(emb_r, response, NH, rWih, rbih, (float*)pRGI);
    k_rnn<<<128, 256>>>(rWhh, rbhh, (const float*)pRGI, out, 1);
}

// round 8
// speedup vs baseline: 1.3228x; 1.3228x over previous
#include <cuda_runtime.h>
#include <math.h>

#define NB 64
#define NS 50
#define NT 50
#define NR 2
#define NV 32000
#define NH 256
#define G3 768
#define NA 51

// output offsets (floats)
#define O_CTXOUT  0
#define O_CTXHID  819200
#define O_RESPOUT 835584
#define O_RESPHID 2473984
#define O_SPKEMB  2506752
#define O_SPKMASK 3342336

// persistent ustep tiling
#define UROWS 128
#define UJT 16
#define UTILES 400          // (3200/128) * (256/16)
#define WPITCH 260
#define APITCH 132
#define USMEM (48*WPITCH*4 + 2*16*APITCH*4)   // 49920 + 16896 = 66816

// ------------- device scratch (static globals; no runtime allocation) -------------
__device__ float g_tables[NB*NA*NH];
__device__ float g_TG[NV*G3];
__device__ float g_Hu0[NB*NS*NH];
__device__ float g_Hu1[NB*NS*NH];
__device__ float g_CIN[NS*NB*2*NH];
__device__ float g_CGI[NS*NB*G3];
__device__ float g_SGI[NS*NB*G3];
__device__ float g_RGI[NT*NB*NR*G3];
__device__ float g_Htab[NB*NA*NH];
__device__ unsigned g_ubar;

// ------------- host: exact numpy legacy MT19937 agent tables (pure CPU) -------------
static float h_tables[NB*NA*NH];
static cudaStream_t g_s2;
static cudaEvent_t g_evFork, g_evJoin;
namespace {
struct MT {
    unsigned mt[624]; int mti;
    void seed(unsigned s){ mt[0]=s; for(int i=1;i<624;i++) mt[i]=1812433253u*(mt[i-1]^(mt[i-1]>>30))+(unsigned)i; mti=624; }
    unsigned next(){
        if(mti>=624){ for(int i=0;i<624;i++){ unsigned y=(mt[i]&0x80000000u)|(mt[(i+1)%624]&0x7fffffffu);
            mt[i]=mt[(i+397)%624]^(y>>1)^((y&1u)?0x9908b0dfu:0u);} mti=0; }
        unsigned y=mt[mti++]; y^=y>>11; y^=(y<<7)&0x9d2c5680u; y^=(y<<15)&0xefc60000u; y^=y>>18; return y;
    }
};
struct TabInit {
    TabInit(){
        MT m; m.seed(1u);
        for(long i=0;i<(long)NB*NA*NH;i++){
            unsigned a=m.next()>>5, b=m.next()>>6;
            h_tables[i]=(float)(((double)a*67108864.0+(double)b)*(1.0/9007199254740992.0));
        }
        cudaStreamCreateWithFlags(&g_s2, cudaStreamNonBlocking);
        cudaEventCreateWithFlags(&g_evFork, cudaEventDisableTiming);
        cudaEventCreateWithFlags(&g_evJoin, cudaEventDisableTiming);
    }
} g_tabinit;
}

// ------------- generic SGEMM: C[M][768] = gather(A) @ W^T + bias -------------
__global__ __launch_bounds__(256) void k_sgemm(
    const float* __restrict__ A, const int* __restrict__ map, int K,
    const float* __restrict__ W, const float* __restrict__ bias, float* __restrict__ C)
{
    __shared__ float As[16][68];
    __shared__ float Bs[16][68];
    int tx = threadIdx.x & 15, ty = threadIdx.x >> 4;
    int m0 = blockIdx.x * 64, n0 = blockIdx.y * 64;
    int e = threadIdx.x * 4, lr = e >> 4, lk = e & 15;
    int arow = m0 + lr;
    int row = map ? map[(arow & 127) * NT + (arow >> 7)] : arow;
    const float* ap = A + (long)row * K + lk;
    const float* wp = W + (long)(n0 + lr) * K + lk;
    float acc[4][4] = {};
    for (int k0 = 0; k0 < K; k0 += 16) {
        float4 av = *(const float4*)(ap + k0);
        float4 wv = *(const float4*)(wp + k0);
        As[lk+0][lr]=av.x; As[lk+1][lr]=av.y; As[lk+2][lr]=av.z; As[lk+3][lr]=av.w;
        Bs[lk+0][lr]=wv.x; Bs[lk+1][lr]=wv.y; Bs[lk+2][lr]=wv.z; Bs[lk+3][lr]=wv.w;
        __syncthreads();
        #pragma unroll
        for (int k = 0; k < 16; k++) {
            float4 a = *(const float4*)&As[k][ty*4];
            float4 b = *(const float4*)&Bs[k][tx*4];
            float ar[4]={a.x,a.y,a.z,a.w}, br[4]={b.x,b.y,b.z,b.w};
            #pragma unroll
            for (int i=0;i<4;i++)
                #pragma unroll
                for (int j=0;j<4;j++) acc[i][j] += ar[i]*br[j];
        }
        __syncthreads();
    }
    float4 bs = *(const float4*)(bias + n0 + tx*4);
    #pragma unroll
    for (int i=0;i<4;i++) {
        float4 o; o.x=acc[i][0]+bs.x; o.y=acc[i][1]+bs.y; o.z=acc[i][2]+bs.z; o.w=acc[i][3]+bs.w;
        *(float4*)(C + (long)(m0+ty*4+i)*G3 + n0 + tx*4) = o;
    }
}

// ------------- persistent utterance GRU: all 50 steps, grid barrier, Whh resident -------------
extern __shared__ float usm[];
__global__ __launch_bounds__(128, 3) void k_ustep_pers(
    const float* __restrict__ Whh, const float* __restrict__ bhh,
    const int* __restrict__ tokens)
{
    float* Wsm = usm;                    // [48][WPITCH]
    float* Asm = usm + 48*WPITCH;        // [2][16][APITCH]
    int tid = threadIdx.x;
    int tx = tid & 7;                    // j pair 0..7
    int ty = tid >> 3;                   // row group 0..15 (8 rows each)
    int m0 = blockIdx.x * UROWS;
    int j0 = blockIdx.y * UJT;
    int jb = j0 + (tx << 1);

    // load Whh slice once: rows g*NH + j0 + jj, all 256 k
    for (int i = tid; i < 48*64; i += 128) {
        int r = i >> 6, q = i & 63;
        int g = r >> 4, jj = r & 15;
        float4 v = *(const float4*)(Whh + (long)(g*NH + j0 + jj)*NH + q*4);
        *(float4*)&Wsm[r*WPITCH + q*4] = v;
    }
    float bh[3][2];
    #pragma unroll
    for (int g=0; g<3; g++) { bh[g][0] = bhh[g*NH + jb]; bh[g][1] = bhh[g*NH + jb + 1]; }
    __syncthreads();

    for (int t = 0; t < NT; t++) {
        const float* Hin  = (t & 1) ? g_Hu1 : g_Hu0;
        float*       Hout = (t & 1) ? g_Hu0 : g_Hu1;
        float acc[3][8][2] = {};
        // prefetch chunk 0
        float4 ld[4];
        #pragma unroll
        for (int q=0; q<4; q++) {
            int idx = q*128 + tid, row = idx >> 2, kq = idx & 3;
            ld[q] = *(const float4*)(Hin + (long)(m0+row)*NH + kq*4);
        }
        int buf = 0;
        for (int c = 0; c < 16; c++) {
            float* Ab = Asm + buf*16*APITCH;
            #pragma unroll
            for (int q=0; q<4; q++) {
                int idx = q*128 + tid, row = idx >> 2, kq = idx & 3;
                Ab[(kq*4+0)*APITCH + row] = ld[q].x;
                Ab[(kq*4+1)*APITCH + row] = ld[q].y;
                Ab[(kq*4+2)*APITCH + row] = ld[q].z;
                Ab[(kq*4+3)*APITCH + row] = ld[q].w;
            }
            __syncthreads();
            if (c < 15) {
                #pragma unroll
                for (int q=0; q<4; q++) {
                    int idx = q*128 + tid, row = idx >> 2, kq = idx & 3;
                    ld[q] = *(const float4*)(Hin + (long)(m0+row)*NH + (c+1)*16 + kq*4);
                }
            }
            #pragma unroll
            for (int k4 = 0; k4 < 16; k4 += 4) {
                float4 w[3][2];
                #pragma unroll
                for (int g=0; g<3; g++)
                    #pragma unroll
                    for (int jj=0; jj<2; jj++)
                        w[g][jj] = *(const float4*)&Wsm[(g*16 + (tx<<1)+jj)*WPITCH + c*16 + k4];
                #pragma unroll
                for (int kk=0; kk<4; kk++) {
                    const float* ak = Ab + (k4+kk)*APITCH + (ty<<3);
                    float4 a0 = *(const float4*)ak;
                    float4 a1 = *(const float4*)(ak + 4);
                    float a[8] = {a0.x,a0.y,a0.z,a0.w,a1.x,a1.y,a1.z,a1.w};
                    #pragma unroll
                    for (int g=0; g<3; g++) {
                        float w0 = (&w[g][0].x)[kk];
                        float w1 = (&w[g][1].x)[kk];
                        #pragma unroll
                        for (int r=0; r<8; r++) {
                            acc[g][r][0] += a[r]*w0;
                            acc[g][r][1] += a[r]*w1;
                        }
                    }
                }
            }
            __syncthreads();
            buf ^= 1;
        }
        // epilogue: gates + h update for 8 rows x 2 j
        #pragma unroll
        for (int r=0; r<8; r++) {
            int m = m0 + (ty<<3) + r;
            int tok = tokens[m*NT + t];
            const float* gi = g_TG + (long)tok * G3;
            float h0v = Hin[(long)m*NH + jb];
            float h1v = Hin[(long)m*NH + jb + 1];
            float rr0 = 1.f/(1.f+expf(-(gi[jb]       + acc[0][r][0] + bh[0][0])));
            float zz0 = 1.f/(1.f+expf(-(gi[NH+jb]    + acc[1][r][0] + bh[1][0])));
            float nn0 = tanhf(gi[2*NH+jb] + rr0*(acc[2][r][0] + bh[2][0]));
            Hout[(long)m*NH + jb] = (1.f - zz0)*nn0 + zz0*h0v;
            float rr1 = 1.f/(1.f+expf(-(gi[jb+1]     + acc[0][r][1] + bh[0][1])));
            float zz1 = 1.f/(1.f+expf(-(gi[NH+jb+1]  + acc[1][r][1] + bh[1][1])));
            float nn1 = tanhf(gi[2*NH+jb+1] + rr1*(acc[2][r][1] + bh[2][1]));
            Hout[(long)m*NH + jb + 1] = (1.f - zz1)*nn1 + zz1*h1v;
        }
        // device-wide barrier (skip after last step)
        if (t < NT-1) {
            __threadfence();
            __syncthreads();
            if (tid == 0) {
                unsigned target = (unsigned)UTILES * (t + 1);
                atomicAdd(&g_ubar, 1u);
                while (*(volatile unsigned*)&g_ubar < target) __nanosleep(64);
                __threadfence();
            }
            __syncthreads();
        }
    }
}

// ------------- persistent GRU helpers -------------
__device__ __forceinline__ float dot8(const float* w, int lane, float4 a, float4 b) {
    float4 x = *(const float4*)(w + lane*4);
    float4 y = *(const float4*)(w + 128 + lane*4);
    return x.x*a.x + x.y*a.y + x.z*a.z + x.w*a.w
         + y.x*b.x + y.y*b.y + y.z*b.z + y.w*b.w;
}
__device__ __forceinline__ float wsum(float v) {
    #pragma unroll
    for (int m=16; m; m>>=1) v += __shfl_xor_sync(0xffffffffu, v, m);
    return v;
}
__device__ __forceinline__ float gru_j(
    const float* __restrict__ Whh, const float* __restrict__ bhh,
    const float* __restrict__ gi, int j, int lane, float4 h0, float4 h1, float hold)
{
    float s0 = wsum(dot8(Whh + j*NH,        lane, h0, h1));
    float s1 = wsum(dot8(Whh + (NH+j)*NH,   lane, h0, h1));
    float s2 = wsum(dot8(Whh + (2*NH+j)*NH, lane, h0, h1));
    float r = 1.f/(1.f+expf(-(gi[j]    + s0 + bhh[j])));
    float z = 1.f/(1.f+expf(-(gi[NH+j] + s1 + bhh[NH+j])));
    float n = tanhf(gi[2*NH+j] + r*(s2 + bhh[2*NH+j]));
    return (1.f - z)*n + z*hold;
}

// ------------- unified ctx (mode 0, grid 64) / resp (mode 1, grid 128) GRU; 512 thr -------------
__global__ __launch_bounds__(512) void k_rnn(
    const float* __restrict__ Whh, const float* __restrict__ bhh,
    const float* __restrict__ GI, float* __restrict__ out, int mode)
{
    __shared__ float H[NH];
    int m = blockIdx.x, tid = threadIdx.x, lane = tid & 31, w = tid >> 5;
    if (tid < NH) H[tid] = 0.f;
    for (int t=0; t<NS; t++) {
        __syncthreads();
        float4 h0 = *(const float4*)&H[lane*4];
        float4 h1 = *(const float4*)&H[128 + lane*4];
        const float* gi = GI + (long)(mode ? (t*128+m) : (t*64+m)) * G3;
        float* po = mode ? out + O_RESPOUT + (long)(((m&1)*NT+t)*64 + (m>>1))*NH
                         : out + O_CTXOUT  + (long)(t*64 + m)*NH;
        __syncthreads();
        for (int jj=0; jj<16; jj++) {
            int j = w*16 + jj;
            float hn = gru_j(Whh, bhh, gi, j, lane, h0, h1, H[j]);
            if (lane == 0) { H[j] = hn; po[j] = hn; }
        }
    }
    __syncthreads();
    if (tid < NH) {
        float* pf = mode ? out + O_RESPHID + (long)((m&1)*64 + (m>>1))*NH
                         : out + O_CTXHID  + (long)m*NH;
        pf[tid] = H[tid];
    }
}

// ------------- speaker GRU: one block per b; only the active speaker row updates -------------
__global__ __launch_bounds__(512) void k_spk(
    const float* __restrict__ Whh, const float* __restrict__ bhh,
    const int* __restrict__ spk, float* __restrict__ out)
{
    __shared__ int flag[NA];
    int b = blockIdx.x, tid = threadIdx.x, lane = tid & 31, w = tid >> 5;
    float* tab = g_Htab + (long)b*NA*NH;
    for (int i=tid; i<NA*NH; i+=512) tab[i] = 0.f;
    if (tid < NA) flag[tid] = 0;
    for (int s=0; s<NS; s++) {
        __syncthreads();
        int a = spk[b*NS + s];
        if (tid == 0) flag[a] = 1;
        const float* hr = tab + a*NH;
        float4 h0 = *(const float4*)(hr + lane*4);
        float4 h1 = *(const float4*)(hr + 128 + lane*4);
        const float* gi = g_SGI + (long)(s*64 + b) * G3;
        __syncthreads();
        for (int jj=0; jj<16; jj++) {
            int j = w*16 + jj;
            float hn = gru_j(Whh, bhh, gi, j, lane, h0, h1, hr[j]);
            if (lane == 0) tab[a*NH + j] = hn;
        }
    }
    __syncthreads();
    for (int i=tid; i<NA*NH; i+=512)
        out[O_SPKEMB + (long)b*NA*NH + i] = flag[i>>8] ? tab[i] : 0.f;
    if (tid < NA) out[O_SPKMASK + b*NA + tid] = (flag[tid] && tid > 0) ? 1.f : 0.f;
}

// ------------- ctx GRU input: concat(utter_hidden, agent_emb) -------------
__global__ void k_cin(const int* __restrict__ spk) {
    int idx = blockIdx.x * 256 + threadIdx.x;     // < 3200*512
    int c = idx & 511, mr = idx >> 9;             // mr = s*64 + b
    int s = mr >> 6, b = mr & 63;
    float v;
    if (c < NH) v = g_Hu0[(b*NS + s)*NH + c];
    else        v = g_tables[(b*NA + spk[b*NS + s])*NH + (c - NH)];
    g_CIN[idx] = v;
}

// ------------- launch -------------
extern "C" void kernel_launch(void* const* d_in, const int* in_sizes, int n_in,
                              void* d_out, int out_size) {
    (void)in_sizes; (void)n_in; (void)out_size;
    const int*   context = (const int*)d_in[0];
    const int*   response= (const int*)d_in[1];
    const int*   spk     = (const int*)d_in[2];
    const float* emb_u   = (const float*)d_in[3];
    const float* emb_r   = (const float*)d_in[4];
    const float* uWih=(const float*)d_in[5],  *uWhh=(const float*)d_in[6];
    const float* ubih=(const float*)d_in[7],  *ubhh=(const float*)d_in[8];
    const float* cWih=(const float*)d_in[9],  *cWhh=(const float*)d_in[10];
    const float* cbih=(const float*)d_in[11], *cbhh=(const float*)d_in[12];
    const float* rWih=(const float*)d_in[13], *rWhh=(const float*)d_in[14];
    const float* rbih=(const float*)d_in[15], *rbhh=(const float*)d_in[16];
    const float* sWih=(const float*)d_in[17], *sWhh=(const float*)d_in[18];
    const float* sbih=(const float*)d_in[19], *sbhh=(const float*)d_in[20];
    float* out = (float*)d_out;

    void *pTab, *pTG, *pHu0, *pCIN, *pCGI, *pSGI, *pRGI, *pBar;
    cudaGetSymbolAddress(&pTab, g_tables);
    cudaGetSymbolAddress(&pTG,  g_TG);
    cudaGetSymbolAddress(&pHu0, g_Hu0);
    cudaGetSymbolAddress(&pCIN, g_CIN);
    cudaGetSymbolAddress(&pCGI, g_CGI);
    cudaGetSymbolAddress(&pSGI, g_SGI);
    cudaGetSymbolAddress(&pRGI, g_RGI);
    cudaGetSymbolAddress(&pBar, g_ubar);

    cudaFuncSetAttribute(k_ustep_pers, cudaFuncAttributeMaxDynamicSharedMemorySize, USMEM);

    cudaMemcpyAsync(pTab, h_tables, sizeof(h_tables), cudaMemcpyHostToDevice, 0);
    cudaMemsetAsync(pHu0, 0, (size_t)NB*NS*NH*sizeof(float), 0);
    cudaMemsetAsync(pBar, 0, sizeof(unsigned), 0);

    // utterance token-gate table + persistent recurrence
    k_sgemm<<<dim3(NV/64, 12), 256>>>(emb_u, nullptr, NH, uWih, ubih, (float*)pTG);
    k_ustep_pers<<<dim3(25, 16), 128, USMEM>>>(uWhh, ubhh, context);

    // fork: response branch overlaps the ctx/spk chain
    cudaEventRecord(g_evFork, 0);
    cudaStreamWaitEvent(g_s2, g_evFork, 0);
    k_sgemm<<<dim3(100, 12), 256, 0, g_s2>>>(emb_r, response, NH, rWih, rbih, (float*)pRGI);
    k_rnn<<<128, 512, 0, g_s2>>>(rWhh, rbhh, (const float*)pRGI, out, 1);
    cudaEventRecord(g_evJoin, g_s2);

    // context GRU
    k_cin<<<6400, 256>>>(spk);
    k_sgemm<<<dim3(50, 12), 256>>>((const float*)pCIN, nullptr, 2*NH, cWih, cbih, (float*)pCGI);
    k_rnn<<<64, 512>>>(cWhh, cbhh, (const float*)pCGI, out, 0);

    // speaker GRU (input = context_output)
    k_sgemm<<<dim3(50, 12), 256>>>(out + O_CTXOUT, nullptr, NH, sWih, sbih, (float*)pSGI);
    k_spk<<<64, 512>>>(sWhh, sbhh, spk, out);

    // join
    cudaStreamWaitEvent(0, g_evJoin, 0);
}

// round 9
// speedup vs baseline: 1.3442x; 1.0162x over previous
#include <cuda_runtime.h>
#include <math.h>

#define NB 64
#define NS 50
#define NT 50
#define NR 2
#define NV 32000
#define NH 256
#define G3 768
#define NA 51

// output offsets (floats)
#define O_CTXOUT  0
#define O_CTXHID  819200
#define O_RESPOUT 835584
#define O_RESPHID 2473984
#define O_SPKEMB  2506752
#define O_SPKMASK 3342336

// persistent ustep tiling
#define UROWS 128
#define UJT 16
#define UTILES 400
#define WPITCH 260
#define APITCH 132
#define USMEM (48*WPITCH*4 + 2*16*APITCH*4)

// persistent small-RNN smem: Wsm 48x260 + Asm 32x260 + flags 32x51
#define RSMEM (48*260*4 + 32*260*4 + 32*51*4)

// ------------- device scratch -------------
__device__ float g_tables[NB*NA*NH];
__device__ float g_TG[NV*G3];
__device__ float g_Hu0[NB*NS*NH];
__device__ float g_Hu1[NB*NS*NH];
__device__ float g_CIN[NS*NB*2*NH];
__device__ float g_CGI[NS*NB*G3];
__device__ float g_SGI[NS*NB*G3];
__device__ float g_RGI[NT*NB*NR*G3];
__device__ float g_Htab[NB*NA*NH];
__device__ unsigned g_ubar;
__device__ unsigned g_bar2[4];

// ------------- host: exact numpy legacy MT19937 agent tables -------------
static float h_tables[NB*NA*NH];
static cudaStream_t g_s2;
static cudaEvent_t g_evFork, g_evJoin;
namespace {
struct MT {
    unsigned mt[624]; int mti;
    void seed(unsigned s){ mt[0]=s; for(int i=1;i<624;i++) mt[i]=1812433253u*(mt[i-1]^(mt[i-1]>>30))+(unsigned)i; mti=624; }
    unsigned next(){
        if(mti>=624){ for(int i=0;i<624;i++){ unsigned y=(mt[i]&0x80000000u)|(mt[(i+1)%624]&0x7fffffffu);
            mt[i]=mt[(i+397)%624]^(y>>1)^((y&1u)?0x9908b0dfu:0u);} mti=0; }
        unsigned y=mt[mti++]; y^=y>>11; y^=(y<<7)&0x9d2c5680u; y^=(y<<15)&0xefc60000u; y^=y>>18; return y;
    }
};
struct TabInit {
    TabInit(){
        MT m; m.seed(1u);
        for(long i=0;i<(long)NB*NA*NH;i++){
            unsigned a=m.next()>>5, b=m.next()>>6;
            h_tables[i]=(float)(((double)a*67108864.0+(double)b)*(1.0/9007199254740992.0));
        }
        cudaStreamCreateWithFlags(&g_s2, cudaStreamNonBlocking);
        cudaEventCreateWithFlags(&g_evFork, cudaEventDisableTiming);
        cudaEventCreateWithFlags(&g_evJoin, cudaEventDisableTiming);
    }
} g_tabinit;
}

// ------------- 128x128x8 double-buffered SGEMM: C[M][768] = gather(A) @ W^T + bias -------------
// grid (M/128, 6), block 256, 8x8/thread (split 4+4 rows/cols).
__global__ __launch_bounds__(256) void k_gemm128(
    const float* __restrict__ A, const int* __restrict__ map, int K,
    const float* __restrict__ W, const float* __restrict__ bias, float* __restrict__ C)
{
    __shared__ float As[2][8][132];
    __shared__ float Bs[2][8][132];
    int tid = threadIdx.x;
    int m0 = blockIdx.x * 128, n0 = blockIdx.y * 128;
    int tx = tid & 15, ty = tid >> 4;
    int lr = tid >> 1, lk = (tid & 1) * 4;
    int arow = m0 + lr;
    int row = map ? map[(arow & 127) * NT + (arow >> 7)] : arow;
    const float* ap = A + (long)row * K + lk;
    const float* wp = W + (long)(n0 + lr) * K + lk;
    float acc[8][8] = {};
    float4 av = *(const float4*)ap;
    float4 wv = *(const float4*)wp;
    int buf = 0;
    for (int k0 = 0; k0 < K; k0 += 8) {
        As[buf][lk+0][lr]=av.x; As[buf][lk+1][lr]=av.y; As[buf][lk+2][lr]=av.z; As[buf][lk+3][lr]=av.w;
        Bs[buf][lk+0][lr]=wv.x; Bs[buf][lk+1][lr]=wv.y; Bs[buf][lk+2][lr]=wv.z; Bs[buf][lk+3][lr]=wv.w;
        __syncthreads();
        if (k0 + 8 < K) { av = *(const float4*)(ap + k0 + 8); wv = *(const float4*)(wp + k0 + 8); }
        #pragma unroll
        for (int k = 0; k < 8; k++) {
            float4 a0 = *(const float4*)&As[buf][k][ty*4];
            float4 a1 = *(const float4*)&As[buf][k][64 + ty*4];
            float4 b0 = *(const float4*)&Bs[buf][k][tx*4];
            float4 b1 = *(const float4*)&Bs[buf][k][64 + tx*4];
            float ar[8] = {a0.x,a0.y,a0.z,a0.w,a1.x,a1.y,a1.z,a1.w};
            float br[8] = {b0.x,b0.y,b0.z,b0.w,b1.x,b1.y,b1.z,b1.w};
            #pragma unroll
            for (int i=0;i<8;i++)
                #pragma unroll
                for (int j=0;j<8;j++) acc[i][j] += ar[i]*br[j];
        }
        buf ^= 1;
    }
    float4 bs0 = *(const float4*)(bias + n0 + tx*4);
    float4 bs1 = *(const float4*)(bias + n0 + 64 + tx*4);
    float bb[8] = {bs0.x,bs0.y,bs0.z,bs0.w,bs1.x,bs1.y,bs1.z,bs1.w};
    #pragma unroll
    for (int i=0;i<8;i++) {
        int m = m0 + ((i<4) ? (ty*4+i) : (64+ty*4+i-4));
        float4 o0, o1;
        o0.x=acc[i][0]+bb[0]; o0.y=acc[i][1]+bb[1]; o0.z=acc[i][2]+bb[2]; o0.w=acc[i][3]+bb[3];
        o1.x=acc[i][4]+bb[4]; o1.y=acc[i][5]+bb[5]; o1.z=acc[i][6]+bb[6]; o1.w=acc[i][7]+bb[7];
        *(float4*)(C + (long)m*G3 + n0 + tx*4)      = o0;
        *(float4*)(C + (long)m*G3 + n0 + 64 + tx*4) = o1;
    }
}

// ------------- persistent utterance GRU (unchanged from R8) -------------
extern __shared__ float usm[];
__global__ __launch_bounds__(128, 3) void k_ustep_pers(
    const float* __restrict__ Whh, const float* __restrict__ bhh,
    const int* __restrict__ tokens)
{
    float* Wsm = usm;
    float* Asm = usm + 48*WPITCH;
    int tid = threadIdx.x;
    int tx = tid & 7, ty = tid >> 3;
    int m0 = blockIdx.x * UROWS;
    int j0 = blockIdx.y * UJT;
    int jb = j0 + (tx << 1);

    for (int i = tid; i < 48*64; i += 128) {
        int r = i >> 6, q = i & 63;
        int g = r >> 4, jj = r & 15;
        float4 v = *(const float4*)(Whh + (long)(g*NH + j0 + jj)*NH + q*4);
        *(float4*)&Wsm[r*WPITCH + q*4] = v;
    }
    float bh[3][2];
    #pragma unroll
    for (int g=0; g<3; g++) { bh[g][0] = bhh[g*NH + jb]; bh[g][1] = bhh[g*NH + jb + 1]; }
    __syncthreads();

    for (int t = 0; t < NT; t++) {
        const float* Hin  = (t & 1) ? g_Hu1 : g_Hu0;
        float*       Hout = (t & 1) ? g_Hu0 : g_Hu1;
        float acc[3][8][2] = {};
        float4 ld[4];
        #pragma unroll
        for (int q=0; q<4; q++) {
            int idx = q*128 + tid, row = idx >> 2, kq = idx & 3;
            ld[q] = *(const float4*)(Hin + (long)(m0+row)*NH + kq*4);
        }
        int buf = 0;
        for (int c = 0; c < 16; c++) {
            float* Ab = Asm + buf*16*APITCH;
            #pragma unroll
            for (int q=0; q<4; q++) {
                int idx = q*128 + tid, row = idx >> 2, kq = idx & 3;
                Ab[(kq*4+0)*APITCH + row] = ld[q].x;
                Ab[(kq*4+1)*APITCH + row] = ld[q].y;
                Ab[(kq*4+2)*APITCH + row] = ld[q].z;
                Ab[(kq*4+3)*APITCH + row] = ld[q].w;
            }
            __syncthreads();
            if (c < 15) {
                #pragma unroll
                for (int q=0; q<4; q++) {
                    int idx = q*128 + tid, row = idx >> 2, kq = idx & 3;
                    ld[q] = *(const float4*)(Hin + (long)(m0+row)*NH + (c+1)*16 + kq*4);
                }
            }
            #pragma unroll
            for (int k4 = 0; k4 < 16; k4 += 4) {
                float4 w[3][2];
                #pragma unroll
                for (int g=0; g<3; g++)
                    #pragma unroll
                    for (int jj=0; jj<2; jj++)
                        w[g][jj] = *(const float4*)&Wsm[(g*16 + (tx<<1)+jj)*WPITCH + c*16 + k4];
                #pragma unroll
                for (int kk=0; kk<4; kk++) {
                    const float* ak = Ab + (k4+kk)*APITCH + (ty<<3);
                    float4 a0 = *(const float4*)ak;
                    float4 a1 = *(const float4*)(ak + 4);
                    float a[8] = {a0.x,a0.y,a0.z,a0.w,a1.x,a1.y,a1.z,a1.w};
                    #pragma unroll
                    for (int g=0; g<3; g++) {
                        float w0 = (&w[g][0].x)[kk];
                        float w1 = (&w[g][1].x)[kk];
                        #pragma unroll
                        for (int r=0; r<8; r++) {
                            acc[g][r][0] += a[r]*w0;
                            acc[g][r][1] += a[r]*w1;
                        }
                    }
                }
            }
            __syncthreads();
            buf ^= 1;
        }
        #pragma unroll
        for (int r=0; r<8; r++) {
            int m = m0 + (ty<<3) + r;
            int tok = tokens[m*NT + t];
            const float* gi = g_TG + (long)tok * G3;
            float h0v = Hin[(long)m*NH + jb];
            float h1v = Hin[(long)m*NH + jb + 1];
            float rr0 = 1.f/(1.f+expf(-(gi[jb]       + acc[0][r][0] + bh[0][0])));
            float zz0 = 1.f/(1.f+expf(-(gi[NH+jb]    + acc[1][r][0] + bh[1][0])));
            float nn0 = tanhf(gi[2*NH+jb] + rr0*(acc[2][r][0] + bh[2][0]));
            Hout[(long)m*NH + jb] = (1.f - zz0)*nn0 + zz0*h0v;
            float rr1 = 1.f/(1.f+expf(-(gi[jb+1]     + acc[0][r][1] + bh[0][1])));
            float zz1 = 1.f/(1.f+expf(-(gi[NH+jb+1]  + acc[1][r][1] + bh[1][1])));
            float nn1 = tanhf(gi[2*NH+jb+1] + rr1*(acc[2][r][1] + bh[2][1]));
            Hout[(long)m*NH + jb + 1] = (1.f - zz1)*nn1 + zz1*h1v;
        }
        if (t < NT-1) {
            __threadfence();
            __syncthreads();
            if (tid == 0) {
                unsigned target = (unsigned)UTILES * (t + 1);
                atomicAdd(&g_ubar, 1u);
                while (*(volatile unsigned*)&g_ubar < target) __nanosleep(64);
                __threadfence();
            }
            __syncthreads();
        }
    }
}

// ------------- persistent small-RNN: mode 0=ctx(32 blk) 1=resp(64 blk) 2=spk(32 blk) -------------
extern __shared__ float rsm[];
__global__ __launch_bounds__(128) void k_rnn_pers(
    const float* __restrict__ Whh, const float* __restrict__ bhh,
    const float* __restrict__ GI, const int* __restrict__ spk,
    float* __restrict__ out, int mode, int nblocks)
{
    float* Wsm = rsm;                    // [48][260]
    float* Asm = rsm + 48*260;           // [32][260]
    int* flags = (int*)(rsm + 48*260 + 32*260);  // [32][51] (mode2)
    int tid = threadIdx.x;
    int jt = blockIdx.x & 15, rt = blockIdx.x >> 4;
    int j0 = jt*16, m0 = rt*32;
    int tx = tid & 15, ty = tid >> 4;
    int j = j0 + tx;

    for (int i = tid; i < 48*64; i += 128) {
        int r = i >> 6, q = i & 63;
        int g = r >> 4, jj = r & 15;
        float4 v = *(const float4*)(Whh + (long)(g*NH + j0 + jj)*NH + q*4);
        *(float4*)&Wsm[r*260 + q*4] = v;
    }
    float b0 = bhh[j], b1 = bhh[NH + j], b2 = bhh[2*NH + j];
    if (mode == 2) for (int i = tid; i < 32*51; i += 128) flags[i] = 0;
    __syncthreads();

    unsigned* bar = &g_bar2[mode];
    for (int t = 0; t < NS; t++) {
        // stage h_prev rows into Asm
        if (mode == 2) {
            for (int i = tid; i < 32*64; i += 128) {
                int r = i >> 6, q = i & 63;
                int b = m0 + r;
                int a = spk[b*NS + t];
                *(float4*)&Asm[r*260 + q*4] =
                    *(const float4*)(g_Htab + ((long)b*NA + a)*NH + q*4);
            }
            if (tid < 32) flags[tid*51 + spk[(m0+tid)*NS + t]] = 1;
        } else if (t == 0) {
            for (int i = tid; i < 32*64; i += 128) {
                int r = i >> 6, q = i & 63;
                *(float4*)&Asm[r*260 + q*4] = make_float4(0.f,0.f,0.f,0.f);
            }
        } else {
            for (int i = tid; i < 32*64; i += 128) {
                int r = i >> 6, q = i & 63;
                int m = m0 + r;
                const float* src = (mode == 0)
                    ? out + O_CTXOUT  + ((long)(t-1)*64 + m)*NH
                    : out + O_RESPOUT + (((long)(m&1)*NT + (t-1))*64 + (m>>1))*NH;
                *(float4*)&Asm[r*260 + q*4] = *(const float4*)(src + q*4);
            }
        }
        __syncthreads();

        float acc[3][4] = {};
        #pragma unroll 2
        for (int k0 = 0; k0 < NH; k0 += 4) {
            float4 w0 = *(const float4*)&Wsm[(tx)*260 + k0];
            float4 w1 = *(const float4*)&Wsm[(16+tx)*260 + k0];
            float4 w2 = *(const float4*)&Wsm[(32+tx)*260 + k0];
            #pragma unroll
            for (int r = 0; r < 4; r++) {
                float4 a = *(const float4*)&Asm[(ty*4+r)*260 + k0];
                acc[0][r] += a.x*w0.x + a.y*w0.y + a.z*w0.z + a.w*w0.w;
                acc[1][r] += a.x*w1.x + a.y*w1.y + a.z*w1.z + a.w*w1.w;
                acc[2][r] += a.x*w2.x + a.y*w2.y + a.z*w2.z + a.w*w2.w;
            }
        }
        #pragma unroll
        for (int r = 0; r < 4; r++) {
            int m = m0 + ty*4 + r;
            long girow = (mode == 1) ? ((long)t*128 + m) : ((long)t*64 + m);
            const float* gi = GI + girow*G3;
            float rr = 1.f/(1.f+expf(-(gi[j]      + acc[0][r] + b0)));
            float zz = 1.f/(1.f+expf(-(gi[NH+j]   + acc[1][r] + b1)));
            float nn = tanhf(gi[2*NH+j] + rr*(acc[2][r] + b2));
            float hp = Asm[(ty*4+r)*260 + j];
            float hn = (1.f - zz)*nn + zz*hp;
            if (mode == 0) {
                out[O_CTXOUT + ((long)t*64 + m)*NH + j] = hn;
                if (t == NS-1) out[O_CTXHID + (long)m*NH + j] = hn;
            } else if (mode == 1) {
                out[O_RESPOUT + (((long)(m&1)*NT + t)*64 + (m>>1))*NH + j] = hn;
                if (t == NS-1) out[O_RESPHID + ((long)(m&1)*64 + (m>>1))*NH + j] = hn;
            } else {
                int a = spk[m*NS + t];
                g_Htab[((long)m*NA + a)*NH + j] = hn;
            }
        }
        if (t < NS-1) {
            __threadfence();
            __syncthreads();
            if (tid == 0) {
                atomicAdd(bar, 1u);
                unsigned target = (unsigned)nblocks * (t + 1);
                while (*(volatile unsigned*)bar < target) __nanosleep(64);
                __threadfence();
            }
            __syncthreads();
        }
    }
    if (mode == 2) {
        __syncthreads();
        for (int a = 0; a < NA; a++) {
            #pragma unroll
            for (int r = 0; r < 4; r++) {
                int lb = ty*4 + r, b = m0 + lb;
                float v = flags[lb*51 + a] ? g_Htab[((long)b*NA + a)*NH + j] : 0.f;
                out[O_SPKEMB + ((long)b*NA + a)*NH + j] = v;
            }
        }
        if (jt == 0) {
            for (int i = tid; i < 32*NA; i += 128) {
                int r = i / NA, a = i % NA;
                out[O_SPKMASK + (m0+r)*NA + a] = (flags[r*51 + a] && a > 0) ? 1.f : 0.f;
            }
        }
    }
}

// ------------- ctx GRU input: concat(utter_hidden, agent_emb) -------------
__global__ void k_cin(const int* __restrict__ spk) {
    int idx = blockIdx.x * 256 + threadIdx.x;
    int c = idx & 511, mr = idx >> 9;
    int s = mr >> 6, b = mr & 63;
    float v;
    if (c < NH) v = g_Hu0[(b*NS + s)*NH + c];
    else        v = g_tables[(b*NA + spk[b*NS + s])*NH + (c - NH)];
    g_CIN[idx] = v;
}

// ------------- launch -------------
extern "C" void kernel_launch(void* const* d_in, const int* in_sizes, int n_in,
                              void* d_out, int out_size) {
    (void)in_sizes; (void)n_in; (void)out_size;
    const int*   context = (const int*)d_in[0];
    const int*   response= (const int*)d_in[1];
    const int*   spk     = (const int*)d_in[2];
    const float* emb_u   = (const float*)d_in[3];
    const float* emb_r   = (const float*)d_in[4];
    const float* uWih=(const float*)d_in[5],  *uWhh=(const float*)d_in[6];
    const float* ubih=(const float*)d_in[7],  *ubhh=(const float*)d_in[8];
    const float* cWih=(const float*)d_in[9],  *cWhh=(const float*)d_in[10];
    const float* cbih=(const float*)d_in[11], *cbhh=(const float*)d_in[12];
    const float* rWih=(const float*)d_in[13], *rWhh=(const float*)d_in[14];
    const float* rbih=(const float*)d_in[15], *rbhh=(const float*)d_in[16];
    const float* sWih=(const float*)d_in[17], *sWhh=(const float*)d_in[18];
    const float* sbih=(const float*)d_in[19], *sbhh=(const float*)d_in[20];
    float* out = (float*)d_out;

    void *pTab, *pTG, *pHu0, *pCIN, *pCGI, *pSGI, *pRGI, *pBar, *pBar2, *pHtab;
    cudaGetSymbolAddress(&pTab, g_tables);
    cudaGetSymbolAddress(&pTG,  g_TG);
    cudaGetSymbolAddress(&pHu0, g_Hu0);
    cudaGetSymbolAddress(&pCIN, g_CIN);
    cudaGetSymbolAddress(&pCGI, g_CGI);
    cudaGetSymbolAddress(&pSGI, g_SGI);
    cudaGetSymbolAddress(&pRGI, g_RGI);
    cudaGetSymbolAddress(&pBar, g_ubar);
    cudaGetSymbolAddress(&pBar2, g_bar2);
    cudaGetSymbolAddress(&pHtab, g_Htab);

    cudaFuncSetAttribute(k_ustep_pers, cudaFuncAttributeMaxDynamicSharedMemorySize, USMEM);
    cudaFuncSetAttribute(k_rnn_pers,   cudaFuncAttributeMaxDynamicSharedMemorySize, RSMEM);

    cudaMemcpyAsync(pTab, h_tables, sizeof(h_tables), cudaMemcpyHostToDevice, 0);
    cudaMemsetAsync(pHu0, 0, (size_t)NB*NS*NH*sizeof(float), 0);
    cudaMemsetAsync(pBar, 0, sizeof(unsigned), 0);
    cudaMemsetAsync(pBar2, 0, 4*sizeof(unsigned), 0);
    cudaMemsetAsync(pHtab, 0, (size_t)NB*NA*NH*sizeof(float), 0);

    // utterance token-gate table + persistent recurrence
    k_gemm128<<<dim3(NV/128, 6), 256>>>(emb_u, nullptr, NH, uWih, ubih, (float*)pTG);
    k_ustep_pers<<<dim3(25, 16), 128, USMEM>>>(uWhh, ubhh, context);

    // fork: response branch overlaps ctx/spk chain
    cudaEventRecord(g_evFork, 0);
    cudaStreamWaitEvent(g_s2, g_evFork, 0);
    k_gemm128<<<dim3(50, 6), 256, 0, g_s2>>>(emb_r, response, NH, rWih, rbih, (float*)pRGI);
    k_rnn_pers<<<64, 128, RSMEM, g_s2>>>(rWhh, rbhh, (const float*)pRGI, spk, out, 1, 64);
    cudaEventRecord(g_evJoin, g_s2);

    // context GRU
    k_cin<<<6400, 256>>>(spk);
    k_gemm128<<<dim3(25, 6), 256>>>((const float*)pCIN, nullptr, 2*NH, cWih, cbih, (float*)pCGI);
    k_rnn_pers<<<32, 128, RSMEM>>>(cWhh, cbhh, (const float*)pCGI, spk, out, 0, 32);

    // speaker GRU (input = context_output)
    k_gemm128<<<dim3(25, 6), 256>>>(out + O_CTXOUT, nullptr, NH, sWih, sbih, (float*)pSGI);
    k_rnn_pers<<<32, 128, RSMEM>>>(sWhh, sbhh, (const float*)pSGI, spk, out, 2, 32);

    // join
    cudaStreamWaitEvent(0, g_evJoin, 0);
}

// round 11
// speedup vs baseline: 1.5582x; 1.1592x over previous
#include <cuda_runtime.h>
#include <math.h>

#define NB 64
#define NS 50
#define NT 50
#define NR 2
#define NV 32000
#define NH 256
#define G3 768
#define NA 51

// output offsets (floats)
#define O_CTXOUT  0
#define O_CTXHID  819200
#define O_RESPOUT 835584
#define O_RESPHID 2473984
#define O_SPKEMB  2506752
#define O_SPKMASK 3342336

// persistent ustep tiling
#define UROWS 128
#define UJT 16
#define UTILES 400
#define WPITCH 260
#define APITCH 132
#define USMEM (48*WPITCH*4 + 2*16*APITCH*4)

// fused tail kernel
#define TBLOCKS 160
#define TSMEM (48*260*4 + 32*260*4 + 32*51*4)

// ------------- device scratch -------------
__device__ float g_tables[NB*NA*NH];
__device__ float g_TG[NV*G3];
__device__ float g_Hu0[NB*NS*NH];
__device__ float g_Hu1[NB*NS*NH];
__device__ float g_CIN[NS*NB*2*NH];
__device__ float g_CGI[NS*NB*G3];
__device__ float g_SGI[NS*NB*G3];
__device__ float g_RGI[NT*NB*NR*G3];
__device__ float g_Htab[NB*NA*NH];
__device__ unsigned g_ubar;
__device__ unsigned g_tbar;

// ------------- host: exact numpy legacy MT19937 agent tables -------------
static float h_tables[NB*NA*NH];
static cudaStream_t g_s2;
static cudaEvent_t g_evFork, g_evJoin;
namespace {
struct MT {
    unsigned mt[624]; int mti;
    void seed(unsigned s){ mt[0]=s; for(int i=1;i<624;i++) mt[i]=1812433253u*(mt[i-1]^(mt[i-1]>>30))+(unsigned)i; mti=624; }
    unsigned next(){
        if(mti>=624){ for(int i=0;i<624;i++){ unsigned y=(mt[i]&0x80000000u)|(mt[(i+1)%624]&0x7fffffffu);
            mt[i]=mt[(i+397)%624]^(y>>1)^((y&1u)?0x9908b0dfu:0u);} mti=0; }
        unsigned y=mt[mti++]; y^=y>>11; y^=(y<<7)&0x9d2c5680u; y^=(y<<15)&0xefc60000u; y^=y>>18; return y;
    }
};
struct TabInit {
    TabInit(){
        MT m; m.seed(1u);
        for(long i=0;i<(long)NB*NA*NH;i++){
            unsigned a=m.next()>>5, b=m.next()>>6;
            h_tables[i]=(float)(((double)a*67108864.0+(double)b)*(1.0/9007199254740992.0));
        }
        cudaStreamCreateWithFlags(&g_s2, cudaStreamNonBlocking);
        cudaEventCreateWithFlags(&g_evFork, cudaEventDisableTiming);
        cudaEventCreateWithFlags(&g_evJoin, cudaEventDisableTiming);
    }
} g_tabinit;
}

// ------------- 128x128x8 double-buffered SGEMM: C[M][768] = gather(A) @ W^T + bias -------------
__global__ __launch_bounds__(256) void k_gemm128(
    const float* __restrict__ A, const int* __restrict__ map, int K,
    const float* __restrict__ W, const float* __restrict__ bias, float* __restrict__ C)
{
    __shared__ float As[2][8][132];
    __shared__ float Bs[2][8][132];
    int tid = threadIdx.x;
    int m0 = blockIdx.x * 128, n0 = blockIdx.y * 128;
    int tx = tid & 15, ty = tid >> 4;
    int lr = tid >> 1, lk = (tid & 1) * 4;
    int arow = m0 + lr;
    int row = map ? map[(arow & 127) * NT + (arow >> 7)] : arow;
    const float* ap = A + (long)row * K + lk;
    const float* wp = W + (long)(n0 + lr) * K + lk;
    float acc[8][8] = {};
    float4 av = *(const float4*)ap;
    float4 wv = *(const float4*)wp;
    int buf = 0;
    for (int k0 = 0; k0 < K; k0 += 8) {
        As[buf][lk+0][lr]=av.x; As[buf][lk+1][lr]=av.y; As[buf][lk+2][lr]=av.z; As[buf][lk+3][lr]=av.w;
        Bs[buf][lk+0][lr]=wv.x; Bs[buf][lk+1][lr]=wv.y; Bs[buf][lk+2][lr]=wv.z; Bs[buf][lk+3][lr]=wv.w;
        __syncthreads();
        if (k0 + 8 < K) { av = *(const float4*)(ap + k0 + 8); wv = *(const float4*)(wp + k0 + 8); }
        #pragma unroll
        for (int k = 0; k < 8; k++) {
            float4 a0 = *(const float4*)&As[buf][k][ty*4];
            float4 a1 = *(const float4*)&As[buf][k][64 + ty*4];
            float4 b0 = *(const float4*)&Bs[buf][k][tx*4];
            float4 b1 = *(const float4*)&Bs[buf][k][64 + tx*4];
            float ar[8] = {a0.x,a0.y,a0.z,a0.w,a1.x,a1.y,a1.z,a1.w};
            float br[8] = {b0.x,b0.y,b0.z,b0.w,b1.x,b1.y,b1.z,b1.w};
            #pragma unroll
            for (int i=0;i<8;i++)
                #pragma unroll
                for (int j=0;j<8;j++) acc[i][j] += ar[i]*br[j];
        }
        buf ^= 1;
    }
    float4 bs0 = *(const float4*)(bias + n0 + tx*4);
    float4 bs1 = *(const float4*)(bias + n0 + 64 + tx*4);
    float bb[8] = {bs0.x,bs0.y,bs0.z,bs0.w,bs1.x,bs1.y,bs1.z,bs1.w};
    #pragma unroll
    for (int i=0;i<8;i++) {
        int m = m0 + ((i<4) ? (ty*4+i) : (64+ty*4+i-4));
        float4 o0, o1;
        o0.x=acc[i][0]+bb[0]; o0.y=acc[i][1]+bb[1]; o0.z=acc[i][2]+bb[2]; o0.w=acc[i][3]+bb[3];
        o1.x=acc[i][4]+bb[4]; o1.y=acc[i][5]+bb[5]; o1.z=acc[i][6]+bb[6]; o1.w=acc[i][7]+bb[7];
        *(float4*)(C + (long)m*G3 + n0 + tx*4)      = o0;
        *(float4*)(C + (long)m*G3 + n0 + 64 + tx*4) = o1;
    }
}

// ------------- persistent utterance GRU -------------
extern __shared__ float usm[];
__global__ __launch_bounds__(128, 3) void k_ustep_pers(
    const float* __restrict__ Whh, const float* __restrict__ bhh,
    const int* __restrict__ tokens)
{
    float* Wsm = usm;
    float* Asm = usm + 48*WPITCH;
    int tid = threadIdx.x;
    int tx = tid & 7, ty = tid >> 3;
    int m0 = blockIdx.x * UROWS;
    int j0 = blockIdx.y * UJT;
    int jb = j0 + (tx << 1);

    for (int i = tid; i < 48*64; i += 128) {
        int r = i >> 6, q = i & 63;
        int g = r >> 4, jj = r & 15;
        float4 v = *(const float4*)(Whh + (long)(g*NH + j0 + jj)*NH + q*4);
        *(float4*)&Wsm[r*WPITCH + q*4] = v;
    }
    float bh[3][2];
    #pragma unroll
    for (int g=0; g<3; g++) { bh[g][0] = bhh[g*NH + jb]; bh[g][1] = bhh[g*NH + jb + 1]; }
    __syncthreads();

    for (int t = 0; t < NT; t++) {
        const float* Hin  = (t & 1) ? g_Hu1 : g_Hu0;
        float*       Hout = (t & 1) ? g_Hu0 : g_Hu1;
        float acc[3][8][2] = {};
        float4 ld[4];
        #pragma unroll
        for (int q=0; q<4; q++) {
            int idx = q*128 + tid, row = idx >> 2, kq = idx & 3;
            ld[q] = *(const float4*)(Hin + (long)(m0+row)*NH + kq*4);
        }
        int buf = 0;
        for (int c = 0; c < 16; c++) {
            float* Ab = Asm + buf*16*APITCH;
            #pragma unroll
            for (int q=0; q<4; q++) {
                int idx = q*128 + tid, row = idx >> 2, kq = idx & 3;
                Ab[(kq*4+0)*APITCH + row] = ld[q].x;
                Ab[(kq*4+1)*APITCH + row] = ld[q].y;
                Ab[(kq*4+2)*APITCH + row] = ld[q].z;
                Ab[(kq*4+3)*APITCH + row] = ld[q].w;
            }
            __syncthreads();
            if (c < 15) {
                #pragma unroll
                for (int q=0; q<4; q++) {
                    int idx = q*128 + tid, row = idx >> 2, kq = idx & 3;
                    ld[q] = *(const float4*)(Hin + (long)(m0+row)*NH + (c+1)*16 + kq*4);
                }
            }
            #pragma unroll
            for (int k4 = 0; k4 < 16; k4 += 4) {
                float4 w[3][2];
                #pragma unroll
                for (int g=0; g<3; g++)
                    #pragma unroll
                    for (int jj=0; jj<2; jj++)
                        w[g][jj] = *(const float4*)&Wsm[(g*16 + (tx<<1)+jj)*WPITCH + c*16 + k4];
                #pragma unroll
                for (int kk=0; kk<4; kk++) {
                    const float* ak = Ab + (k4+kk)*APITCH + (ty<<3);
                    float4 a0 = *(const float4*)ak;
                    float4 a1 = *(const float4*)(ak + 4);
                    float a[8] = {a0.x,a0.y,a0.z,a0.w,a1.x,a1.y,a1.z,a1.w};
                    #pragma unroll
                    for (int g=0; g<3; g++) {
                        float w0 = (&w[g][0].x)[kk];
                        float w1 = (&w[g][1].x)[kk];
                        #pragma unroll
                        for (int r=0; r<8; r++) {
                            acc[g][r][0] += a[r]*w0;
                            acc[g][r][1] += a[r]*w1;
                        }
                    }
                }
            }
            __syncthreads();
            buf ^= 1;
        }
        #pragma unroll
        for (int r=0; r<8; r++) {
            int m = m0 + (ty<<3) + r;
            int tok = tokens[m*NT + t];
            const float* gi = g_TG + (long)tok * G3;
            float h0v = Hin[(long)m*NH + jb];
            float h1v = Hin[(long)m*NH + jb + 1];
            float rr0 = 1.f/(1.f+expf(-(gi[jb]       + acc[0][r][0] + bh[0][0])));
            float zz0 = 1.f/(1.f+expf(-(gi[NH+jb]    + acc[1][r][0] + bh[1][0])));
            float nn0 = tanhf(gi[2*NH+jb] + rr0*(acc[2][r][0] + bh[2][0]));
            Hout[(long)m*NH + jb] = (1.f - zz0)*nn0 + zz0*h0v;
            float rr1 = 1.f/(1.f+expf(-(gi[jb+1]     + acc[0][r][1] + bh[0][1])));
            float zz1 = 1.f/(1.f+expf(-(gi[NH+jb+1]  + acc[1][r][1] + bh[1][1])));
            float nn1 = tanhf(gi[2*NH+jb+1] + rr1*(acc[2][r][1] + bh[2][1]));
            Hout[(long)m*NH + jb + 1] = (1.f - zz1)*nn1 + zz1*h1v;
        }
        if (t < NT-1) {
            __threadfence();
            __syncthreads();
            if (tid == 0) {
                unsigned target = (unsigned)UTILES * (t + 1);
                atomicAdd(&g_ubar, 1u);
                while (*(volatile unsigned*)&g_ubar < target) __nanosleep(64);
                __threadfence();
            }
            __syncthreads();
        }
    }
}

// ------------- fused tail: ctx + SGI-gemm + spk + resp, one barrier per pipelined step -------------
// blocks: [0,32) ctx | [32,64) sgi | [64,96) spk | [96,160) resp.  256 threads.
extern __shared__ float tsm[];
__global__ __launch_bounds__(256) void k_tail(
    const float* __restrict__ cWhh, const float* __restrict__ cbhh,
    const float* __restrict__ sWih, const float* __restrict__ sbih,
    const float* __restrict__ sWhh, const float* __restrict__ sbhh,
    const float* __restrict__ rWhh, const float* __restrict__ rbhh,
    const int* __restrict__ spk, float* __restrict__ out)
{
    float* Wsm = tsm;                          // [48][260]
    float* Asm = tsm + 48*260;                 // [32][260]
    int* flags = (int*)(tsm + 48*260 + 32*260);// [32][51] (spk)
    int tid = threadIdx.x, bid = blockIdx.x;
    int role = (bid < 32) ? 0 : (bid < 64) ? 1 : (bid < 96) ? 2 : 3;
    int rel  = bid - ((role == 0) ? 0 : (role == 1) ? 32 : (role == 2) ? 64 : 96);
    int jt = rel & 15, rt = rel >> 4;
    int j0 = jt*16, m0 = rt*32;
    int tx = tid & 15, ty = tid >> 4;
    int j = j0 + tx;
    const float* W    = (role==0) ? cWhh : (role==1) ? sWih : (role==2) ? sWhh : rWhh;
    const float* bias = (role==0) ? cbhh : (role==1) ? sbih : (role==2) ? sbhh : rbhh;

    for (int i = tid; i < 48*64; i += 256) {
        int r = i >> 6, q = i & 63;
        int g = r >> 4, jj = r & 15;
        *(float4*)&Wsm[r*260 + q*4] = *(const float4*)(W + (long)(g*NH + j0 + jj)*NH + q*4);
    }
    float b0 = bias[j], b1 = bias[NH + j], b2 = bias[2*NH + j];
    if (role == 2) for (int i = tid; i < 32*51; i += 256) flags[i] = 0;
    __syncthreads();

    for (int it = 0; it < NS + 2; ++it) {
        int t = (role == 1) ? it - 1 : (role == 2) ? it - 2 : it;
        bool active = (t >= 0) && (t < NS);
        if (active) {
            // stage 32 h/input rows into Asm
            if (role == 2) {
                for (int i = tid; i < 32*64; i += 256) {
                    int r = i >> 6, q = i & 63;
                    int b = m0 + r, a = spk[b*NS + t];
                    *(float4*)&Asm[r*260 + q*4] = *(const float4*)(g_Htab + ((long)b*NA + a)*NH + q*4);
                }
                if (tid < 32) flags[tid*51 + spk[(m0+tid)*NS + t]] = 1;
            } else if (role == 1) {
                for (int i = tid; i < 32*64; i += 256) {
                    int r = i >> 6, q = i & 63;
                    *(float4*)&Asm[r*260 + q*4] =
                        *(const float4*)(out + O_CTXOUT + ((long)t*64 + m0 + r)*NH + q*4);
                }
            } else if (t == 0) {
                for (int i = tid; i < 32*64; i += 256) {
                    int r = i >> 6, q = i & 63;
                    *(float4*)&Asm[r*260 + q*4] = make_float4(0.f,0.f,0.f,0.f);
                }
            } else {
                for (int i = tid; i < 32*64; i += 256) {
                    int r = i >> 6, q = i & 63;
                    int m = m0 + r;
                    const float* src = (role == 0)
                        ? out + O_CTXOUT  + ((long)(t-1)*64 + m)*NH
                        : out + O_RESPOUT + (((long)(m&1)*NT + (t-1))*64 + (m>>1))*NH;
                    *(float4*)&Asm[r*260 + q*4] = *(const float4*)(src + q*4);
                }
            }
            __syncthreads();

            float acc[3][2] = {};
            #pragma unroll 4
            for (int k0 = 0; k0 < NH; k0 += 4) {
                float4 w0 = *(const float4*)&Wsm[tx*260 + k0];
                float4 w1 = *(const float4*)&Wsm[(16+tx)*260 + k0];
                float4 w2 = *(const float4*)&Wsm[(32+tx)*260 + k0];
                #pragma unroll
                for (int r = 0; r < 2; r++) {
                    float4 a = *(const float4*)&Asm[(ty*2+r)*260 + k0];
                    acc[0][r] += a.x*w0.x + a.y*w0.y + a.z*w0.z + a.w*w0.w;
                    acc[1][r] += a.x*w1.x + a.y*w1.y + a.z*w1.z + a.w*w1.w;
                    acc[2][r] += a.x*w2.x + a.y*w2.y + a.z*w2.z + a.w*w2.w;
                }
            }
            if (role == 1) {
                #pragma unroll
                for (int r = 0; r < 2; r++) {
                    int m = m0 + ty*2 + r;
                    float* o = g_SGI + ((long)t*64 + m)*G3;
                    o[j] = acc[0][r] + b0; o[NH+j] = acc[1][r] + b1; o[2*NH+j] = acc[2][r] + b2;
                }
            } else {
                #pragma unroll
                for (int r = 0; r < 2; r++) {
                    int lr = ty*2 + r, m = m0 + lr;
                    const float* gi = (role == 0) ? g_CGI + ((long)t*64 + m)*G3
                                    : (role == 2) ? g_SGI + ((long)t*64 + m)*G3
                                    :               g_RGI + ((long)t*128 + m)*G3;
                    float rr = 1.f/(1.f+expf(-(gi[j]      + acc[0][r] + b0)));
                    float zz = 1.f/(1.f+expf(-(gi[NH+j]   + acc[1][r] + b1)));
                    float nn = tanhf(gi[2*NH+j] + rr*(acc[2][r] + b2));
                    float hp = Asm[lr*260 + j];
                    float hn = (1.f - zz)*nn + zz*hp;
                    if (role == 0) {
                        out[O_CTXOUT + ((long)t*64 + m)*NH + j] = hn;
                        if (t == NS-1) out[O_CTXHID + (long)m*NH + j] = hn;
                    } else if (role == 3) {
                        out[O_RESPOUT + (((long)(m&1)*NT + t)*64 + (m>>1))*NH + j] = hn;
                        if (t == NS-1) out[O_RESPHID + ((long)(m&1)*64 + (m>>1))*NH + j] = hn;
                    } else {
                        int a = spk[m*NS + t];
                        g_Htab[((long)m*NA + a)*NH + j] = hn;
                    }
                }
            }
        }
        if (it < NS + 1) {
            __threadfence();
            __syncthreads();
            if (tid == 0) {
                atomicAdd(&g_tbar, 1u);
                unsigned target = (unsigned)TBLOCKS * (it + 1);
                while (*(volatile unsigned*)&g_tbar < target) __nanosleep(64);
                __threadfence();
            }
            __syncthreads();
        } else {
            __syncthreads();
        }
    }

    if (role == 2) {
        for (int a = 0; a < NA; a++) {
            #pragma unroll
            for (int r = 0; r < 2; r++) {
                int lb = ty*2 + r, b = m0 + lb;
                float v = flags[lb*51 + a] ? g_Htab[((long)b*NA + a)*NH + j] : 0.f;
                out[O_SPKEMB + ((long)b*NA + a)*NH + j] = v;
            }
        }
        if (jt == 0) {
            for (int i = tid; i < 32*NA; i += 256) {
                int r = i / NA, a = i % NA;
                out[O_SPKMASK + (m0+r)*NA + a] = (flags[r*51 + a] && a > 0) ? 1.f : 0.f;
            }
        }
    }
}

// ------------- ctx GRU input: concat(utter_hidden, agent_emb) -------------
__global__ void k_cin(const int* __restrict__ spk) {
    int idx = blockIdx.x * 256 + threadIdx.x;
    int c = idx & 511, mr = idx >> 9;
    int s = mr >> 6, b = mr & 63;
    float v;
    if (c < NH) v = g_Hu0[(b*NS + s)*NH + c];
    else        v = g_tables[(b*NA + spk[b*NS + s])*NH + (c - NH)];
    g_CIN[idx] = v;
}

// ------------- launch -------------
extern "C" void kernel_launch(void* const* d_in, const int* in_sizes, int n_in,
                              void* d_out, int out_size) {
    (void)in_sizes; (void)n_in; (void)out_size;
    const int*   context = (const int*)d_in[0];
    const int*   response= (const int*)d_in[1];
    const int*   spk     = (const int*)d_in[2];
    const float* emb_u   = (const float*)d_in[3];
    const float* emb_r   = (const float*)d_in[4];
    const float* uWih=(const float*)d_in[5],  *uWhh=(const float*)d_in[6];
    const float* ubih=(const float*)d_in[7],  *ubhh=(const float*)d_in[8];
    const float* cWih=(const float*)d_in[9],  *cWhh=(const float*)d_in[10];
    const float* cbih=(const float*)d_in[11], *cbhh=(const float*)d_in[12];
    const float* rWih=(const float*)d_in[13], *rWhh=(const float*)d_in[14];
    const float* rbih=(const float*)d_in[15], *rbhh=(const float*)d_in[16];
    const float* sWih=(const float*)d_in[17], *sWhh=(const float*)d_in[18];
    const float* sbih=(const float*)d_in[19], *sbhh=(const float*)d_in[20];
    float* out = (float*)d_out;

    void *pTab, *pTG, *pHu0, *pCIN, *pCGI, *pRGI, *pBar, *pTbar, *pHtab;
    cudaGetSymbolAddress(&pTab, g_tables);
    cudaGetSymbolAddress(&pTG,  g_TG);
    cudaGetSymbolAddress(&pHu0, g_Hu0);
    cudaGetSymbolAddress(&pCIN, g_CIN);
    cudaGetSymbolAddress(&pCGI, g_CGI);
    cudaGetSymbolAddress(&pRGI, g_RGI);
    cudaGetSymbolAddress(&pBar, g_ubar);
    cudaGetSymbolAddress(&pTbar, g_tbar);
    cudaGetSymbolAddress(&pHtab, g_Htab);

    cudaFuncSetAttribute(k_ustep_pers, cudaFuncAttributeMaxDynamicSharedMemorySize, USMEM);
    cudaFuncSetAttribute(k_tail,       cudaFuncAttributeMaxDynamicSharedMemorySize, TSMEM);

    cudaMemcpyAsync(pTab, h_tables, sizeof(h_tables), cudaMemcpyHostToDevice, 0);
    cudaMemsetAsync(pHu0, 0, (size_t)NB*NS*NH*sizeof(float), 0);
    cudaMemsetAsync(pBar, 0, sizeof(unsigned), 0);
    cudaMemsetAsync(pTbar, 0, sizeof(unsigned), 0);
    cudaMemsetAsync(pHtab, 0, (size_t)NB*NA*NH*sizeof(float), 0);

    // fork: RGI gemm (independent) overlaps TG gemm + utterance recurrence
    cudaEventRecord(g_evFork, 0);
    cudaStreamWaitEvent(g_s2, g_evFork, 0);
    k_gemm128<<<dim3(50, 6), 256, 0, g_s2>>>(emb_r, response, NH, rWih, rbih, (float*)pRGI);
    cudaEventRecord(g_evJoin, g_s2);

    // utterance token-gate table + persistent recurrence
    k_gemm128<<<dim3(NV/128, 6), 256>>>(emb_u, nullptr, NH, uWih, ubih, (float*)pTG);
    k_ustep_pers<<<dim3(25, 16), 128, USMEM>>>(uWhh, ubhh, context);

    // ctx input + CGI gemm
    k_cin<<<6400, 256>>>(spk);
    k_gemm128<<<dim3(25, 6), 256>>>((const float*)pCIN, nullptr, 2*NH, cWih, cbih, (float*)pCGI);

    // fused tail (needs RGI)
    cudaStreamWaitEvent(0, g_evJoin, 0);
    k_tail<<<TBLOCKS, 256, TSMEM>>>(cWhh, cbhh, sWih, sbih, sWhh, sbhh, rWhh, rbhh, spk, out);
}

// round 13
// speedup vs baseline: 1.6713x; 1.0725x over previous
#include <cuda_runtime.h>
#include <math.h>

#define NB 64
#define NS 50
#define NT 50
#define NR 2
#define NV 32000
#define NH 256
#define G3 768
#define NA 51

// output offsets (floats)
#define O_CTXOUT  0
#define O_CTXHID  819200
#define O_RESPOUT 835584
#define O_RESPHID 2473984
#define O_SPKEMB  2506752
#define O_SPKMASK 3342336

// persistent ustep tiling
#define UROWS 128
#define UJT 16
#define UTILES 400
#define WPITCH 260
#define APITCH 132
#define USMEM (48*WPITCH*4 + 2*16*APITCH*4)

// fused tail kernel
#define TBLOCKS 160
#define TSMEM (48*260*4 + 32*260*4 + 32*51*4)

typedef unsigned long long ull;

// ------------- f32x2 packed-FMA helpers (sm_100+) -------------
__device__ __forceinline__ void ffma2(ull& d, ull a, ull b) {
    asm("fma.rn.f32x2 %0, %1, %2, %0;" : "+l"(d) : "l"(a), "l"(b));
}
__device__ __forceinline__ ull pack2(float x, float y) {
    ull r; asm("mov.b64 %0, {%1, %2};" : "=l"(r) : "f"(x), "f"(y)); return r;
}
__device__ __forceinline__ float2 unpack2(ull v) {
    float2 r; asm("mov.b64 {%0, %1}, %2;" : "=f"(r.x), "=f"(r.y) : "l"(v)); return r;
}

// ------------- device scratch -------------
__device__ float g_tables[NB*NA*NH];
__device__ float g_TG[NV*G3];
__device__ float g_Hu0[NB*NS*NH];
__device__ float g_Hu1[NB*NS*NH];
__device__ float g_CIN[NS*NB*2*NH];
__device__ float g_CGI[NS*NB*G3];
__device__ float g_SGI[NS*NB*G3];
__device__ float g_RGI[NT*NB*NR*G3];
__device__ float g_Htab[NB*NA*NH];
__device__ unsigned g_ubar;
__device__ unsigned g_tbar;

// ------------- host: exact numpy legacy MT19937 agent tables -------------
static float h_tables[NB*NA*NH];
static cudaStream_t g_s2;
static cudaEvent_t g_evFork, g_evJoin;
namespace {
struct MT {
    unsigned mt[624]; int mti;
    void seed(unsigned s){ mt[0]=s; for(int i=1;i<624;i++) mt[i]=1812433253u*(mt[i-1]^(mt[i-1]>>30))+(unsigned)i; mti=624; }
    unsigned next(){
        if(mti>=624){ for(int i=0;i<624;i++){ unsigned y=(mt[i]&0x80000000u)|(mt[(i+1)%624]&0x7fffffffu);
            mt[i]=mt[(i+397)%624]^(y>>1)^((y&1u)?0x9908b0dfu:0u);} mti=0; }
        unsigned y=mt[mti++]; y^=y>>11; y^=(y<<7)&0x9d2c5680u; y^=(y<<15)&0xefc60000u; y^=y>>18; return y;
    }
};
struct TabInit {
    TabInit(){
        MT m; m.seed(1u);
        for(long i=0;i<(long)NB*NA*NH;i++){
            unsigned a=m.next()>>5, b=m.next()>>6;
            h_tables[i]=(float)(((double)a*67108864.0+(double)b)*(1.0/9007199254740992.0));
        }
        cudaStreamCreateWithFlags(&g_s2, cudaStreamNonBlocking);
        cudaEventCreateWithFlags(&g_evFork, cudaEventDisableTiming);
        cudaEventCreateWithFlags(&g_evJoin, cudaEventDisableTiming);
    }
} g_tabinit;
}

// ------------- 128x128x8 double-buffered SGEMM (f32x2): C[M][768] = gather(A) @ W^T + bias -------------
__global__ __launch_bounds__(256) void k_gemm128(
    const float* __restrict__ A, const int* __restrict__ map, int K,
    const float* __restrict__ W, const float* __restrict__ bias, float* __restrict__ C)
{
    __shared__ float As[2][8][132];
    __shared__ float Bs[2][8][132];
    int tid = threadIdx.x;
    int m0 = blockIdx.x * 128, n0 = blockIdx.y * 128;
    int tx = tid & 15, ty = tid >> 4;
    int lr = tid >> 1, lk = (tid & 1) * 4;
    int arow = m0 + lr;
    int row = map ? map[(arow & 127) * NT + (arow >> 7)] : arow;
    const float* ap = A + (long)row * K + lk;
    const float* wp = W + (long)(n0 + lr) * K + lk;
    ull acc2[8][4] = {};
    float4 av = *(const float4*)ap;
    float4 wv = *(const float4*)wp;
    int buf = 0;
    for (int k0 = 0; k0 < K; k0 += 8) {
        As[buf][lk+0][lr]=av.x; As[buf][lk+1][lr]=av.y; As[buf][lk+2][lr]=av.z; As[buf][lk+3][lr]=av.w;
        Bs[buf][lk+0][lr]=wv.x; Bs[buf][lk+1][lr]=wv.y; Bs[buf][lk+2][lr]=wv.z; Bs[buf][lk+3][lr]=wv.w;
        __syncthreads();
        if (k0 + 8 < K) { av = *(const float4*)(ap + k0 + 8); wv = *(const float4*)(wp + k0 + 8); }
        #pragma unroll
        for (int k = 0; k < 8; k++) {
            float4 a0 = *(const float4*)&As[buf][k][ty*4];
            float4 a1 = *(const float4*)&As[buf][k][64 + ty*4];
            ulonglong2 bA = *(const ulonglong2*)&Bs[buf][k][tx*4];
            ulonglong2 bB = *(const ulonglong2*)&Bs[buf][k][64 + tx*4];
            ull bp[4] = {bA.x, bA.y, bB.x, bB.y};
            float ar[8] = {a0.x,a0.y,a0.z,a0.w,a1.x,a1.y,a1.z,a1.w};
            #pragma unroll
            for (int i=0;i<8;i++) {
                ull ad = pack2(ar[i], ar[i]);
                #pragma unroll
                for (int jp=0;jp<4;jp++) ffma2(acc2[i][jp], ad, bp[jp]);
            }
        }
        buf ^= 1;
    }
    float4 bs0 = *(const float4*)(bias + n0 + tx*4);
    float4 bs1 = *(const float4*)(bias + n0 + 64 + tx*4);
    #pragma unroll
    for (int i=0;i<8;i++) {
        int m = m0 + ((i<4) ? (ty*4+i) : (64+ty*4+i-4));
        float2 u0 = unpack2(acc2[i][0]), u1 = unpack2(acc2[i][1]);
        float2 u2 = unpack2(acc2[i][2]), u3 = unpack2(acc2[i][3]);
        float4 o0, o1;
        o0.x=u0.x+bs0.x; o0.y=u0.y+bs0.y; o0.z=u1.x+bs0.z; o0.w=u1.y+bs0.w;
        o1.x=u2.x+bs1.x; o1.y=u2.y+bs1.y; o1.z=u3.x+bs1.z; o1.w=u3.y+bs1.w;
        *(float4*)(C + (long)m*G3 + n0 + tx*4)      = o0;
        *(float4*)(C + (long)m*G3 + n0 + 64 + tx*4) = o1;
    }
}

// ------------- persistent utterance GRU (f32x2 row-pair accumulators) -------------
extern __shared__ float usm[];
__global__ __launch_bounds__(128, 3) void k_ustep_pers(
    const float* __restrict__ Whh, const float* __restrict__ bhh,
    const int* __restrict__ tokens)
{
    float* Wsm = usm;
    float* Asm = usm + 48*WPITCH;
    int tid = threadIdx.x;
    int tx = tid & 7, ty = tid >> 3;
    int m0 = blockIdx.x * UROWS;
    int j0 = blockIdx.y * UJT;
    int jb = j0 + (tx << 1);

    for (int i = tid; i < 48*64; i += 128) {
        int r = i >> 6, q = i & 63;
        int g = r >> 4, jj = r & 15;
        float4 v = *(const float4*)(Whh + (long)(g*NH + j0 + jj)*NH + q*4);
        *(float4*)&Wsm[r*WPITCH + q*4] = v;
    }
    float bh[3][2];
    #pragma unroll
    for (int g=0; g<3; g++) { bh[g][0] = bhh[g*NH + jb]; bh[g][1] = bhh[g*NH + jb + 1]; }
    __syncthreads();

    for (int t = 0; t < NT; t++) {
        const float* Hin  = (t & 1) ? g_Hu1 : g_Hu0;
        float*       Hout = (t & 1) ? g_Hu0 : g_Hu1;
        // acc2[g][jj][rp]: row-pair packed (rows 2rp, 2rp+1 of this thread's 8)
        ull acc2[3][2][4] = {};
        float4 ld[4];
        #pragma unroll
        for (int q=0; q<4; q++) {
            int idx = q*128 + tid, row = idx >> 2, kq = idx & 3;
            ld[q] = *(const float4*)(Hin + (long)(m0+row)*NH + kq*4);
        }
        int buf = 0;
        for (int c = 0; c < 16; c++) {
            float* Ab = Asm + buf*16*APITCH;
            #pragma unroll
            for (int q=0; q<4; q++) {
                int idx = q*128 + tid, row = idx >> 2, kq = idx & 3;
                Ab[(kq*4+0)*APITCH + row] = ld[q].x;
                Ab[(kq*4+1)*APITCH + row] = ld[q].y;
                Ab[(kq*4+2)*APITCH + row] = ld[q].z;
                Ab[(kq*4+3)*APITCH + row] = ld[q].w;
            }
            __syncthreads();
            if (c < 15) {
                #pragma unroll
                for (int q=0; q<4; q++) {
                    int idx = q*128 + tid, row = idx >> 2, kq = idx & 3;
                    ld[q] = *(const float4*)(Hin + (long)(m0+row)*NH + (c+1)*16 + kq*4);
                }
            }
            #pragma unroll
            for (int k4 = 0; k4 < 16; k4 += 4) {
                float4 w[3][2];
                #pragma unroll
                for (int g=0; g<3; g++)
                    #pragma unroll
                    for (int jj=0; jj<2; jj++)
                        w[g][jj] = *(const float4*)&Wsm[(g*16 + (tx<<1)+jj)*WPITCH + c*16 + k4];
                #pragma unroll
                for (int kk=0; kk<4; kk++) {
                    const float* ak = Ab + (k4+kk)*APITCH + (ty<<3);
                    ulonglong2 aA = *(const ulonglong2*)ak;        // rows 0-3 (2 pairs)
                    ulonglong2 aB = *(const ulonglong2*)(ak + 4);  // rows 4-7
                    ull ap[4] = {aA.x, aA.y, aB.x, aB.y};
                    #pragma unroll
                    for (int g=0; g<3; g++) {
                        #pragma unroll
                        for (int jj=0; jj<2; jj++) {
                            float ws = (&w[g][jj].x)[kk];
                            ull wd = pack2(ws, ws);
                            #pragma unroll
                            for (int rp=0; rp<4; rp++) ffma2(acc2[g][jj][rp], ap[rp], wd);
                        }
                    }
                }
            }
            __syncthreads();
            buf ^= 1;
        }
        // unpack row-pair accumulators
        float accf[3][8][2];
        #pragma unroll
        for (int g=0; g<3; g++)
            #pragma unroll
            for (int jj=0; jj<2; jj++)
                #pragma unroll
                for (int rp=0; rp<4; rp++) {
                    float2 u = unpack2(acc2[g][jj][rp]);
                    accf[g][2*rp][jj] = u.x;
                    accf[g][2*rp+1][jj] = u.y;
                }
        #pragma unroll
        for (int r=0; r<8; r++) {
            int m = m0 + (ty<<3) + r;
            int tok = tokens[m*NT + t];
            const float* gi = g_TG + (long)tok * G3;
            float h0v = Hin[(long)m*NH + jb];
            float h1v = Hin[(long)m*NH + jb + 1];
            float rr0 = 1.f/(1.f+expf(-(gi[jb]       + accf[0][r][0] + bh[0][0])));
            float zz0 = 1.f/(1.f+expf(-(gi[NH+jb]    + accf[1][r][0] + bh[1][0])));
            float nn0 = tanhf(gi[2*NH+jb] + rr0*(accf[2][r][0] + bh[2][0]));
            Hout[(long)m*NH + jb] = (1.f - zz0)*nn0 + zz0*h0v;
            float rr1 = 1.f/(1.f+expf(-(gi[jb+1]     + accf[0][r][1] + bh[0][1])));
            float zz1 = 1.f/(1.f+expf(-(gi[NH+jb+1]  + accf[1][r][1] + bh[1][1])));
            float nn1 = tanhf(gi[2*NH+jb+1] + rr1*(accf[2][r][1] + bh[2][1]));
            Hout[(long)m*NH + jb + 1] = (1.f - zz1)*nn1 + zz1*h1v;
        }
        if (t < NT-1) {
            __threadfence();
            __syncthreads();
            if (tid == 0) {
                unsigned target = (unsigned)UTILES * (t + 1);
                atomicAdd(&g_ubar, 1u);
                while (*(volatile unsigned*)&g_ubar < target) __nanosleep(64);
                __threadfence();
            }
            __syncthreads();
        }
    }
}

// ------------- fused tail: ctx + SGI-gemm + spk + resp (f32x2 over k) -------------
extern __shared__ float tsm[];
__global__ __launch_bounds__(256) void k_tail(
    const float* __restrict__ cWhh, const float* __restrict__ cbhh,
    const float* __restrict__ sWih, const float* __restrict__ sbih,
    const float* __restrict__ sWhh, const float* __restrict__ sbhh,
    const float* __restrict__ rWhh, const float* __restrict__ rbhh,
    const int* __restrict__ spk, float* __restrict__ out)
{
    float* Wsm = tsm;                          // [48][260]
    float* Asm = tsm + 48*260;                 // [32][260]
    int* flags = (int*)(tsm + 48*260 + 32*260);// [32][51] (spk)
    int tid = threadIdx.x, bid = blockIdx.x;
    int role = (bid < 32) ? 0 : (bid < 64) ? 1 : (bid < 96) ? 2 : 3;
    int rel  = bid - ((role == 0) ? 0 : (role == 1) ? 32 : (role == 2) ? 64 : 96);
    int jt = rel & 15, rt = rel >> 4;
    int j0 = jt*16, m0 = rt*32;
    int tx = tid & 15, ty = tid >> 4;
    int j = j0 + tx;
    const float* W    = (role==0) ? cWhh : (role==1) ? sWih : (role==2) ? sWhh : rWhh;
    const float* bias = (role==0) ? cbhh : (role==1) ? sbih : (role==2) ? sbhh : rbhh;

    for (int i = tid; i < 48*64; i += 256) {
        int r = i >> 6, q = i & 63;
        int g = r >> 4, jj = r & 15;
        *(float4*)&Wsm[r*260 + q*4] = *(const float4*)(W + (long)(g*NH + j0 + jj)*NH + q*4);
    }
    float b0 = bias[j], b1 = bias[NH + j], b2 = bias[2*NH + j];
    if (role == 2) for (int i = tid; i < 32*51; i += 256) flags[i] = 0;
    __syncthreads();

    for (int it = 0; it < NS + 2; ++it) {
        int t = (role == 1) ? it - 1 : (role == 2) ? it - 2 : it;
        bool active = (t >= 0) && (t < NS);
        if (active) {
            if (role == 2) {
                for (int i = tid; i < 32*64; i += 256) {
                    int r = i >> 6, q = i & 63;
                    int b = m0 + r, a = spk[b*NS + t];
                    *(float4*)&Asm[r*260 + q*4] = *(const float4*)(g_Htab + ((long)b*NA + a)*NH + q*4);
                }
                if (tid < 32) flags[tid*51 + spk[(m0+tid)*NS + t]] = 1;
            } else if (role == 1) {
                for (int i = tid; i < 32*64; i += 256) {
                    int r = i >> 6, q = i & 63;
                    *(float4*)&Asm[r*260 + q*4] =
                        *(const float4*)(out + O_CTXOUT + ((long)t*64 + m0 + r)*NH + q*4);
                }
            } else if (t == 0) {
                for (int i = tid; i < 32*64; i += 256) {
                    int r = i >> 6, q = i & 63;
                    *(float4*)&Asm[r*260 + q*4] = make_float4(0.f,0.f,0.f,0.f);
                }
            } else {
                for (int i = tid; i < 32*64; i += 256) {
                    int r = i >> 6, q = i & 63;
                    int m = m0 + r;
                    const float* src = (role == 0)
                        ? out + O_CTXOUT  + ((long)(t-1)*64 + m)*NH
                        : out + O_RESPOUT + (((long)(m&1)*NT + (t-1))*64 + (m>>1))*NH;
                    *(float4*)&Asm[r*260 + q*4] = *(const float4*)(src + q*4);
                }
            }
            __syncthreads();

            ull acc2[3][2] = {};
            #pragma unroll 4
            for (int k0 = 0; k0 < NH; k0 += 4) {
                ulonglong2 w0 = *(const ulonglong2*)&Wsm[tx*260 + k0];
                ulonglong2 w1 = *(const ulonglong2*)&Wsm[(16+tx)*260 + k0];
                ulonglong2 w2 = *(const ulonglong2*)&Wsm[(32+tx)*260 + k0];
                #pragma unroll
                for (int r = 0; r < 2; r++) {
                    ulonglong2 a = *(const ulonglong2*)&Asm[(ty*2+r)*260 + k0];
                    ffma2(acc2[0][r], a.x, w0.x); ffma2(acc2[0][r], a.y, w0.y);
                    ffma2(acc2[1][r], a.x, w1.x); ffma2(acc2[1][r], a.y, w1.y);
                    ffma2(acc2[2][r], a.x, w2.x); ffma2(acc2[2][r], a.y, w2.y);
                }
            }
            float acc[3][2];
            #pragma unroll
            for (int g=0; g<3; g++)
                #pragma unroll
                for (int r=0; r<2; r++) { float2 u = unpack2(acc2[g][r]); acc[g][r] = u.x + u.y; }

            if (role == 1) {
                #pragma unroll
                for (int r = 0; r < 2; r++) {
                    int m = m0 + ty*2 + r;
                    float* o = g_SGI + ((long)t*64 + m)*G3;
                    o[j] = acc[0][r] + b0; o[NH+j] = acc[1][r] + b1; o[2*NH+j] = acc[2][r] + b2;
                }
            } else {
                #pragma unroll
                for (int r = 0; r < 2; r++) {
                    int lr = ty*2 + r, m = m0 + lr;
                    const float* gi = (role == 0) ? g_CGI + ((long)t*64 + m)*G3
                                    : (role == 2) ? g_SGI + ((long)t*64 + m)*G3
                                    :               g_RGI + ((long)t*128 + m)*G3;
                    float rr = 1.f/(1.f+expf(-(gi[j]      + acc[0][r] + b0)));
                    float zz = 1.f/(1.f+expf(-(gi[NH+j]   + acc[1][r] + b1)));
                    float nn = tanhf(gi[2*NH+j] + rr*(acc[2][r] + b2));
                    float hp = Asm[lr*260 + j];
                    float hn = (1.f - zz)*nn + zz*hp;
                    if (role == 0) {
                        out[O_CTXOUT + ((long)t*64 + m)*NH + j] = hn;
                        if (t == NS-1) out[O_CTXHID + (long)m*NH + j] = hn;
                    } else if (role == 3) {
                        out[O_RESPOUT + (((long)(m&1)*NT + t)*64 + (m>>1))*NH + j] = hn;
                        if (t == NS-1) out[O_RESPHID + ((long)(m&1)*64 + (m>>1))*NH + j] = hn;
                    } else {
                        int a = spk[m*NS + t];
                        g_Htab[((long)m*NA + a)*NH + j] = hn;
                    }
                }
            }
        }
        if (it < NS + 1) {
            __threadfence();
            __syncthreads();
            if (tid == 0) {
                atomicAdd(&g_tbar, 1u);
                unsigned target = (unsigned)TBLOCKS * (it + 1);
                while (*(volatile unsigned*)&g_tbar < target) __nanosleep(64);
                __threadfence();
            }
            __syncthreads();
        } else {
            __syncthreads();
        }
    }

    if (role == 2) {
        for (int a = 0; a < NA; a++) {
            #pragma unroll
            for (int r = 0; r < 2; r++) {
                int lb = ty*2 + r, b = m0 + lb;
                float v = flags[lb*51 + a] ? g_Htab[((long)b*NA + a)*NH + j] : 0.f;
                out[O_SPKEMB + ((long)b*NA + a)*NH + j] = v;
            }
        }
        if (jt == 0) {
            for (int i = tid; i < 32*NA; i += 256) {
                int r = i / NA, a = i % NA;
                out[O_SPKMASK + (m0+r)*NA + a] = (flags[r*51 + a] && a > 0) ? 1.f : 0.f;
            }
        }
    }
}

// ------------- ctx GRU input: concat(utter_hidden, agent_emb) -------------
__global__ void k_cin(const int* __restrict__ spk) {
    int idx = blockIdx.x * 256 + threadIdx.x;
    int c = idx & 511, mr = idx >> 9;
    int s = mr >> 6, b = mr & 63;
    float v;
    if (c < NH) v = g_Hu0[(b*NS + s)*NH + c];
    else        v = g_tables[(b*NA + spk[b*NS + s])*NH + (c - NH)];
    g_CIN[idx] = v;
}

// ------------- launch -------------
extern "C" void kernel_launch(void* const* d_in, const int* in_sizes, int n_in,
                              void* d_out, int out_size) {
    (void)in_sizes; (void)n_in; (void)out_size;
    const int*   context = (const int*)d_in[0];
    const int*   response= (const int*)d_in[1];
    const int*   spk     = (const int*)d_in[2];
    const float* emb_u   = (const float*)d_in[3];
    const float* emb_r   = (const float*)d_in[4];
    const float* uWih=(const float*)d_in[5],  *uWhh=(const float*)d_in[6];
    const float* ubih=(const float*)d_in[7],  *ubhh=(const float*)d_in[8];
    const float* cWih=(const float*)d_in[9],  *cWhh=(const float*)d_in[10];
    const float* cbih=(const float*)d_in[11], *cbhh=(const float*)d_in[12];
    const float* rWih=(const float*)d_in[13], *rWhh=(const float*)d_in[14];
    const float* rbih=(const float*)d_in[15], *rbhh=(const float*)d_in[16];
    const float* sWih=(const float*)d_in[17], *sWhh=(const float*)d_in[18];
    const float* sbih=(const float*)d_in[19], *sbhh=(const float*)d_in[20];
    float* out = (float*)d_out;

    void *pTab, *pTG, *pHu0, *pCIN, *pCGI, *pRGI, *pBar, *pTbar, *pHtab;
    cudaGetSymbolAddress(&pTab, g_tables);
    cudaGetSymbolAddress(&pTG,  g_TG);
    cudaGetSymbolAddress(&pHu0, g_Hu0);
    cudaGetSymbolAddress(&pCIN, g_CIN);
    cudaGetSymbolAddress(&pCGI, g_CGI);
    cudaGetSymbolAddress(&pRGI, g_RGI);
    cudaGetSymbolAddress(&pBar, g_ubar);
    cudaGetSymbolAddress(&pTbar, g_tbar);
    cudaGetSymbolAddress(&pHtab, g_Htab);

    cudaFuncSetAttribute(k_ustep_pers, cudaFuncAttributeMaxDynamicSharedMemorySize, USMEM);
    cudaFuncSetAttribute(k_tail,       cudaFuncAttributeMaxDynamicSharedMemorySize, TSMEM);

    cudaMemcpyAsync(pTab, h_tables, sizeof(h_tables), cudaMemcpyHostToDevice, 0);
    cudaMemsetAsync(pHu0, 0, (size_t)NB*NS*NH*sizeof(float), 0);
    cudaMemsetAsync(pBar, 0, sizeof(unsigned), 0);
    cudaMemsetAsync(pTbar, 0, sizeof(unsigned), 0);
    cudaMemsetAsync(pHtab, 0, (size_t)NB*NA*NH*sizeof(float), 0);

    // fork: RGI gemm (independent) overlaps TG gemm + utterance recurrence
    cudaEventRecord(g_evFork, 0);
    cudaStreamWaitEvent(g_s2, g_evFork, 0);
    k_gemm128<<<dim3(50, 6), 256, 0, g_s2>>>(emb_r, response, NH, rWih, rbih, (float*)pRGI);
    cudaEventRecord(g_evJoin, g_s2);

    // utterance token-gate table + persistent recurrence
    k_gemm128<<<dim3(NV/128, 6), 256>>>(emb_u, nullptr, NH, uWih, ubih, (float*)pTG);
    k_ustep_pers<<<dim3(25, 16), 128, USMEM>>>(uWhh, ubhh, context);

    // ctx input + CGI gemm
    k_cin<<<6400, 256>>>(spk);
    k_gemm128<<<dim3(25, 6), 256>>>((const float*)pCIN, nullptr, 2*NH, cWih, cbih, (float*)pCGI);

    // fused tail (needs RGI)
    cudaStreamWaitEvent(0, g_evJoin, 0);
    k_tail<<<TBLOCKS, 256, TSMEM>>>(cWhh, cbhh, sWih, sbih, sWhh, sbhh, rWhh, rbhh, spk, out);
}

// round 14
// speedup vs baseline: 2.3739x; 1.4204x over previous
#include <cuda_runtime.h>
#include <cuda_bf16.h>
#include <math.h>

#define NB 64
#define NS 50
#define NT 50
#define NR 2
#define NV 32000
#define NH 256
#define G3 768
#define NA 51

// output offsets (floats)
#define O_CTXOUT  0
#define O_CTXHID  819200
#define O_RESPOUT 835584
#define O_RESPHID 2473984
#define O_SPKEMB  2506752
#define O_SPKMASK 3342336

// persistent ustep (tensor-core version)
#define UTILES 400
#define UWP 264                      // W smem pitch (bf16 units); 528B rows, conflict-free
#define UW_BYTES (96*UWP*2)          // 48 hi rows + 48 lo rows = 50688B
#define UA_PLANE 6144                // 128 rows * 24 bf16 * 2B
#define USMEM2 (UW_BYTES + 4*UA_PLANE)   // 75264B -> 3 blocks/SM
#define PL (NB*NS*NH)                // bf16 plane stride

// fused tail kernel
#define TBLOCKS 160
#define TSMEM (48*260*4 + 32*260*4 + 32*51*4)

typedef unsigned long long ull;

// ------------- f32x2 helpers (kept for gemm/tail) -------------
__device__ __forceinline__ void ffma2(ull& d, ull a, ull b) {
    asm("fma.rn.f32x2 %0, %1, %2, %0;" : "+l"(d) : "l"(a), "l"(b));
}
__device__ __forceinline__ ull pack2(float x, float y) {
    ull r; asm("mov.b64 %0, {%1, %2};" : "=l"(r) : "f"(x), "f"(y)); return r;
}
__device__ __forceinline__ float2 unpack2(ull v) {
    float2 r; asm("mov.b64 {%0, %1}, %2;" : "=f"(r.x), "=f"(r.y) : "l"(v)); return r;
}

// ------------- tensor-core helpers -------------
__device__ __forceinline__ void ldsm4(unsigned* r, unsigned a) {
    asm volatile("ldmatrix.sync.aligned.m8n8.x4.shared.b16 {%0,%1,%2,%3}, [%4];"
        : "=r"(r[0]), "=r"(r[1]), "=r"(r[2]), "=r"(r[3]) : "r"(a));
}
__device__ __forceinline__ void ldsm2(unsigned* r, unsigned a) {
    asm volatile("ldmatrix.sync.aligned.m8n8.x2.shared.b16 {%0,%1}, [%2];"
        : "=r"(r[0]), "=r"(r[1]) : "r"(a));
}
__device__ __forceinline__ void mma16816(float* c, const unsigned* a, const unsigned* b) {
    asm volatile("mma.sync.aligned.m16n8k16.row.col.f32.bf16.bf16.f32 "
        "{%0,%1,%2,%3}, {%4,%5,%6,%7}, {%8,%9}, {%0,%1,%2,%3};"
        : "+f"(c[0]), "+f"(c[1]), "+f"(c[2]), "+f"(c[3])
        : "r"(a[0]), "r"(a[1]), "r"(a[2]), "r"(a[3]), "r"(b[0]), "r"(b[1]));
}

// ------------- device scratch -------------
__device__ float g_tables[NB*NA*NH];
__device__ float g_TG[NV*G3];
__device__ float g_Hu0[NB*NS*NH];
__device__ float g_Hu1[NB*NS*NH];
__device__ __nv_bfloat16 g_HbfA[2*PL];   // [plane hi/lo][m][k]
__device__ __nv_bfloat16 g_HbfB[2*PL];
__device__ float g_CIN[NS*NB*2*NH];
__device__ float g_CGI[NS*NB*G3];
__device__ float g_SGI[NS*NB*G3];
__device__ float g_RGI[NT*NB*NR*G3];
__device__ float g_Htab[NB*NA*NH];
__device__ unsigned g_ubar;
__device__ unsigned g_tbar;

// ------------- host: exact numpy legacy MT19937 agent tables -------------
static float h_tables[NB*NA*NH];
static cudaStream_t g_s2;
static cudaEvent_t g_evFork, g_evJoin;
namespace {
struct MT {
    unsigned mt[624]; int mti;
    void seed(unsigned s){ mt[0]=s; for(int i=1;i<624;i++) mt[i]=1812433253u*(mt[i-1]^(mt[i-1]>>30))+(unsigned)i; mti=624; }
    unsigned next(){
        if(mti>=624){ for(int i=0;i<624;i++){ unsigned y=(mt[i]&0x80000000u)|(mt[(i+1)%624]&0x7fffffffu);
            mt[i]=mt[(i+397)%624]^(y>>1)^((y&1u)?0x9908b0dfu:0u);} mti=0; }
        unsigned y=mt[mti++]; y^=y>>11; y^=(y<<7)&0x9d2c5680u; y^=(y<<15)&0xefc60000u; y^=y>>18; return y;
    }
};
struct TabInit {
    TabInit(){
        MT m; m.seed(1u);
        for(long i=0;i<(long)NB*NA*NH;i++){
            unsigned a=m.next()>>5, b=m.next()>>6;
            h_tables[i]=(float)(((double)a*67108864.0+(double)b)*(1.0/9007199254740992.0));
        }
        cudaStreamCreateWithFlags(&g_s2, cudaStreamNonBlocking);
        cudaEventCreateWithFlags(&g_evFork, cudaEventDisableTiming);
        cudaEventCreateWithFlags(&g_evJoin, cudaEventDisableTiming);
    }
} g_tabinit;
}

// ------------- 128x128x8 double-buffered SGEMM (f32x2) -------------
__global__ __launch_bounds__(256) void k_gemm128(
    const float* __restrict__ A, const int* __restrict__ map, int K,
    const float* __restrict__ W, const float* __restrict__ bias, float* __restrict__ C)
{
    __shared__ float As[2][8][132];
    __shared__ float Bs[2][8][132];
    int tid = threadIdx.x;
    int m0 = blockIdx.x * 128, n0 = blockIdx.y * 128;
    int tx = tid & 15, ty = tid >> 4;
    int lr = tid >> 1, lk = (tid & 1) * 4;
    int arow = m0 + lr;
    int row = map ? map[(arow & 127) * NT + (arow >> 7)] : arow;
    const float* ap = A + (long)row * K + lk;
    const float* wp = W + (long)(n0 + lr) * K + lk;
    ull acc2[8][4] = {};
    float4 av = *(const float4*)ap;
    float4 wv = *(const float4*)wp;
    int buf = 0;
    for (int k0 = 0; k0 < K; k0 += 8) {
        As[buf][lk+0][lr]=av.x; As[buf][lk+1][lr]=av.y; As[buf][lk+2][lr]=av.z; As[buf][lk+3][lr]=av.w;
        Bs[buf][lk+0][lr]=wv.x; Bs[buf][lk+1][lr]=wv.y; Bs[buf][lk+2][lr]=wv.z; Bs[buf][lk+3][lr]=wv.w;
        __syncthreads();
        if (k0 + 8 < K) { av = *(const float4*)(ap + k0 + 8); wv = *(const float4*)(wp + k0 + 8); }
        #pragma unroll
        for (int k = 0; k < 8; k++) {
            float4 a0 = *(const float4*)&As[buf][k][ty*4];
            float4 a1 = *(const float4*)&As[buf][k][64 + ty*4];
            ulonglong2 bA = *(const ulonglong2*)&Bs[buf][k][tx*4];
            ulonglong2 bB = *(const ulonglong2*)&Bs[buf][k][64 + tx*4];
            ull bp[4] = {bA.x, bA.y, bB.x, bB.y};
            float ar[8] = {a0.x,a0.y,a0.z,a0.w,a1.x,a1.y,a1.z,a1.w};
            #pragma unroll
            for (int i=0;i<8;i++) {
                ull ad = pack2(ar[i], ar[i]);
                #pragma unroll
                for (int jp=0;jp<4;jp++) ffma2(acc2[i][jp], ad, bp[jp]);
            }
        }
        buf ^= 1;
    }
    float4 bs0 = *(const float4*)(bias + n0 + tx*4);
    float4 bs1 = *(const float4*)(bias + n0 + 64 + tx*4);
    #pragma unroll
    for (int i=0;i<8;i++) {
        int m = m0 + ((i<4) ? (ty*4+i) : (64+ty*4+i-4));
        float2 u0 = unpack2(acc2[i][0]), u1 = unpack2(acc2[i][1]);
        float2 u2 = unpack2(acc2[i][2]), u3 = unpack2(acc2[i][3]);
        float4 o0, o1;
        o0.x=u0.x+bs0.x; o0.y=u0.y+bs0.y; o0.z=u1.x+bs0.z; o0.w=u1.y+bs0.w;
        o1.x=u2.x+bs1.x; o1.y=u2.y+bs1.y; o1.z=u3.x+bs1.z; o1.w=u3.y+bs1.w;
        *(float4*)(C + (long)m*G3 + n0 + tx*4)      = o0;
        *(float4*)(C + (long)m*G3 + n0 + 64 + tx*4) = o1;
    }
}

// ------------- persistent utterance GRU on tensor cores (bf16 hi/lo split) -------------
extern __shared__ float usm[];
__global__ __launch_bounds__(128, 3) void k_ustep_mma(
    const float* __restrict__ Whh, const float* __restrict__ bhh,
    const int* __restrict__ tokens)
{
    __nv_bfloat16* Wm = (__nv_bfloat16*)usm;                     // 96 rows x UWP
    __nv_bfloat16* Am = (__nv_bfloat16*)((char*)usm + UW_BYTES); // [buf][plane][128*24]
    int tid = threadIdx.x, lane = tid & 31, w = tid >> 5;
    int m0 = blockIdx.x * 128, j0 = blockIdx.y * 16;

    // W -> smem bf16 hi/lo, once
    for (int i = tid; i < 48*64; i += 128) {
        int r = i >> 6, q = i & 63;
        int g = r >> 4, jj = r & 15;
        float4 v = *(const float4*)(Whh + (long)(g*NH + j0 + jj)*NH + q*4);
        float e[4] = {v.x, v.y, v.z, v.w};
        __nv_bfloat16* ph = Wm + r*UWP + q*4;
        __nv_bfloat16* pl = Wm + (r+48)*UWP + q*4;
        #pragma unroll
        for (int k = 0; k < 4; k++) {
            __nv_bfloat16 h = __float2bfloat16(e[k]);
            ph[k] = h;
            pl[k] = __float2bfloat16(e[k] - __bfloat162float(h));
        }
    }
    // bias regs: [g][jt2][ci]
    float bh[3][2][2];
    #pragma unroll
    for (int g=0; g<3; g++)
        #pragma unroll
        for (int jt2=0; jt2<2; jt2++)
            #pragma unroll
            for (int ci=0; ci<2; ci++)
                bh[g][jt2][ci] = bhh[g*NH + j0 + jt2*8 + (lane&3)*2 + ci];
    __syncthreads();

    unsigned wsm = (unsigned)__cvta_generic_to_shared(Wm);
    unsigned asmb = (unsigned)__cvta_generic_to_shared(Am);
    unsigned baddr[6][2];
    #pragma unroll
    for (int nt=0; nt<6; nt++)
        #pragma unroll
        for (int pl=0; pl<2; pl++) {
            int wr = pl*48 + nt*8 + (lane & 7);
            baddr[nt][pl] = wsm + (unsigned)(wr*UWP*2 + ((lane>>3)&1)*16);
        }
    unsigned aaddr[2][2];
    #pragma unroll
    for (int mt=0; mt<2; mt++) {
        int ar = w*32 + mt*16 + (lane & 7) + ((lane>>3)&1)*8;
        #pragma unroll
        for (int pl=0; pl<2; pl++)
            aaddr[mt][pl] = asmb + (unsigned)(pl*UA_PLANE + ar*48 + (lane>>4)*16);
    }

    for (int t = 0; t < NT; t++) {
        const float* Hin  = (t & 1) ? g_Hu1 : g_Hu0;
        float*       Hout = (t & 1) ? g_Hu0 : g_Hu1;
        const __nv_bfloat16* Rbf = (t & 1) ? g_HbfB : g_HbfA;
        __nv_bfloat16*       Wbf = (t & 1) ? g_HbfA : g_HbfB;

        float acc[2][6][4] = {};
        uint2 ph[4], plo[4];
        #pragma unroll
        for (int q=0; q<4; q++) {
            int idx = q*128 + tid, row = idx >> 2, kq = (idx & 3)*4;
            ph[q]  = *(const uint2*)(Rbf +      (long)(m0+row)*NH + kq);
            plo[q] = *(const uint2*)(Rbf + PL + (long)(m0+row)*NH + kq);
        }
        int buf = 0;
        for (int c = 0; c < 16; c++) {
            __nv_bfloat16* Ahi = Am + buf*6144;
            __nv_bfloat16* Alo = Ahi + 3072;
            #pragma unroll
            for (int q=0; q<4; q++) {
                int idx = q*128 + tid, row = idx >> 2, kq = (idx & 3)*4;
                *(uint2*)(Ahi + row*24 + kq) = ph[q];
                *(uint2*)(Alo + row*24 + kq) = plo[q];
            }
            __syncthreads();
            if (c < 15) {
                #pragma unroll
                for (int q=0; q<4; q++) {
                    int idx = q*128 + tid, row = idx >> 2, kq = (idx & 3)*4;
                    ph[q]  = *(const uint2*)(Rbf +      (long)(m0+row)*NH + (c+1)*16 + kq);
                    plo[q] = *(const uint2*)(Rbf + PL + (long)(m0+row)*NH + (c+1)*16 + kq);
                }
            }
            unsigned bfr[6][2][2];
            #pragma unroll
            for (int nt=0; nt<6; nt++)
                #pragma unroll
                for (int pl=0; pl<2; pl++)
                    ldsm2(bfr[nt][pl], baddr[nt][pl] + c*32);
            unsigned afr[2][2][4];
            #pragma unroll
            for (int mt=0; mt<2; mt++)
                #pragma unroll
                for (int pl=0; pl<2; pl++)
                    ldsm4(afr[mt][pl], aaddr[mt][pl] + buf*12288);
            #pragma unroll
            for (int mt=0; mt<2; mt++)
                #pragma unroll
                for (int nt=0; nt<6; nt++) {
                    mma16816(acc[mt][nt], afr[mt][0], bfr[nt][0]);  // hi*hi
                    mma16816(acc[mt][nt], afr[mt][1], bfr[nt][0]);  // lo*hi
                    mma16816(acc[mt][nt], afr[mt][0], bfr[nt][1]);  // hi*lo
                }
            buf ^= 1;
        }
        // epilogue: gates + fp32 h update + bf16 hi/lo write for next step
        #pragma unroll
        for (int mt=0; mt<2; mt++)
            #pragma unroll
            for (int rh=0; rh<2; rh++) {
                int m = m0 + w*32 + mt*16 + (lane>>2) + rh*8;
                int tok = tokens[m*NT + t];
                const float* gi = g_TG + (long)tok * G3;
                int fi = rh*2;
                #pragma unroll
                for (int jt2=0; jt2<2; jt2++) {
                    int jb2 = j0 + jt2*8 + (lane&3)*2;
                    float2 gr2 = *(const float2*)(gi + jb2);
                    float2 gz2 = *(const float2*)(gi + NH + jb2);
                    float2 gn2 = *(const float2*)(gi + 2*NH + jb2);
                    float2 ho  = *(const float2*)(Hin + (long)m*NH + jb2);
                    float r0 = 1.f/(1.f+expf(-(gr2.x + acc[mt][jt2][fi]   + bh[0][jt2][0])));
                    float z0 = 1.f/(1.f+expf(-(gz2.x + acc[mt][2+jt2][fi] + bh[1][jt2][0])));
                    float n0 = tanhf(gn2.x + r0*(acc[mt][4+jt2][fi] + bh[2][jt2][0]));
                    float h0 = (1.f - z0)*n0 + z0*ho.x;
                    float r1 = 1.f/(1.f+expf(-(gr2.y + acc[mt][jt2][fi+1]   + bh[0][jt2][1])));
                    float z1 = 1.f/(1.f+expf(-(gz2.y + acc[mt][2+jt2][fi+1] + bh[1][jt2][1])));
                    float n1 = tanhf(gn2.y + r1*(acc[mt][4+jt2][fi+1] + bh[2][jt2][1]));
                    float h1 = (1.f - z1)*n1 + z1*ho.y;
                    float2 hv; hv.x = h0; hv.y = h1;
                    *(float2*)(Hout + (long)m*NH + jb2) = hv;
                    __nv_bfloat16 b0 = __float2bfloat16(h0);
                    __nv_bfloat16 b1 = __float2bfloat16(h1);
                    __nv_bfloat162 hp; hp.x = b0; hp.y = b1;
                    *(__nv_bfloat162*)(Wbf + (long)m*NH + jb2) = hp;
                    __nv_bfloat162 lp;
                    lp.x = __float2bfloat16(h0 - __bfloat162float(b0));
                    lp.y = __float2bfloat16(h1 - __bfloat162float(b1));
                    *(__nv_bfloat162*)(Wbf + PL + (long)m*NH + jb2) = lp;
                }
            }
        if (t < NT-1) {
            __threadfence();
            __syncthreads();
            if (tid == 0) {
                unsigned target = (unsigned)UTILES * (t + 1);
                atomicAdd(&g_ubar, 1u);
                while (*(volatile unsigned*)&g_ubar < target) __nanosleep(64);
                __threadfence();
            }
            __syncthreads();
        }
    }
}

// ------------- fused tail: ctx + SGI-gemm + spk + resp (f32x2 over k) -------------
extern __shared__ float tsm[];
__global__ __launch_bounds__(256) void k_tail(
    const float* __restrict__ cWhh, const float* __restrict__ cbhh,
    const float* __restrict__ sWih, const float* __restrict__ sbih,
    const float* __restrict__ sWhh, const float* __restrict__ sbhh,
    const float* __restrict__ rWhh, const float* __restrict__ rbhh,
    const int* __restrict__ spk, float* __restrict__ out)
{
    float* Wsm = tsm;
    float* Asm = tsm + 48*260;
    int* flags = (int*)(tsm + 48*260 + 32*260);
    int tid = threadIdx.x, bid = blockIdx.x;
    int role = (bid < 32) ? 0 : (bid < 64) ? 1 : (bid < 96) ? 2 : 3;
    int rel  = bid - ((role == 0) ? 0 : (role == 1) ? 32 : (role == 2) ? 64 : 96);
    int jt = rel & 15, rt = rel >> 4;
    int j0 = jt*16, m0 = rt*32;
    int tx = tid & 15, ty = tid >> 4;
    int j = j0 + tx;
    const float* W    = (role==0) ? cWhh : (role==1) ? sWih : (role==2) ? sWhh : rWhh;
    const float* bias = (role==0) ? cbhh : (role==1) ? sbih : (role==2) ? sbhh : rbhh;

    for (int i = tid; i < 48*64; i += 256) {
        int r = i >> 6, q = i & 63;
        int g = r >> 4, jj = r & 15;
        *(float4*)&Wsm[r*260 + q*4] = *(const float4*)(W + (long)(g*NH + j0 + jj)*NH + q*4);
    }
    float b0 = bias[j], b1 = bias[NH + j], b2 = bias[2*NH + j];
    if (role == 2) for (int i = tid; i < 32*51; i += 256) flags[i] = 0;
    __syncthreads();

    for (int it = 0; it < NS + 2; ++it) {
        int t = (role == 1) ? it - 1 : (role == 2) ? it - 2 : it;
        bool active = (t >= 0) && (t < NS);
        if (active) {
            if (role == 2) {
                for (int i = tid; i < 32*64; i += 256) {
                    int r = i >> 6, q = i & 63;
                    int b = m0 + r, a = spk[b*NS + t];
                    *(float4*)&Asm[r*260 + q*4] = *(const float4*)(g_Htab + ((long)b*NA + a)*NH + q*4);
                }
                if (tid < 32) flags[tid*51 + spk[(m0+tid)*NS + t]] = 1;
            } else if (role == 1) {
                for (int i = tid; i < 32*64; i += 256) {
                    int r = i >> 6, q = i & 63;
                    *(float4*)&Asm[r*260 + q*4] =
                        *(const float4*)(out + O_CTXOUT + ((long)t*64 + m0 + r)*NH + q*4);
                }
            } else if (t == 0) {
                for (int i = tid; i < 32*64; i += 256) {
                    int r = i >> 6, q = i & 63;
                    *(float4*)&Asm[r*260 + q*4] = make_float4(0.f,0.f,0.f,0.f);
                }
            } else {
                for (int i = tid; i < 32*64; i += 256) {
                    int r = i >> 6, q = i & 63;
                    int m = m0 + r;
                    const float* src = (role == 0)
                        ? out + O_CTXOUT  + ((long)(t-1)*64 + m)*NH
                        : out + O_RESPOUT + (((long)(m&1)*NT + (t-1))*64 + (m>>1))*NH;
                    *(float4*)&Asm[r*260 + q*4] = *(const float4*)(src + q*4);
                }
            }
            __syncthreads();

            ull acc2[3][2] = {};
            #pragma unroll 4
            for (int k0 = 0; k0 < NH; k0 += 4) {
                ulonglong2 w0 = *(const ulonglong2*)&Wsm[tx*260 + k0];
                ulonglong2 w1 = *(const ulonglong2*)&Wsm[(16+tx)*260 + k0];
                ulonglong2 w2 = *(const ulonglong2*)&Wsm[(32+tx)*260 + k0];
                #pragma unroll
                for (int r = 0; r < 2; r++) {
                    ulonglong2 a = *(const ulonglong2*)&Asm[(ty*2+r)*260 + k0];
                    ffma2(acc2[0][r], a.x, w0.x); ffma2(acc2[0][r], a.y, w0.y);
                    ffma2(acc2[1][r], a.x, w1.x); ffma2(acc2[1][r], a.y, w1.y);
                    ffma2(acc2[2][r], a.x, w2.x); ffma2(acc2[2][r], a.y, w2.y);
                }
            }
            float acc[3][2];
            #pragma unroll
            for (int g=0; g<3; g++)
                #pragma unroll
                for (int r=0; r<2; r++) { float2 u = unpack2(acc2[g][r]); acc[g][r] = u.x + u.y; }

            if (role == 1) {
                #pragma unroll
                for (int r = 0; r < 2; r++) {
                    int m = m0 + ty*2 + r;
                    float* o = g_SGI + ((long)t*64 + m)*G3;
                    o[j] = acc[0][r] + b0; o[NH+j] = acc[1][r] + b1; o[2*NH+j] = acc[2][r] + b2;
                }
            } else {
                #pragma unroll
                for (int r = 0; r < 2; r++) {
                    int lr = ty*2 + r, m = m0 + lr;
                    const float* gi = (role == 0) ? g_CGI + ((long)t*64 + m)*G3
                                    : (role == 2) ? g_SGI + ((long)t*64 + m)*G3
                                    :               g_RGI + ((long)t*128 + m)*G3;
                    float rr = 1.f/(1.f+expf(-(gi[j]      + acc[0][r] + b0)));
                    float zz = 1.f/(1.f+expf(-(gi[NH+j]   + acc[1][r] + b1)));
                    float nn = tanhf(gi[2*NH+j] + rr*(acc[2][r] + b2));
                    float hp = Asm[lr*260 + j];
                    float hn = (1.f - zz)*nn + zz*hp;
                    if (role == 0) {
                        out[O_CTXOUT + ((long)t*64 + m)*NH + j] = hn;
                        if (t == NS-1) out[O_CTXHID + (long)m*NH + j] = hn;
                    } else if (role == 3) {
                        out[O_RESPOUT + (((long)(m&1)*NT + t)*64 + (m>>1))*NH + j] = hn;
                        if (t == NS-1) out[O_RESPHID + ((long)(m&1)*64 + (m>>1))*NH + j] = hn;
                    } else {
                        int a = spk[m*NS + t];
                        g_Htab[((long)m*NA + a)*NH + j] = hn;
                    }
                }
            }
        }
        if (it < NS + 1) {
            __threadfence();
            __syncthreads();
            if (tid == 0) {
                atomicAdd(&g_tbar, 1u);
                unsigned target = (unsigned)TBLOCKS * (it + 1);
                while (*(volatile unsigned*)&g_tbar < target) __nanosleep(64);
                __threadfence();
            }
            __syncthreads();
        } else {
            __syncthreads();
        }
    }

    if (role == 2) {
        for (int a = 0; a < NA; a++) {
            #pragma unroll
            for (int r = 0; r < 2; r++) {
                int lb = ty*2 + r, b = m0 + lb;
                float v = flags[lb*51 + a] ? g_Htab[((long)b*NA + a)*NH + j] : 0.f;
                out[O_SPKEMB + ((long)b*NA + a)*NH + j] = v;
            }
        }
        if (jt == 0) {
            for (int i = tid; i < 32*NA; i += 256) {
                int r = i / NA, a = i % NA;
                out[O_SPKMASK + (m0+r)*NA + a] = (flags[r*51 + a] && a > 0) ? 1.f : 0.f;
            }
        }
    }
}

// ------------- ctx GRU input: concat(utter_hidden, agent_emb) -------------
__global__ void k_cin(const int* __restrict__ spk) {
    int idx = blockIdx.x * 256 + threadIdx.x;
    int c = idx & 511, mr = idx >> 9;
    int s = mr >> 6, b = mr & 63;
    float v;
    if (c < NH) v = g_Hu0[(b*NS + s)*NH + c];
    else        v = g_tables[(b*NA + spk[b*NS + s])*NH + (c - NH)];
    g_CIN[idx] = v;
}

// ------------- launch -------------
extern "C" void kernel_launch(void* const* d_in, const int* in_sizes, int n_in,
                              void* d_out, int out_size) {
    (void)in_sizes; (void)n_in; (void)out_size;
    const int*   context = (const int*)d_in[0];
    const int*   response= (const int*)d_in[1];
    const int*   spk     = (const int*)d_in[2];
    const float* emb_u   = (const float*)d_in[3];
    const float* emb_r   = (const float*)d_in[4];
    const float* uWih=(const float*)d_in[5],  *uWhh=(const float*)d_in[6];
    const float* ubih=(const float*)d_in[7],  *ubhh=(const float*)d_in[8];
    const float* cWih=(const float*)d_in[9],  *cWhh=(const float*)d_in[10];
    const float* cbih=(const float*)d_in[11], *cbhh=(const float*)d_in[12];
    const float* rWih=(const float*)d_in[13], *rWhh=(const float*)d_in[14];
    const float* rbih=(const float*)d_in[15], *rbhh=(const float*)d_in[16];
    const float* sWih=(const float*)d_in[17], *sWhh=(const float*)d_in[18];
    const float* sbih=(const float*)d_in[19], *sbhh=(const float*)d_in[20];
    float* out = (float*)d_out;

    void *pTab, *pTG, *pHu0, *pCIN, *pCGI, *pRGI, *pBar, *pTbar, *pHtab, *pBfA;
    cudaGetSymbolAddress(&pTab, g_tables);
    cudaGetSymbolAddress(&pTG,  g_TG);
    cudaGetSymbolAddress(&pHu0, g_Hu0);
    cudaGetSymbolAddress(&pCIN, g_CIN);
    cudaGetSymbolAddress(&pCGI, g_CGI);
    cudaGetSymbolAddress(&pRGI, g_RGI);
    cudaGetSymbolAddress(&pBar, g_ubar);
    cudaGetSymbolAddress(&pTbar, g_tbar);
    cudaGetSymbolAddress(&pHtab, g_Htab);
    cudaGetSymbolAddress(&pBfA, g_HbfA);

    cudaFuncSetAttribute(k_ustep_mma, cudaFuncAttributeMaxDynamicSharedMemorySize, USMEM2);
    cudaFuncSetAttribute(k_tail,      cudaFuncAttributeMaxDynamicSharedMemorySize, TSMEM);

    cudaMemcpyAsync(pTab, h_tables, sizeof(h_tables), cudaMemcpyHostToDevice, 0);
    cudaMemsetAsync(pHu0, 0, (size_t)NB*NS*NH*sizeof(float), 0);
    cudaMemsetAsync(pBfA, 0, (size_t)2*PL*sizeof(__nv_bfloat16), 0);
    cudaMemsetAsync(pBar, 0, sizeof(unsigned), 0);
    cudaMemsetAsync(pTbar, 0, sizeof(unsigned), 0);
    cudaMemsetAsync(pHtab, 0, (size_t)NB*NA*NH*sizeof(float), 0);

    // fork: RGI gemm (independent) overlaps TG gemm + utterance recurrence
    cudaEventRecord(g_evFork, 0);
    cudaStreamWaitEvent(g_s2, g_evFork, 0);
    k_gemm128<<<dim3(50, 6), 256, 0, g_s2>>>(emb_r, response, NH, rWih, rbih, (float*)pRGI);
    cudaEventRecord(g_evJoin, g_s2);

    // utterance token-gate table + persistent tensor-core recurrence
    k_gemm128<<<dim3(NV/128, 6), 256>>>(emb_u, nullptr, NH, uWih, ubih, (float*)pTG);
    k_ustep_mma<<<dim3(25, 16), 128, USMEM2>>>(uWhh, ubhh, context);

    // ctx input + CGI gemm
    k_cin<<<6400, 256>>>(spk);
    k_gemm128<<<dim3(25, 6), 256>>>((const float*)pCIN, nullptr, 2*NH, cWih, cbih, (float*)pCGI);

    // fused tail (needs RGI)
    cudaStreamWaitEvent(0, g_evJoin, 0);
    k_tail<<<TBLOCKS, 256, TSMEM>>>(cWhh, cbhh, sWih, sbih, sWhh, sbhh, rWhh, rbhh, spk, out);
}

// round 15
// speedup vs baseline: 2.7095x; 1.1414x over previous
#include <cuda_runtime.h>
#include <cuda_bf16.h>
#include <math.h>

#define NB 64
#define NS 50
#define NT 50
#define NR 2
#define NV 32000
#define NH 256
#define G3 768
#define NA 51

// output offsets (floats)
#define O_CTXOUT  0
#define O_CTXHID  819200
#define O_RESPOUT 835584
#define O_RESPHID 2473984
#define O_SPKEMB  2506752
#define O_SPKMASK 3342336

// persistent ustep (tensor-core version)
#define UTILES 400
#define UWP 264
#define UW_BYTES (96*UWP*2)
#define UA_PLANE 6144
#define USMEM2 (UW_BYTES + 4*UA_PLANE)
#define PL (NB*NS*NH)

// fused tail kernel
#define TBLOCKS 160
#define TSMEM (48*260*4 + 32*260*4 + 32*51*4)

// tensor-core GEMM (TG) tiling
#define GC_APITCH 40
#define GC_APLANE (128*GC_APITCH)
#define GC_ABUF (2*GC_APLANE)
#define GC_BPLANE (64*GC_APITCH)
#define GC_BBUF (2*GC_BPLANE)
#define GCSMEM ((2*GC_ABUF + 2*GC_BBUF)*2)   // 61440 bytes

typedef unsigned long long ull;

// ------------- f32x2 helpers -------------
__device__ __forceinline__ void ffma2(ull& d, ull a, ull b) {
    asm("fma.rn.f32x2 %0, %1, %2, %0;" : "+l"(d) : "l"(a), "l"(b));
}
__device__ __forceinline__ ull pack2(float x, float y) {
    ull r; asm("mov.b64 %0, {%1, %2};" : "=l"(r) : "f"(x), "f"(y)); return r;
}
__device__ __forceinline__ float2 unpack2(ull v) {
    float2 r; asm("mov.b64 {%0, %1}, %2;" : "=f"(r.x), "=f"(r.y) : "l"(v)); return r;
}

// ------------- tensor-core helpers -------------
__device__ __forceinline__ void ldsm4(unsigned* r, unsigned a) {
    asm volatile("ldmatrix.sync.aligned.m8n8.x4.shared.b16 {%0,%1,%2,%3}, [%4];"
        : "=r"(r[0]), "=r"(r[1]), "=r"(r[2]), "=r"(r[3]) : "r"(a));
}
__device__ __forceinline__ void ldsm2(unsigned* r, unsigned a) {
    asm volatile("ldmatrix.sync.aligned.m8n8.x2.shared.b16 {%0,%1}, [%2];"
        : "=r"(r[0]), "=r"(r[1]) : "r"(a));
}
__device__ __forceinline__ void mma16816(float* c, const unsigned* a, const unsigned* b) {
    asm volatile("mma.sync.aligned.m16n8k16.row.col.f32.bf16.bf16.f32 "
        "{%0,%1,%2,%3}, {%4,%5,%6,%7}, {%8,%9}, {%0,%1,%2,%3};"
        : "+f"(c[0]), "+f"(c[1]), "+f"(c[2]), "+f"(c[3])
        : "r"(a[0]), "r"(a[1]), "r"(a[2]), "r"(a[3]), "r"(b[0]), "r"(b[1]));
}
__device__ __forceinline__ void cpa16(unsigned sm, const void* gm) {
    asm volatile("cp.async.ca.shared.global [%0], [%1], 16;" :: "r"(sm), "l"(gm));
}
__device__ __forceinline__ void cpa_commit() { asm volatile("cp.async.commit_group;"); }
template<int N> __device__ __forceinline__ void cpa_wait() {
    asm volatile("cp.async.wait_group %0;" :: "n"(N));
}

// ------------- device scratch -------------
__device__ float g_tables[NB*NA*NH];
__device__ float g_TG[NV*G3];
__device__ float g_Hu0[NB*NS*NH];
__device__ float g_Hu1[NB*NS*NH];
__device__ __nv_bfloat16 g_HbfA[2*PL];
__device__ __nv_bfloat16 g_HbfB[2*PL];
__device__ __nv_bfloat16 g_Ebf[2*NV*NH];     // emb_utter hi/lo
__device__ __nv_bfloat16 g_Wubf[2*G3*NH];    // utter_Wih hi/lo
__device__ float g_CIN[NS*NB*2*NH];
__device__ float g_CGI[NS*NB*G3];
__device__ float g_SGI[NS*NB*G3];
__device__ float g_RGI[NT*NB*NR*G3];
__device__ float g_Htab[NB*NA*NH];
__device__ unsigned g_ubar;
__device__ unsigned g_tbar;

// ------------- host: exact numpy legacy MT19937 agent tables -------------
static float h_tables[NB*NA*NH];
static cudaStream_t g_s2;
static cudaEvent_t g_evFork, g_evJoin;
namespace {
struct MT {
    unsigned mt[624]; int mti;
    void seed(unsigned s){ mt[0]=s; for(int i=1;i<624;i++) mt[i]=1812433253u*(mt[i-1]^(mt[i-1]>>30))+(unsigned)i; mti=624; }
    unsigned next(){
        if(mti>=624){ for(int i=0;i<624;i++){ unsigned y=(mt[i]&0x80000000u)|(mt[(i+1)%624]&0x7fffffffu);
            mt[i]=mt[(i+397)%624]^(y>>1)^((y&1u)?0x9908b0dfu:0u);} mti=0; }
        unsigned y=mt[mti++]; y^=y>>11; y^=(y<<7)&0x9d2c5680u; y^=(y<<15)&0xefc60000u; y^=y>>18; return y;
    }
};
struct TabInit {
    TabInit(){
        MT m; m.seed(1u);
        for(long i=0;i<(long)NB*NA*NH;i++){
            unsigned a=m.next()>>5, b=m.next()>>6;
            h_tables[i]=(float)(((double)a*67108864.0+(double)b)*(1.0/9007199254740992.0));
        }
        cudaStreamCreateWithFlags(&g_s2, cudaStreamNonBlocking);
        cudaEventCreateWithFlags(&g_evFork, cudaEventDisableTiming);
        cudaEventCreateWithFlags(&g_evJoin, cudaEventDisableTiming);
    }
} g_tabinit;
}

// ------------- fp32 -> bf16 hi/lo conversion -------------
__global__ void k_cvt(const float* __restrict__ src, __nv_bfloat16* __restrict__ hi,
                      __nv_bfloat16* __restrict__ lo, int n4)
{
    int i = blockIdx.x * 256 + threadIdx.x;
    if (i >= n4) return;
    float4 v = ((const float4*)src)[i];
    float e[4] = {v.x, v.y, v.z, v.w};
    __nv_bfloat16 h[4], l[4];
    #pragma unroll
    for (int k = 0; k < 4; k++) {
        h[k] = __float2bfloat16(e[k]);
        l[k] = __float2bfloat16(e[k] - __bfloat162float(h[k]));
    }
    __nv_bfloat162 h0; h0.x = h[0]; h0.y = h[1];
    __nv_bfloat162 h1; h1.x = h[2]; h1.y = h[3];
    __nv_bfloat162 l0; l0.x = l[0]; l0.y = l[1];
    __nv_bfloat162 l1; l1.x = l[2]; l1.y = l[3];
    ((__nv_bfloat162*)hi)[2*i]   = h0;
    ((__nv_bfloat162*)hi)[2*i+1] = h1;
    ((__nv_bfloat162*)lo)[2*i]   = l0;
    ((__nv_bfloat162*)lo)[2*i+1] = l1;
}

// ------------- tensor-core GEMM: C[M][768] = Abf @ Wbf^T + bias (bf16 hi/lo, K=256) -------------
// grid (12, M/128): x = n-tile(64), y = m-tile(128). block 128.
extern __shared__ float usm[];
__global__ __launch_bounds__(128) void k_gemmtc(
    const __nv_bfloat16* __restrict__ Abf, long sA,
    const __nv_bfloat16* __restrict__ Wbf, long sW,
    const float* __restrict__ bias, float* __restrict__ C)
{
    __nv_bfloat16* gsm = (__nv_bfloat16*)usm;
    int tid = threadIdx.x, lane = tid & 31, w = tid >> 5;
    int n0 = blockIdx.x * 64, m0 = blockIdx.y * 128;
    unsigned asmb = (unsigned)__cvta_generic_to_shared(gsm);

    // ldsm base addresses
    unsigned aBase[2][2], bBase[8][2];
    #pragma unroll
    for (int mt=0; mt<2; mt++)
        #pragma unroll
        for (int pl=0; pl<2; pl++) {
            int row = w*32 + mt*16 + (lane&7) + ((lane>>3)&1)*8;
            aBase[mt][pl] = asmb + (unsigned)((pl*GC_APLANE + row*GC_APITCH)*2) + (lane>>4)*16;
        }
    #pragma unroll
    for (int nt=0; nt<8; nt++)
        #pragma unroll
        for (int pl=0; pl<2; pl++) {
            int row = nt*8 + (lane&7);
            bBase[nt][pl] = asmb + (unsigned)((2*GC_ABUF + pl*GC_BPLANE + row*GC_APITCH)*2)
                          + ((lane>>3)&1)*16;
        }

    auto issue = [&](int c, int b) {
        #pragma unroll
        for (int p2=0; p2<4; p2++) {
            int idx = p2*128 + tid, row = idx >> 2, kq = (idx & 3)*8;
            #pragma unroll
            for (int pl=0; pl<2; pl++)
                cpa16(asmb + (unsigned)((b*GC_ABUF + pl*GC_APLANE + row*GC_APITCH + kq)*2),
                      (const void*)(Abf + pl*sA + (long)(m0+row)*NH + c*32 + kq));
        }
        #pragma unroll
        for (int p2=0; p2<2; p2++) {
            int idx = p2*128 + tid, row = idx >> 2, kq = (idx & 3)*8;
            #pragma unroll
            for (int pl=0; pl<2; pl++)
                cpa16(asmb + (unsigned)((2*GC_ABUF + b*GC_BBUF + pl*GC_BPLANE + row*GC_APITCH + kq)*2),
                      (const void*)(Wbf + pl*sW + (long)(n0+row)*NH + c*32 + kq));
        }
        cpa_commit();
    };

    float acc[2][8][4] = {};
    issue(0, 0);
    for (int c = 0; c < 8; c++) {
        int b = c & 1;
        if (c < 7) issue(c+1, b^1);
        if (c < 7) { cpa_wait<1>(); } else { cpa_wait<0>(); }
        __syncthreads();
        #pragma unroll
        for (int h = 0; h < 2; h++) {
            unsigned afr[2][2][4];
            #pragma unroll
            for (int mt=0; mt<2; mt++)
                #pragma unroll
                for (int pl=0; pl<2; pl++)
                    ldsm4(afr[mt][pl], aBase[mt][pl] + b*GC_ABUF*2 + h*32);
            unsigned bfr[8][2][2];
            #pragma unroll
            for (int nt=0; nt<8; nt++)
                #pragma unroll
                for (int pl=0; pl<2; pl++)
                    ldsm2(bfr[nt][pl], bBase[nt][pl] + b*GC_BBUF*2 + h*32);
            #pragma unroll
            for (int mt=0; mt<2; mt++)
                #pragma unroll
                for (int nt=0; nt<8; nt++) {
                    mma16816(acc[mt][nt], afr[mt][0], bfr[nt][0]);
                    mma16816(acc[mt][nt], afr[mt][1], bfr[nt][0]);
                    mma16816(acc[mt][nt], afr[mt][0], bfr[nt][1]);
                }
        }
        __syncthreads();
    }
    #pragma unroll
    for (int mt=0; mt<2; mt++) {
        int row = m0 + w*32 + mt*16 + (lane>>2);
        #pragma unroll
        for (int nt=0; nt<8; nt++) {
            int col = n0 + nt*8 + (lane&3)*2;
            float2 bb = *(const float2*)(bias + col);
            float2 s0, s1;
            s0.x = acc[mt][nt][0] + bb.x; s0.y = acc[mt][nt][1] + bb.y;
            s1.x = acc[mt][nt][2] + bb.x; s1.y = acc[mt][nt][3] + bb.y;
            *(float2*)(C + (long)row*G3 + col)     = s0;
            *(float2*)(C + (long)(row+8)*G3 + col) = s1;
        }
    }
}

// ------------- 128x128x8 double-buffered SGEMM (f32x2) — CGI/RGI -------------
__global__ __launch_bounds__(256) void k_gemm128(
    const float* __restrict__ A, const int* __restrict__ map, int K,
    const float* __restrict__ W, const float* __restrict__ bias, float* __restrict__ C)
{
    __shared__ float As[2][8][132];
    __shared__ float Bs[2][8][132];
    int tid = threadIdx.x;
    int m0 = blockIdx.x * 128, n0 = blockIdx.y * 128;
    int tx = tid & 15, ty = tid >> 4;
    int lr = tid >> 1, lk = (tid & 1) * 4;
    int arow = m0 + lr;
    int row = map ? map[(arow & 127) * NT + (arow >> 7)] : arow;
    const float* ap = A + (long)row * K + lk;
    const float* wp = W + (long)(n0 + lr) * K + lk;
    ull acc2[8][4] = {};
    float4 av = *(const float4*)ap;
    float4 wv = *(const float4*)wp;
    int buf = 0;
    for (int k0 = 0; k0 < K; k0 += 8) {
        As[buf][lk+0][lr]=av.x; As[buf][lk+1][lr]=av.y; As[buf][lk+2][lr]=av.z; As[buf][lk+3][lr]=av.w;
        Bs[buf][lk+0][lr]=wv.x; Bs[buf][lk+1][lr]=wv.y; Bs[buf][lk+2][lr]=wv.z; Bs[buf][lk+3][lr]=wv.w;
        __syncthreads();
        if (k0 + 8 < K) { av = *(const float4*)(ap + k0 + 8); wv = *(const float4*)(wp + k0 + 8); }
        #pragma unroll
        for (int k = 0; k < 8; k++) {
            float4 a0 = *(const float4*)&As[buf][k][ty*4];
            float4 a1 = *(const float4*)&As[buf][k][64 + ty*4];
            ulonglong2 bA = *(const ulonglong2*)&Bs[buf][k][tx*4];
            ulonglong2 bB = *(const ulonglong2*)&Bs[buf][k][64 + tx*4];
            ull bp[4] = {bA.x, bA.y, bB.x, bB.y};
            float ar[8] = {a0.x,a0.y,a0.z,a0.w,a1.x,a1.y,a1.z,a1.w};
            #pragma unroll
            for (int i=0;i<8;i++) {
                ull ad = pack2(ar[i], ar[i]);
                #pragma unroll
                for (int jp=0;jp<4;jp++) ffma2(acc2[i][jp], ad, bp[jp]);
            }
        }
        buf ^= 1;
    }
    float4 bs0 = *(const float4*)(bias + n0 + tx*4);
    float4 bs1 = *(const float4*)(bias + n0 + 64 + tx*4);
    #pragma unroll
    for (int i=0;i<8;i++) {
        int m = m0 + ((i<4) ? (ty*4+i) : (64+ty*4+i-4));
        float2 u0 = unpack2(acc2[i][0]), u1 = unpack2(acc2[i][1]);
        float2 u2 = unpack2(acc2[i][2]), u3 = unpack2(acc2[i][3]);
        float4 o0, o1;
        o0.x=u0.x+bs0.x; o0.y=u0.y+bs0.y; o0.z=u1.x+bs0.z; o0.w=u1.y+bs0.w;
        o1.x=u2.x+bs1.x; o1.y=u2.y+bs1.y; o1.z=u3.x+bs1.z; o1.w=u3.y+bs1.w;
        *(float4*)(C + (long)m*G3 + n0 + tx*4)      = o0;
        *(float4*)(C + (long)m*G3 + n0 + 64 + tx*4) = o1;
    }
}

// ------------- persistent utterance GRU on tensor cores (bf16 hi/lo split) -------------
__global__ __launch_bounds__(128, 3) void k_ustep_mma(
    const float* __restrict__ Whh, const float* __restrict__ bhh,
    const int* __restrict__ tokens)
{
    __nv_bfloat16* Wm = (__nv_bfloat16*)usm;
    __nv_bfloat16* Am = (__nv_bfloat16*)((char*)usm + UW_BYTES);
    int tid = threadIdx.x, lane = tid & 31, w = tid >> 5;
    int m0 = blockIdx.x * 128, j0 = blockIdx.y * 16;

    for (int i = tid; i < 48*64; i += 128) {
        int r = i >> 6, q = i & 63;
        int g = r >> 4, jj = r & 15;
        float4 v = *(const float4*)(Whh + (long)(g*NH + j0 + jj)*NH + q*4);
        float e[4] = {v.x, v.y, v.z, v.w};
        __nv_bfloat16* ph = Wm + r*UWP + q*4;
        __nv_bfloat16* pl = Wm + (r+48)*UWP + q*4;
        #pragma unroll
        for (int k = 0; k < 4; k++) {
            __nv_bfloat16 h = __float2bfloat16(e[k]);
            ph[k] = h;
            pl[k] = __float2bfloat16(e[k] - __bfloat162float(h));
        }
    }
    float bh[3][2][2];
    #pragma unroll
    for (int g=0; g<3; g++)
        #pragma unroll
        for (int jt2=0; jt2<2; jt2++)
            #pragma unroll
            for (int ci=0; ci<2; ci++)
                bh[g][jt2][ci] = bhh[g*NH + j0 + jt2*8 + (lane&3)*2 + ci];
    __syncthreads();

    unsigned wsm = (unsigned)__cvta_generic_to_shared(Wm);
    unsigned asmb = (unsigned)__cvta_generic_to_shared(Am);
    unsigned baddr[6][2];
    #pragma unroll
    for (int nt=0; nt<6; nt++)
        #pragma unroll
        for (int pl=0; pl<2; pl++) {
            int wr = pl*48 + nt*8 + (lane & 7);
            baddr[nt][pl] = wsm + (unsigned)(wr*UWP*2 + ((lane>>3)&1)*16);
        }
    unsigned aaddr[2][2];
    #pragma unroll
    for (int mt=0; mt<2; mt++) {
        int ar = w*32 + mt*16 + (lane & 7) + ((lane>>3)&1)*8;
        #pragma unroll
        for (int pl=0; pl<2; pl++)
            aaddr[mt][pl] = asmb + (unsigned)(pl*UA_PLANE + ar*48 + (lane>>4)*16);
    }

    for (int t = 0; t < NT; t++) {
        const float* Hin  = (t & 1) ? g_Hu1 : g_Hu0;
        float*       Hout = (t & 1) ? g_Hu0 : g_Hu1;
        const __nv_bfloat16* Rbf = (t & 1) ? g_HbfB : g_HbfA;
        __nv_bfloat16*       Wbf = (t & 1) ? g_HbfA : g_HbfB;

        float acc[2][6][4] = {};
        uint2 ph[4], plo[4];
        #pragma unroll
        for (int q=0; q<4; q++) {
            int idx = q*128 + tid, row = idx >> 2, kq = (idx & 3)*4;
            ph[q]  = *(const uint2*)(Rbf +      (long)(m0+row)*NH + kq);
            plo[q] = *(const uint2*)(Rbf + PL + (long)(m0+row)*NH + kq);
        }
        int buf = 0;
        for (int c = 0; c < 16; c++) {
            __nv_bfloat16* Ahi = Am + buf*6144;
            __nv_bfloat16* Alo = Ahi + 3072;
            #pragma unroll
            for (int q=0; q<4; q++) {
                int idx = q*128 + tid, row = idx >> 2, kq = (idx & 3)*4;
                *(uint2*)(Ahi + row*24 + kq) = ph[q];
                *(uint2*)(Alo + row*24 + kq) = plo[q];
            }
            __syncthreads();
            if (c < 15) {
                #pragma unroll
                for (int q=0; q<4; q++) {
                    int idx = q*128 + tid, row = idx >> 2, kq = (idx & 3)*4;
                    ph[q]  = *(const uint2*)(Rbf +      (long)(m0+row)*NH + (c+1)*16 + kq);
                    plo[q] = *(const uint2*)(Rbf + PL + (long)(m0+row)*NH + (c+1)*16 + kq);
                }
            }
            unsigned bfr[6][2][2];
            #pragma unroll
            for (int nt=0; nt<6; nt++)
                #pragma unroll
                for (int pl=0; pl<2; pl++)
                    ldsm2(bfr[nt][pl], baddr[nt][pl] + c*32);
            unsigned afr[2][2][4];
            #pragma unroll
            for (int mt=0; mt<2; mt++)
                #pragma unroll
                for (int pl=0; pl<2; pl++)
                    ldsm4(afr[mt][pl], aaddr[mt][pl] + buf*12288);
            #pragma unroll
            for (int mt=0; mt<2; mt++)
                #pragma unroll
                for (int nt=0; nt<6; nt++) {
                    mma16816(acc[mt][nt], afr[mt][0], bfr[nt][0]);
                    mma16816(acc[mt][nt], afr[mt][1], bfr[nt][0]);
                    mma16816(acc[mt][nt], afr[mt][0], bfr[nt][1]);
                }
            buf ^= 1;
        }
        #pragma unroll
        for (int mt=0; mt<2; mt++)
            #pragma unroll
            for (int rh=0; rh<2; rh++) {
                int m = m0 + w*32 + mt*16 + (lane>>2) + rh*8;
                int tok = tokens[m*NT + t];
                const float* gi = g_TG + (long)tok * G3;
                int fi = rh*2;
                #pragma unroll
                for (int jt2=0; jt2<2; jt2++) {
                    int jb2 = j0 + jt2*8 + (lane&3)*2;
                    float2 gr2 = *(const float2*)(gi + jb2);
                    float2 gz2 = *(const float2*)(gi + NH + jb2);
                    float2 gn2 = *(const float2*)(gi + 2*NH + jb2);
                    float2 ho  = *(const float2*)(Hin + (long)m*NH + jb2);
                    float r0 = 1.f/(1.f+expf(-(gr2.x + acc[mt][jt2][fi]   + bh[0][jt2][0])));
                    float z0 = 1.f/(1.f+expf(-(gz2.x + acc[mt][2+jt2][fi] + bh[1][jt2][0])));
                    float n0 = tanhf(gn2.x + r0*(acc[mt][4+jt2][fi] + bh[2][jt2][0]));
                    float h0 = (1.f - z0)*n0 + z0*ho.x;
                    float r1 = 1.f/(1.f+expf(-(gr2.y + acc[mt][jt2][fi+1]   + bh[0][jt2][1])));
                    float z1 = 1.f/(1.f+expf(-(gz2.y + acc[mt][2+jt2][fi+1] + bh[1][jt2][1])));
                    float n1 = tanhf(gn2.y + r1*(acc[mt][4+jt2][fi+1] + bh[2][jt2][1]));
                    float h1 = (1.f - z1)*n1 + z1*ho.y;
                    float2 hv; hv.x = h0; hv.y = h1;
                    *(float2*)(Hout + (long)m*NH + jb2) = hv;
                    __nv_bfloat16 b0 = __float2bfloat16(h0);
                    __nv_bfloat16 b1 = __float2bfloat16(h1);
                    __nv_bfloat162 hp; hp.x = b0; hp.y = b1;
                    *(__nv_bfloat162*)(Wbf + (long)m*NH + jb2) = hp;
                    __nv_bfloat162 lp;
                    lp.x = __float2bfloat16(h0 - __bfloat162float(b0));
                    lp.y = __float2bfloat16(h1 - __bfloat162float(b1));
                    *(__nv_bfloat162*)(Wbf + PL + (long)m*NH + jb2) = lp;
                }
            }
        if (t < NT-1) {
            __threadfence();
            __syncthreads();
            if (tid == 0) {
                unsigned target = (unsigned)UTILES * (t + 1);
                atomicAdd(&g_ubar, 1u);
                while (*(volatile unsigned*)&g_ubar < target) __nanosleep(64);
                __threadfence();
            }
            __syncthreads();
        }
    }
}

// ------------- fused tail: ctx + SGI-gemm + spk + resp (f32x2 over k) -------------
extern __shared__ float tsm[];
__global__ __launch_bounds__(256) void k_tail(
    const float* __restrict__ cWhh, const float* __restrict__ cbhh,
    const float* __restrict__ sWih, const float* __restrict__ sbih,
    const float* __restrict__ sWhh, const float* __restrict__ sbhh,
    const float* __restrict__ rWhh, const float* __restrict__ rbhh,
    const int* __restrict__ spk, float* __restrict__ out)
{
    float* Wsm = tsm;
    float* Asm = tsm + 48*260;
    int* flags = (int*)(tsm + 48*260 + 32*260);
    int tid = threadIdx.x, bid = blockIdx.x;
    int role = (bid < 32) ? 0 : (bid < 64) ? 1 : (bid < 96) ? 2 : 3;
    int rel  = bid - ((role == 0) ? 0 : (role == 1) ? 32 : (role == 2) ? 64 : 96);
    int jt = rel & 15, rt = rel >> 4;
    int j0 = jt*16, m0 = rt*32;
    int tx = tid & 15, ty = tid >> 4;
    int j = j0 + tx;
    const float* W    = (role==0) ? cWhh : (role==1) ? sWih : (role==2) ? sWhh : rWhh;
    const float* bias = (role==0) ? cbhh : (role==1) ? sbih : (role==2) ? sbhh : rbhh;

    for (int i = tid; i < 48*64; i += 256) {
        int r = i >> 6, q = i & 63;
        int g = r >> 4, jj = r & 15;
        *(float4*)&Wsm[r*260 + q*4] = *(const float4*)(W + (long)(g*NH + j0 + jj)*NH + q*4);
    }
    float b0 = bias[j], b1 = bias[NH + j], b2 = bias[2*NH + j];
    if (role == 2) for (int i = tid; i < 32*51; i += 256) flags[i] = 0;
    __syncthreads();

    for (int it = 0; it < NS + 2; ++it) {
        int t = (role == 1) ? it - 1 : (role == 2) ? it - 2 : it;
        bool active = (t >= 0) && (t < NS);
        if (active) {
            if (role == 2) {
                for (int i = tid; i < 32*64; i += 256) {
                    int r = i >> 6, q = i & 63;
                    int b = m0 + r, a = spk[b*NS + t];
                    *(float4*)&Asm[r*260 + q*4] = *(const float4*)(g_Htab + ((long)b*NA + a)*NH + q*4);
                }
                if (tid < 32) flags[tid*51 + spk[(m0+tid)*NS + t]] = 1;
            } else if (role == 1) {
                for (int i = tid; i < 32*64; i += 256) {
                    int r = i >> 6, q = i & 63;
                    *(float4*)&Asm[r*260 + q*4] =
                        *(const float4*)(out + O_CTXOUT + ((long)t*64 + m0 + r)*NH + q*4);
                }
            } else if (t == 0) {
                for (int i = tid; i < 32*64; i += 256) {
                    int r = i >> 6, q = i & 63;
                    *(float4*)&Asm[r*260 + q*4] = make_float4(0.f,0.f,0.f,0.f);
                }
            } else {
                for (int i = tid; i < 32*64; i += 256) {
                    int r = i >> 6, q = i & 63;
                    int m = m0 + r;
                    const float* src = (role == 0)
                        ? out + O_CTXOUT  + ((long)(t-1)*64 + m)*NH
                        : out + O_RESPOUT + (((long)(m&1)*NT + (t-1))*64 + (m>>1))*NH;
                    *(float4*)&Asm[r*260 + q*4] = *(const float4*)(src + q*4);
                }
            }
            __syncthreads();

            ull acc2[3][2] = {};
            #pragma unroll 4
            for (int k0 = 0; k0 < NH; k0 += 4) {
                ulonglong2 w0 = *(const ulonglong2*)&Wsm[tx*260 + k0];
                ulonglong2 w1 = *(const ulonglong2*)&Wsm[(16+tx)*260 + k0];
                ulonglong2 w2 = *(const ulonglong2*)&Wsm[(32+tx)*260 + k0];
                #pragma unroll
                for (int r = 0; r < 2; r++) {
                    ulonglong2 a = *(const ulonglong2*)&Asm[(ty*2+r)*260 + k0];
                    ffma2(acc2[0][r], a.x, w0.x); ffma2(acc2[0][r], a.y, w0.y);
                    ffma2(acc2[1][r], a.x, w1.x); ffma2(acc2[1][r], a.y, w1.y);
                    ffma2(acc2[2][r], a.x, w2.x); ffma2(acc2[2][r], a.y, w2.y);
                }
            }
            float acc[3][2];
            #pragma unroll
            for (int g=0; g<3; g++)
                #pragma unroll
                for (int r=0; r<2; r++) { float2 u = unpack2(acc2[g][r]); acc[g][r] = u.x + u.y; }

            if (role == 1) {
                #pragma unroll
                for (int r = 0; r < 2; r++) {
                    int m = m0 + ty*2 + r;
                    float* o = g_SGI + ((long)t*64 + m)*G3;
                    o[j] = acc[0][r] + b0; o[NH+j] = acc[1][r] + b1; o[2*NH+j] = acc[2][r] + b2;
                }
            } else {
                #pragma unroll
                for (int r = 0; r < 2; r++) {
                    int lr = ty*2 + r, m = m0 + lr;
                    const float* gi = (role == 0) ? g_CGI + ((long)t*64 + m)*G3
                                    : (role == 2) ? g_SGI + ((long)t*64 + m)*G3
                                    :               g_RGI + ((long)t*128 + m)*G3;
                    float rr = 1.f/(1.f+expf(-(gi[j]      + acc[0][r] + b0)));
                    float zz = 1.f/(1.f+expf(-(gi[NH+j]   + acc[1][r] + b1)));
                    float nn = tanhf(gi[2*NH+j] + rr*(acc[2][r] + b2));
                    float hp = Asm[lr*260 + j];
                    float hn = (1.f - zz)*nn + zz*hp;
                    if (role == 0) {
                        out[O_CTXOUT + ((long)t*64 + m)*NH + j] = hn;
                        if (t == NS-1) out[O_CTXHID + (long)m*NH + j] = hn;
                    } else if (role == 3) {
                        out[O_RESPOUT + (((long)(m&1)*NT + t)*64 + (m>>1))*NH + j] = hn;
                        if (t == NS-1) out[O_RESPHID + ((long)(m&1)*64 + (m>>1))*NH + j] = hn;
                    } else {
                        int a = spk[m*NS + t];
                        g_Htab[((long)m*NA + a)*NH + j] = hn;
                    }
                }
            }
        }
        if (it < NS + 1) {
            __threadfence();
            __syncthreads();
            if (tid == 0) {
                atomicAdd(&g_tbar, 1u);
                unsigned target = (unsigned)TBLOCKS * (it + 1);
                while (*(volatile unsigned*)&g_tbar < target) __nanosleep(64);
                __threadfence();
            }
            __syncthreads();
        } else {
            __syncthreads();
        }
    }

    if (role == 2) {
        for (int a = 0; a < NA; a++) {
            #pragma unroll
            for (int r = 0; r < 2; r++) {
                int lb = ty*2 + r, b = m0 + lb;
                float v = flags[lb*51 + a] ? g_Htab[((long)b*NA + a)*NH + j] : 0.f;
                out[O_SPKEMB + ((long)b*NA + a)*NH + j] = v;
            }
        }
        if (jt == 0) {
            for (int i = tid; i < 32*NA; i += 256) {
                int r = i / NA, a = i % NA;
                out[O_SPKMASK + (m0+r)*NA + a] = (flags[r*51 + a] && a > 0) ? 1.f : 0.f;
            }
        }
    }
}

// ------------- ctx GRU input: concat(utter_hidden, agent_emb) -------------
__global__ void k_cin(const int* __restrict__ spk) {
    int idx = blockIdx.x * 256 + threadIdx.x;
    int c = idx & 511, mr = idx >> 9;
    int s = mr >> 6, b = mr & 63;
    float v;
    if (c < NH) v = g_Hu0[(b*NS + s)*NH + c];
    else        v = g_tables[(b*NA + spk[b*NS + s])*NH + (c - NH)];
    g_CIN[idx] = v;
}

// ------------- launch -------------
extern "C" void kernel_launch(void* const* d_in, const int* in_sizes, int n_in,
                              void* d_out, int out_size) {
    (void)in_sizes; (void)n_in; (void)out_size;
    const int*   context = (const int*)d_in[0];
    const int*   response= (const int*)d_in[1];
    const int*   spk     = (const int*)d_in[2];
    const float* emb_u   = (const float*)d_in[3];
    const float* emb_r   = (const float*)d_in[4];
    const float* uWih=(const float*)d_in[5],  *uWhh=(const float*)d_in[6];
    const float* ubih=(const float*)d_in[7],  *ubhh=(const float*)d_in[8];
    const float* cWih=(const float*)d_in[9],  *cWhh=(const float*)d_in[10];
    const float* cbih=(const float*)d_in[11], *cbhh=(const float*)d_in[12];
    const float* rWih=(const float*)d_in[13], *rWhh=(const float*)d_in[14];
    const float* rbih=(const float*)d_in[15], *rbhh=(const float*)d_in[16];
    const float* sWih=(const float*)d_in[17], *sWhh=(const float*)d_in[18];
    const float* sbih=(const float*)d_in[19], *sbhh=(const float*)d_in[20];
    float* out = (float*)d_out;

    void *pTab, *pTG, *pHu0, *pCIN, *pCGI, *pRGI, *pBar, *pTbar, *pHtab, *pBfA, *pEbf, *pWubf;
    cudaGetSymbolAddress(&pTab, g_tables);
    cudaGetSymbolAddress(&pTG,  g_TG);
    cudaGetSymbolAddress(&pHu0, g_Hu0);
    cudaGetSymbolAddress(&pCIN, g_CIN);
    cudaGetSymbolAddress(&pCGI, g_CGI);
    cudaGetSymbolAddress(&pRGI, g_RGI);
    cudaGetSymbolAddress(&pBar, g_ubar);
    cudaGetSymbolAddress(&pTbar, g_tbar);
    cudaGetSymbolAddress(&pHtab, g_Htab);
    cudaGetSymbolAddress(&pBfA, g_HbfA);
    cudaGetSymbolAddress(&pEbf, g_Ebf);
    cudaGetSymbolAddress(&pWubf, g_Wubf);

    cudaFuncSetAttribute(k_ustep_mma, cudaFuncAttributeMaxDynamicSharedMemorySize, USMEM2);
    cudaFuncSetAttribute(k_gemmtc,    cudaFuncAttributeMaxDynamicSharedMemorySize, GCSMEM);
    cudaFuncSetAttribute(k_tail,      cudaFuncAttributeMaxDynamicSharedMemorySize, TSMEM);

    cudaMemcpyAsync(pTab, h_tables, sizeof(h_tables), cudaMemcpyHostToDevice, 0);
    cudaMemsetAsync(pHu0, 0, (size_t)NB*NS*NH*sizeof(float), 0);
    cudaMemsetAsync(pBfA, 0, (size_t)2*PL*sizeof(__nv_bfloat16), 0);
    cudaMemsetAsync(pBar, 0, sizeof(unsigned), 0);
    cudaMemsetAsync(pTbar, 0, sizeof(unsigned), 0);
    cudaMemsetAsync(pHtab, 0, (size_t)NB*NA*NH*sizeof(float), 0);

    // fork: RGI gemm (independent) on s2
    cudaEventRecord(g_evFork, 0);
    cudaStreamWaitEvent(g_s2, g_evFork, 0);
    k_gemm128<<<dim3(50, 6), 256, 0, g_s2>>>(emb_r, response, NH, rWih, rbih, (float*)pRGI);
    cudaEventRecord(g_evJoin, g_s2);

    // TG = emb_u @ uWih^T + ubih on tensor cores (bf16 hi/lo)
    __nv_bfloat16* Ebf  = (__nv_bfloat16*)pEbf;
    __nv_bfloat16* Wubf = (__nv_bfloat16*)pWubf;
    k_cvt<<<(NV*NH/4 + 255)/256, 256>>>(emb_u, Ebf, Ebf + (long)NV*NH, NV*NH/4);
    k_cvt<<<(G3*NH/4 + 255)/256, 256>>>(uWih, Wubf, Wubf + G3*NH, G3*NH/4);
    k_gemmtc<<<dim3(12, NV/128), 128, GCSMEM>>>(Ebf, (long)NV*NH, Wubf, (long)G3*NH, ubih, (float*)pTG);

    // persistent tensor-core utterance recurrence
    k_ustep_mma<<<dim3(25, 16), 128, USMEM2>>>(uWhh, ubhh, context);

    // ctx input + CGI gemm
    k_cin<<<6400, 256>>>(spk);
    k_gemm128<<<dim3(25, 6), 256>>>((const float*)pCIN, nullptr, 2*NH, cWih, cbih, (float*)pCGI);

    // fused tail (needs RGI)
    cudaStreamWaitEvent(0, g_evJoin, 0);
    k_tail<<<TBLOCKS, 256, TSMEM>>>(cWhh, cbhh, sWih, sbih, sWhh, sbhh, rWhh, rbhh, spk, out);
}

// round 16
// speedup vs baseline: 2.8806x; 1.0631x over previous
#include <cuda_runtime.h>
#include <cuda_bf16.h>
#include <math.h>

#define NB 64
#define NS 50
#define NT 50
#define NR 2
#define NV 32000
#define NH 256
#define G3 768
#define NA 51

// output offsets (floats)
#define O_CTXOUT  0
#define O_CTXHID  819200
#define O_RESPOUT 835584
#define O_RESPHID 2473984
#define O_SPKEMB  2506752
#define O_SPKMASK 3342336

// persistent ustep (tensor-core version)
#define UTILES 400
#define UWP 264
#define UW_BYTES (96*UWP*2)
#define UA_PLANE 6144
#define USMEM2 (UW_BYTES + 4*UA_PLANE)
#define PL (NB*NS*NH)

// fused tail kernel: 144 blocks (ctx 32 | sgi 32 | spk 32 | resp 48)
#define TBLOCKS 144
#define TSMEM ((96*260)*4 + 32*51*4)

// tensor-core GEMM tiling (k-chunk = 32)
#define GC_APITCH 40
#define GC_APLANE (128*GC_APITCH)
#define GC_ABUF (2*GC_APLANE)
#define GC_BPLANE (64*GC_APITCH)
#define GC_BBUF (2*GC_BPLANE)
#define GCSMEM ((2*GC_ABUF + 2*GC_BBUF)*2)   // 61440 bytes

typedef unsigned long long ull;

// ------------- f32x2 helpers -------------
__device__ __forceinline__ void ffma2(ull& d, ull a, ull b) {
    asm("fma.rn.f32x2 %0, %1, %2, %0;" : "+l"(d) : "l"(a), "l"(b));
}
__device__ __forceinline__ ull pack2(float x, float y) {
    ull r; asm("mov.b64 %0, {%1, %2};" : "=l"(r) : "f"(x), "f"(y)); return r;
}
__device__ __forceinline__ float2 unpack2(ull v) {
    float2 r; asm("mov.b64 {%0, %1}, %2;" : "=f"(r.x), "=f"(r.y) : "l"(v)); return r;
}

// ------------- tensor-core helpers -------------
__device__ __forceinline__ void ldsm4(unsigned* r, unsigned a) {
    asm volatile("ldmatrix.sync.aligned.m8n8.x4.shared.b16 {%0,%1,%2,%3}, [%4];"
        : "=r"(r[0]), "=r"(r[1]), "=r"(r[2]), "=r"(r[3]) : "r"(a));
}
__device__ __forceinline__ void ldsm2(unsigned* r, unsigned a) {
    asm volatile("ldmatrix.sync.aligned.m8n8.x2.shared.b16 {%0,%1}, [%2];"
        : "=r"(r[0]), "=r"(r[1]) : "r"(a));
}
__device__ __forceinline__ void mma16816(float* c, const unsigned* a, const unsigned* b) {
    asm volatile("mma.sync.aligned.m16n8k16.row.col.f32.bf16.bf16.f32 "
        "{%0,%1,%2,%3}, {%4,%5,%6,%7}, {%8,%9}, {%0,%1,%2,%3};"
        : "+f"(c[0]), "+f"(c[1]), "+f"(c[2]), "+f"(c[3])
        : "r"(a[0]), "r"(a[1]), "r"(a[2]), "r"(a[3]), "r"(b[0]), "r"(b[1]));
}
__device__ __forceinline__ void cpa16(unsigned sm, const void* gm) {
    asm volatile("cp.async.ca.shared.global [%0], [%1], 16;" :: "r"(sm), "l"(gm));
}
__device__ __forceinline__ void cpa_commit() { asm volatile("cp.async.commit_group;"); }
template<int N> __device__ __forceinline__ void cpa_wait() {
    asm volatile("cp.async.wait_group %0;" :: "n"(N));
}

// ------------- device scratch -------------
__device__ float g_tables[NB*NA*NH];
__device__ float g_TG[NV*G3];
__device__ float g_Hu0[NB*NS*NH];
__device__ float g_Hu1[NB*NS*NH];
__device__ __nv_bfloat16 g_HbfA[2*PL];
__device__ __nv_bfloat16 g_HbfB[2*PL];
__device__ __nv_bfloat16 g_Ebf[2*NV*NH];        // emb_utter hi/lo
__device__ __nv_bfloat16 g_Wubf[2*G3*NH];       // utter_Wih hi/lo
__device__ __nv_bfloat16 g_Wcbf[2*G3*2*NH];     // ctx_Wih hi/lo (K=512)
__device__ __nv_bfloat16 g_CINbf[2*NS*NB*2*NH]; // CIN hi/lo (K=512)
__device__ float g_CIN[NS*NB*2*NH];
__device__ float g_CGI[NS*NB*G3];
__device__ float g_SGI[NS*NB*G3];
__device__ float g_RGI[NT*NB*NR*G3];
__device__ float g_Htab[NB*NA*NH];
__device__ unsigned g_ubar;
__device__ unsigned g_tbar;

// ------------- host: exact numpy legacy MT19937 agent tables -------------
static float h_tables[NB*NA*NH];
static cudaStream_t g_s2;
static cudaEvent_t g_evFork, g_evJoin;
namespace {
struct MT {
    unsigned mt[624]; int mti;
    void seed(unsigned s){ mt[0]=s; for(int i=1;i<624;i++) mt[i]=1812433253u*(mt[i-1]^(mt[i-1]>>30))+(unsigned)i; mti=624; }
    unsigned next(){
        if(mti>=624){ for(int i=0;i<624;i++){ unsigned y=(mt[i]&0x80000000u)|(mt[(i+1)%624]&0x7fffffffu);
            mt[i]=mt[(i+397)%624]^(y>>1)^((y&1u)?0x9908b0dfu:0u);} mti=0; }
        unsigned y=mt[mti++]; y^=y>>11; y^=(y<<7)&0x9d2c5680u; y^=(y<<15)&0xefc60000u; y^=y>>18; return y;
    }
};
struct TabInit {
    TabInit(){
        MT m; m.seed(1u);
        for(long i=0;i<(long)NB*NA*NH;i++){
            unsigned a=m.next()>>5, b=m.next()>>6;
            h_tables[i]=(float)(((double)a*67108864.0+(double)b)*(1.0/9007199254740992.0));
        }
        cudaStreamCreateWithFlags(&g_s2, cudaStreamNonBlocking);
        cudaEventCreateWithFlags(&g_evFork, cudaEventDisableTiming);
        cudaEventCreateWithFlags(&g_evJoin, cudaEventDisableTiming);
    }
} g_tabinit;
}

// ------------- fp32 -> bf16 hi/lo conversion -------------
__global__ void k_cvt(const float* __restrict__ src, __nv_bfloat16* __restrict__ hi,
                      __nv_bfloat16* __restrict__ lo, int n4)
{
    int i = blockIdx.x * 256 + threadIdx.x;
    if (i >= n4) return;
    float4 v = ((const float4*)src)[i];
    float e[4] = {v.x, v.y, v.z, v.w};
    __nv_bfloat16 h[4], l[4];
    #pragma unroll
    for (int k = 0; k < 4; k++) {
        h[k] = __float2bfloat16(e[k]);
        l[k] = __float2bfloat16(e[k] - __bfloat162float(h[k]));
    }
    __nv_bfloat162 h0; h0.x = h[0]; h0.y = h[1];
    __nv_bfloat162 h1; h1.x = h[2]; h1.y = h[3];
    __nv_bfloat162 l0; l0.x = l[0]; l0.y = l[1];
    __nv_bfloat162 l1; l1.x = l[2]; l1.y = l[3];
    ((__nv_bfloat162*)hi)[2*i]   = h0;
    ((__nv_bfloat162*)hi)[2*i+1] = h1;
    ((__nv_bfloat162*)lo)[2*i]   = l0;
    ((__nv_bfloat162*)lo)[2*i+1] = l1;
}

// ------------- tensor-core GEMM: C[M][768] = Abf @ Wbf^T + bias (bf16 hi/lo, runtime K) -------------
// grid (12, M/128): x = n-tile(64), y = m-tile(128). block 128. KD multiple of 32.
extern __shared__ float usm[];
__global__ __launch_bounds__(128) void k_gemmtc(
    const __nv_bfloat16* __restrict__ Abf, long sA,
    const __nv_bfloat16* __restrict__ Wbf, long sW,
    const float* __restrict__ bias, float* __restrict__ C, int KD)
{
    __nv_bfloat16* gsm = (__nv_bfloat16*)usm;
    int tid = threadIdx.x, lane = tid & 31, w = tid >> 5;
    int n0 = blockIdx.x * 64, m0 = blockIdx.y * 128;
    unsigned asmb = (unsigned)__cvta_generic_to_shared(gsm);

    unsigned aBase[2][2], bBase[8][2];
    #pragma unroll
    for (int mt=0; mt<2; mt++)
        #pragma unroll
        for (int pl=0; pl<2; pl++) {
            int row = w*32 + mt*16 + (lane&7) + ((lane>>3)&1)*8;
            aBase[mt][pl] = asmb + (unsigned)((pl*GC_APLANE + row*GC_APITCH)*2) + (lane>>4)*16;
        }
    #pragma unroll
    for (int nt=0; nt<8; nt++)
        #pragma unroll
        for (int pl=0; pl<2; pl++) {
            int row = nt*8 + (lane&7);
            bBase[nt][pl] = asmb + (unsigned)((2*GC_ABUF + pl*GC_BPLANE + row*GC_APITCH)*2)
                          + ((lane>>3)&1)*16;
        }

    auto issue = [&](int c, int b) {
        #pragma unroll
        for (int p2=0; p2<4; p2++) {
            int idx = p2*128 + tid, row = idx >> 2, kq = (idx & 3)*8;
            #pragma unroll
            for (int pl=0; pl<2; pl++)
                cpa16(asmb + (unsigned)((b*GC_ABUF + pl*GC_APLANE + row*GC_APITCH + kq)*2),
                      (const void*)(Abf + pl*sA + (long)(m0+row)*KD + c*32 + kq));
        }
        #pragma unroll
        for (int p2=0; p2<2; p2++) {
            int idx = p2*128 + tid, row = idx >> 2, kq = (idx & 3)*8;
            #pragma unroll
            for (int pl=0; pl<2; pl++)
                cpa16(asmb + (unsigned)((2*GC_ABUF + b*GC_BBUF + pl*GC_BPLANE + row*GC_APITCH + kq)*2),
                      (const void*)(Wbf + pl*sW + (long)(n0+row)*KD + c*32 + kq));
        }
        cpa_commit();
    };

    float acc[2][8][4] = {};
    int NC = KD >> 5;
    issue(0, 0);
    for (int c = 0; c < NC; c++) {
        int b = c & 1;
        if (c < NC-1) { issue(c+1, b^1); cpa_wait<1>(); }
        else { cpa_wait<0>(); }
        __syncthreads();
        #pragma unroll
        for (int h = 0; h < 2; h++) {
            unsigned afr[2][2][4];
            #pragma unroll
            for (int mt=0; mt<2; mt++)
                #pragma unroll
                for (int pl=0; pl<2; pl++)
                    ldsm4(afr[mt][pl], aBase[mt][pl] + b*GC_ABUF*2 + h*32);
            unsigned bfr[8][2][2];
            #pragma unroll
            for (int nt=0; nt<8; nt++)
                #pragma unroll
                for (int pl=0; pl<2; pl++)
                    ldsm2(bfr[nt][pl], bBase[nt][pl] + b*GC_BBUF*2 + h*32);
            #pragma unroll
            for (int mt=0; mt<2; mt++)
                #pragma unroll
                for (int nt=0; nt<8; nt++) {
                    mma16816(acc[mt][nt], afr[mt][0], bfr[nt][0]);
                    mma16816(acc[mt][nt], afr[mt][1], bfr[nt][0]);
                    mma16816(acc[mt][nt], afr[mt][0], bfr[nt][1]);
                }
        }
        __syncthreads();
    }
    #pragma unroll
    for (int mt=0; mt<2; mt++) {
        int row = m0 + w*32 + mt*16 + (lane>>2);
        #pragma unroll
        for (int nt=0; nt<8; nt++) {
            int col = n0 + nt*8 + (lane&3)*2;
            float2 bb = *(const float2*)(bias + col);
            float2 s0, s1;
            s0.x = acc[mt][nt][0] + bb.x; s0.y = acc[mt][nt][1] + bb.y;
            s1.x = acc[mt][nt][2] + bb.x; s1.y = acc[mt][nt][3] + bb.y;
            *(float2*)(C + (long)row*G3 + col)     = s0;
            *(float2*)(C + (long)(row+8)*G3 + col) = s1;
        }
    }
}

// ------------- 128x128x8 double-buffered SGEMM (f32x2) — RGI only -------------
__global__ __launch_bounds__(256) void k_gemm128(
    const float* __restrict__ A, const int* __restrict__ map, int K,
    const float* __restrict__ W, const float* __restrict__ bias, float* __restrict__ C)
{
    __shared__ float As[2][8][132];
    __shared__ float Bs[2][8][132];
    int tid = threadIdx.x;
    int m0 = blockIdx.x * 128, n0 = blockIdx.y * 128;
    int tx = tid & 15, ty = tid >> 4;
    int lr = tid >> 1, lk = (tid & 1) * 4;
    int arow = m0 + lr;
    int row = map ? map[(arow & 127) * NT + (arow >> 7)] : arow;
    const float* ap = A + (long)row * K + lk;
    const float* wp = W + (long)(n0 + lr) * K + lk;
    ull acc2[8][4] = {};
    float4 av = *(const float4*)ap;
    float4 wv = *(const float4*)wp;
    int buf = 0;
    for (int k0 = 0; k0 < K; k0 += 8) {
        As[buf][lk+0][lr]=av.x; As[buf][lk+1][lr]=av.y; As[buf][lk+2][lr]=av.z; As[buf][lk+3][lr]=av.w;
        Bs[buf][lk+0][lr]=wv.x; Bs[buf][lk+1][lr]=wv.y; Bs[buf][lk+2][lr]=wv.z; Bs[buf][lk+3][lr]=wv.w;
        __syncthreads();
        if (k0 + 8 < K) { av = *(const float4*)(ap + k0 + 8); wv = *(const float4*)(wp + k0 + 8); }
        #pragma unroll
        for (int k = 0; k < 8; k++) {
            float4 a0 = *(const float4*)&As[buf][k][ty*4];
            float4 a1 = *(const float4*)&As[buf][k][64 + ty*4];
            ulonglong2 bA = *(const ulonglong2*)&Bs[buf][k][tx*4];
            ulonglong2 bB = *(const ulonglong2*)&Bs[buf][k][64 + tx*4];
            ull bp[4] = {bA.x, bA.y, bB.x, bB.y};
            float ar[8] = {a0.x,a0.y,a0.z,a0.w,a1.x,a1.y,a1.z,a1.w};
            #pragma unroll
            for (int i=0;i<8;i++) {
                ull ad = pack2(ar[i], ar[i]);
                #pragma unroll
                for (int jp=0;jp<4;jp++) ffma2(acc2[i][jp], ad, bp[jp]);
            }
        }
        buf ^= 1;
    }
    float4 bs0 = *(const float4*)(bias + n0 + tx*4);
    float4 bs1 = *(const float4*)(bias + n0 + 64 + tx*4);
    #pragma unroll
    for (int i=0;i<8;i++) {
        int m = m0 + ((i<4) ? (ty*4+i) : (64+ty*4+i-4));
        float2 u0 = unpack2(acc2[i][0]), u1 = unpack2(acc2[i][1]);
        float2 u2 = unpack2(acc2[i][2]), u3 = unpack2(acc2[i][3]);
        float4 o0, o1;
        o0.x=u0.x+bs0.x; o0.y=u0.y+bs0.y; o0.z=u1.x+bs0.z; o0.w=u1.y+bs0.w;
        o1.x=u2.x+bs1.x; o1.y=u2.y+bs1.y; o1.z=u3.x+bs1.z; o1.w=u3.y+bs1.w;
        *(float4*)(C + (long)m*G3 + n0 + tx*4)      = o0;
        *(float4*)(C + (long)m*G3 + n0 + 64 + tx*4) = o1;
    }
}

// ------------- persistent utterance GRU on tensor cores (bf16 hi/lo split) -------------
__global__ __launch_bounds__(128, 3) void k_ustep_mma(
    const float* __restrict__ Whh, const float* __restrict__ bhh,
    const int* __restrict__ tokens)
{
    __nv_bfloat16* Wm = (__nv_bfloat16*)usm;
    __nv_bfloat16* Am = (__nv_bfloat16*)((char*)usm + UW_BYTES);
    int tid = threadIdx.x, lane = tid & 31, w = tid >> 5;
    int m0 = blockIdx.x * 128, j0 = blockIdx.y * 16;

    for (int i = tid; i < 48*64; i += 128) {
        int r = i >> 6, q = i & 63;
        int g = r >> 4, jj = r & 15;
        float4 v = *(const float4*)(Whh + (long)(g*NH + j0 + jj)*NH + q*4);
        float e[4] = {v.x, v.y, v.z, v.w};
        __nv_bfloat16* ph = Wm + r*UWP + q*4;
        __nv_bfloat16* pl = Wm + (r+48)*UWP + q*4;
        #pragma unroll
        for (int k = 0; k < 4; k++) {
            __nv_bfloat16 h = __float2bfloat16(e[k]);
            ph[k] = h;
            pl[k] = __float2bfloat16(e[k] - __bfloat162float(h));
        }
    }
    float bh[3][2][2];
    #pragma unroll
    for (int g=0; g<3; g++)
        #pragma unroll
        for (int jt2=0; jt2<2; jt2++)
            #pragma unroll
            for (int ci=0; ci<2; ci++)
                bh[g][jt2][ci] = bhh[g*NH + j0 + jt2*8 + (lane&3)*2 + ci];
    __syncthreads();

    unsigned wsm = (unsigned)__cvta_generic_to_shared(Wm);
    unsigned asmb = (unsigned)__cvta_generic_to_shared(Am);
    unsigned baddr[6][2];
    #pragma unroll
    for (int nt=0; nt<6; nt++)
        #pragma unroll
        for (int pl=0; pl<2; pl++) {
            int wr = pl*48 + nt*8 + (lane & 7);
            baddr[nt][pl] = wsm + (unsigned)(wr*UWP*2 + ((lane>>3)&1)*16);
        }
    unsigned aaddr[2][2];
    #pragma unroll
    for (int mt=0; mt<2; mt++) {
        int ar = w*32 + mt*16 + (lane & 7) + ((lane>>3)&1)*8;
        #pragma unroll
        for (int pl=0; pl<2; pl++)
            aaddr[mt][pl] = asmb + (unsigned)(pl*UA_PLANE + ar*48 + (lane>>4)*16);
    }

    for (int t = 0; t < NT; t++) {
        const float* Hin  = (t & 1) ? g_Hu1 : g_Hu0;
        float*       Hout = (t & 1) ? g_Hu0 : g_Hu1;
        const __nv_bfloat16* Rbf = (t & 1) ? g_HbfB : g_HbfA;
        __nv_bfloat16*       Wbf = (t & 1) ? g_HbfA : g_HbfB;

        float acc[2][6][4] = {};
        uint2 ph[4], plo[4];
        #pragma unroll
        for (int q=0; q<4; q++) {
            int idx = q*128 + tid, row = idx >> 2, kq = (idx & 3)*4;
            ph[q]  = *(const uint2*)(Rbf +      (long)(m0+row)*NH + kq);
            plo[q] = *(const uint2*)(Rbf + PL + (long)(m0+row)*NH + kq);
        }
        int buf = 0;
        for (int c = 0; c < 16; c++) {
            __nv_bfloat16* Ahi = Am + buf*6144;
            __nv_bfloat16* Alo = Ahi + 3072;
            #pragma unroll
            for (int q=0; q<4; q++) {
                int idx = q*128 + tid, row = idx >> 2, kq = (idx & 3)*4;
                *(uint2*)(Ahi + row*24 + kq) = ph[q];
                *(uint2*)(Alo + row*24 + kq) = plo[q];
            }
            __syncthreads();
            if (c < 15) {
                #pragma unroll
                for (int q=0; q<4; q++) {
                    int idx = q*128 + tid, row = idx >> 2, kq = (idx & 3)*4;
                    ph[q]  = *(const uint2*)(Rbf +      (long)(m0+row)*NH + (c+1)*16 + kq);
                    plo[q] = *(const uint2*)(Rbf + PL + (long)(m0+row)*NH + (c+1)*16 + kq);
                }
            }
            unsigned bfr[6][2][2];
            #pragma unroll
            for (int nt=0; nt<6; nt++)
                #pragma unroll
                for (int pl=0; pl<2; pl++)
                    ldsm2(bfr[nt][pl], baddr[nt][pl] + c*32);
            unsigned afr[2][2][4];
            #pragma unroll
            for (int mt=0; mt<2; mt++)
                #pragma unroll
                for (int pl=0; pl<2; pl++)
                    ldsm4(afr[mt][pl], aaddr[mt][pl] + buf*12288);
            #pragma unroll
            for (int mt=0; mt<2; mt++)
                #pragma unroll
                for (int nt=0; nt<6; nt++) {
                    mma16816(acc[mt][nt], afr[mt][0], bfr[nt][0]);
                    mma16816(acc[mt][nt], afr[mt][1], bfr[nt][0]);
                    mma16816(acc[mt][nt], afr[mt][0], bfr[nt][1]);
                }
            buf ^= 1;
        }
        #pragma unroll
        for (int mt=0; mt<2; mt++)
            #pragma unroll
            for (int rh=0; rh<2; rh++) {
                int m = m0 + w*32 + mt*16 + (lane>>2) + rh*8;
                int tok = tokens[m*NT + t];
                const float* gi = g_TG + (long)tok * G3;
                int fi = rh*2;
                #pragma unroll
                for (int jt2=0; jt2<2; jt2++) {
                    int jb2 = j0 + jt2*8 + (lane&3)*2;
                    float2 gr2 = *(const float2*)(gi + jb2);
                    float2 gz2 = *(const float2*)(gi + NH + jb2);
                    float2 gn2 = *(const float2*)(gi + 2*NH + jb2);
                    float2 ho  = *(const float2*)(Hin + (long)m*NH + jb2);
                    float r0 = 1.f/(1.f+expf(-(gr2.x + acc[mt][jt2][fi]   + bh[0][jt2][0])));
                    float z0 = 1.f/(1.f+expf(-(gz2.x + acc[mt][2+jt2][fi] + bh[1][jt2][0])));
                    float n0 = tanhf(gn2.x + r0*(acc[mt][4+jt2][fi] + bh[2][jt2][0]));
                    float h0 = (1.f - z0)*n0 + z0*ho.x;
                    float r1 = 1.f/(1.f+expf(-(gr2.y + acc[mt][jt2][fi+1]   + bh[0][jt2][1])));
                    float z1 = 1.f/(1.f+expf(-(gz2.y + acc[mt][2+jt2][fi+1] + bh[1][jt2][1])));
                    float n1 = tanhf(gn2.y + r1*(acc[mt][4+jt2][fi+1] + bh[2][jt2][1]));
                    float h1 = (1.f - z1)*n1 + z1*ho.y;
                    float2 hv; hv.x = h0; hv.y = h1;
                    *(float2*)(Hout + (long)m*NH + jb2) = hv;
                    __nv_bfloat16 b0 = __float2bfloat16(h0);
                    __nv_bfloat16 b1 = __float2bfloat16(h1);
                    __nv_bfloat162 hp; hp.x = b0; hp.y = b1;
                    *(__nv_bfloat162*)(Wbf + (long)m*NH + jb2) = hp;
                    __nv_bfloat162 lp;
                    lp.x = __float2bfloat16(h0 - __bfloat162float(b0));
                    lp.y = __float2bfloat16(h1 - __bfloat162float(b1));
                    *(__nv_bfloat162*)(Wbf + PL + (long)m*NH + jb2) = lp;
                }
            }
        if (t < NT-1) {
            __threadfence();
            __syncthreads();
            if (tid == 0) {
                unsigned target = (unsigned)UTILES * (t + 1);
                atomicAdd(&g_ubar, 1u);
                while (*(volatile unsigned*)&g_ubar < target) __nanosleep(64);
                __threadfence();
            }
            __syncthreads();
        }
    }
}

// ------------- fused tail: ctx(32) + SGI(32) + spk(32) + resp(48) -------------
extern __shared__ float tsm[];
__global__ __launch_bounds__(256) void k_tail(
    const float* __restrict__ cWhh, const float* __restrict__ cbhh,
    const float* __restrict__ sWih, const float* __restrict__ sbih,
    const float* __restrict__ sWhh, const float* __restrict__ sbhh,
    const float* __restrict__ rWhh, const float* __restrict__ rbhh,
    const int* __restrict__ spk, float* __restrict__ out)
{
    float* Wsm = tsm;                       // [48][260]
    float* Asm = tsm + 48*260;              // [48][260]
    int* flags = (int*)(tsm + 96*260);      // [32][51] (spk)
    int tid = threadIdx.x, bid = blockIdx.x;
    int role = (bid < 32) ? 0 : (bid < 64) ? 1 : (bid < 96) ? 2 : 3;
    int jt, m0, mcount;
    if (role < 3) {
        int rel = bid - role*32;
        jt = rel & 15; m0 = (rel >> 4) * 32; mcount = 32;
    } else {
        int rel = bid - 96;
        jt = rel & 15;
        int rt = rel >> 4;                   // 0..2
        m0 = rt * 43; mcount = (rt < 2) ? 43 : 42;
    }
    int j0 = jt*16;
    int tx = tid & 15, ty = tid >> 4;
    int j = j0 + tx;
    const float* W    = (role==0) ? cWhh : (role==1) ? sWih : (role==2) ? sWhh : rWhh;
    const float* bias = (role==0) ? cbhh : (role==1) ? sbih : (role==2) ? sbhh : rbhh;

    for (int i = tid; i < 48*64; i += 256) {
        int r = i >> 6, q = i & 63;
        int g = r >> 4, jj = r & 15;
        *(float4*)&Wsm[r*260 + q*4] = *(const float4*)(W + (long)(g*NH + j0 + jj)*NH + q*4);
    }
    float b0 = bias[j], b1 = bias[NH + j], b2 = bias[2*NH + j];
    if (role == 2) for (int i = tid; i < 32*51; i += 256) flags[i] = 0;
    __syncthreads();

    for (int it = 0; it < NS + 2; ++it) {
        int t = (role == 1) ? it - 1 : (role == 2) ? it - 2 : it;
        bool active = (t >= 0) && (t < NS);
        if (active) {
            if (role == 2) {
                for (int i = tid; i < 32*64; i += 256) {
                    int r = i >> 6, q = i & 63;
                    int b = m0 + r, a = spk[b*NS + t];
                    *(float4*)&Asm[r*260 + q*4] = *(const float4*)(g_Htab + ((long)b*NA + a)*NH + q*4);
                }
                if (tid < 32) flags[tid*51 + spk[(m0+tid)*NS + t]] = 1;
            } else if (role == 1) {
                for (int i = tid; i < 32*64; i += 256) {
                    int r = i >> 6, q = i & 63;
                    *(float4*)&Asm[r*260 + q*4] =
                        *(const float4*)(out + O_CTXOUT + ((long)t*64 + m0 + r)*NH + q*4);
                }
            } else if (role == 3) {
                for (int i = tid; i < 48*64; i += 256) {
                    int r = i >> 6, q = i & 63;
                    float4 v = make_float4(0.f,0.f,0.f,0.f);
                    if (r < mcount && t > 0) {
                        int m = m0 + r;
                        v = *(const float4*)(out + O_RESPOUT +
                              (((long)(m&1)*NT + (t-1))*64 + (m>>1))*NH + q*4);
                    }
                    *(float4*)&Asm[r*260 + q*4] = v;
                }
            } else if (t == 0) {
                for (int i = tid; i < 32*64; i += 256) {
                    int r = i >> 6, q = i & 63;
                    *(float4*)&Asm[r*260 + q*4] = make_float4(0.f,0.f,0.f,0.f);
                }
            } else {
                for (int i = tid; i < 32*64; i += 256) {
                    int r = i >> 6, q = i & 63;
                    *(float4*)&Asm[r*260 + q*4] =
                        *(const float4*)(out + O_CTXOUT + ((long)(t-1)*64 + m0 + r)*NH + q*4);
                }
            }
            __syncthreads();

            if (role == 3) {
                // up to 3 rows/thread: rows ty, ty+16, ty+32
                ull acc2[3][3] = {};
                #pragma unroll 4
                for (int k0 = 0; k0 < NH; k0 += 4) {
                    ulonglong2 w0 = *(const ulonglong2*)&Wsm[tx*260 + k0];
                    ulonglong2 w1 = *(const ulonglong2*)&Wsm[(16+tx)*260 + k0];
                    ulonglong2 w2 = *(const ulonglong2*)&Wsm[(32+tx)*260 + k0];
                    #pragma unroll
                    for (int r = 0; r < 3; r++) {
                        ulonglong2 a = *(const ulonglong2*)&Asm[(ty + r*16)*260 + k0];
                        ffma2(acc2[0][r], a.x, w0.x); ffma2(acc2[0][r], a.y, w0.y);
                        ffma2(acc2[1][r], a.x, w1.x); ffma2(acc2[1][r], a.y, w1.y);
                        ffma2(acc2[2][r], a.x, w2.x); ffma2(acc2[2][r], a.y, w2.y);
                    }
                }
                #pragma unroll
                for (int r = 0; r < 3; r++) {
                    int lr = ty + r*16;
                    if (lr < mcount) {
                        int m = m0 + lr;
                        float a0, a1, a2;
                        { float2 u = unpack2(acc2[0][r]); a0 = u.x + u.y; }
                        { float2 u = unpack2(acc2[1][r]); a1 = u.x + u.y; }
                        { float2 u = unpack2(acc2[2][r]); a2 = u.x + u.y; }
                        const float* gi = g_RGI + ((long)t*128 + m)*G3;
                        float rr = 1.f/(1.f+expf(-(gi[j]      + a0 + b0)));
                        float zz = 1.f/(1.f+expf(-(gi[NH+j]   + a1 + b1)));
                        float nn = tanhf(gi[2*NH+j] + rr*(a2 + b2));
                        float hp = Asm[lr*260 + j];
                        float hn = (1.f - zz)*nn + zz*hp;
                        out[O_RESPOUT + (((long)(m&1)*NT + t)*64 + (m>>1))*NH + j] = hn;
                        if (t == NS-1) out[O_RESPHID + ((long)(m&1)*64 + (m>>1))*NH + j] = hn;
                    }
                }
            } else {
                ull acc2[3][2] = {};
                #pragma unroll 4
                for (int k0 = 0; k0 < NH; k0 += 4) {
                    ulonglong2 w0 = *(const ulonglong2*)&Wsm[tx*260 + k0];
                    ulonglong2 w1 = *(const ulonglong2*)&Wsm[(16+tx)*260 + k0];
                    ulonglong2 w2 = *(const ulonglong2*)&Wsm[(32+tx)*260 + k0];
                    #pragma unroll
                    for (int r = 0; r < 2; r++) {
                        ulonglong2 a = *(const ulonglong2*)&Asm[(ty*2+r)*260 + k0];
                        ffma2(acc2[0][r], a.x, w0.x); ffma2(acc2[0][r], a.y, w0.y);
                        ffma2(acc2[1][r], a.x, w1.x); ffma2(acc2[1][r], a.y, w1.y);
                        ffma2(acc2[2][r], a.x, w2.x); ffma2(acc2[2][r], a.y, w2.y);
                    }
                }
                float acc[3][2];
                #pragma unroll
                for (int g=0; g<3; g++)
                    #pragma unroll
                    for (int r=0; r<2; r++) { float2 u = unpack2(acc2[g][r]); acc[g][r] = u.x + u.y; }

                if (role == 1) {
                    #pragma unroll
                    for (int r = 0; r < 2; r++) {
                        int m = m0 + ty*2 + r;
                        float* o = g_SGI + ((long)t*64 + m)*G3;
                        o[j] = acc[0][r] + b0; o[NH+j] = acc[1][r] + b1; o[2*NH+j] = acc[2][r] + b2;
                    }
                } else {
                    #pragma unroll
                    for (int r = 0; r < 2; r++) {
                        int lr = ty*2 + r, m = m0 + lr;
                        const float* gi = (role == 0) ? g_CGI + ((long)t*64 + m)*G3
                                        :               g_SGI + ((long)t*64 + m)*G3;
                        float rr = 1.f/(1.f+expf(-(gi[j]      + acc[0][r] + b0)));
                        float zz = 1.f/(1.f+expf(-(gi[NH+j]   + acc[1][r] + b1)));
                        float nn = tanhf(gi[2*NH+j] + rr*(acc[2][r] + b2));
                        float hp = Asm[lr*260 + j];
                        float hn = (1.f - zz)*nn + zz*hp;
                        if (role == 0) {
                            out[O_CTXOUT + ((long)t*64 + m)*NH + j] = hn;
                            if (t == NS-1) out[O_CTXHID + (long)m*NH + j] = hn;
                        } else {
                            int a = spk[m*NS + t];
                            g_Htab[((long)m*NA + a)*NH + j] = hn;
                        }
                    }
                }
            }
        }
        if (it < NS + 1) {
            __threadfence();
            __syncthreads();
            if (tid == 0) {
                atomicAdd(&g_tbar, 1u);
                unsigned target = (unsigned)TBLOCKS * (it + 1);
                while (*(volatile unsigned*)&g_tbar < target) __nanosleep(64);
                __threadfence();
            }
            __syncthreads();
        } else {
            __syncthreads();
        }
    }

    if (role == 2) {
        for (int a = 0; a < NA; a++) {
            #pragma unroll
            for (int r = 0; r < 2; r++) {
                int lb = ty*2 + r, b = m0 + lb;
                float v = flags[lb*51 + a] ? g_Htab[((long)b*NA + a)*NH + j] : 0.f;
                out[O_SPKEMB + ((long)b*NA + a)*NH + j] = v;
            }
        }
        if (jt == 0) {
            for (int i = tid; i < 32*NA; i += 256) {
                int r = i / NA, a = i % NA;
                out[O_SPKMASK + (m0+r)*NA + a] = (flags[r*51 + a] && a > 0) ? 1.f : 0.f;
            }
        }
    }
}

// ------------- ctx GRU input: concat(utter_hidden, agent_emb) -------------
__global__ void k_cin(const int* __restrict__ spk) {
    int idx = blockIdx.x * 256 + threadIdx.x;
    int c = idx & 511, mr = idx >> 9;
    int s = mr >> 6, b = mr & 63;
    float v;
    if (c < NH) v = g_Hu0[(b*NS + s)*NH + c];
    else        v = g_tables[(b*NA + spk[b*NS + s])*NH + (c - NH)];
    g_CIN[idx] = v;
}

// ------------- launch -------------
extern "C" void kernel_launch(void* const* d_in, const int* in_sizes, int n_in,
                              void* d_out, int out_size) {
    (void)in_sizes; (void)n_in; (void)out_size;
    const int*   context = (const int*)d_in[0];
    const int*   response= (const int*)d_in[1];
    const int*   spk     = (const int*)d_in[2];
    const float* emb_u   = (const float*)d_in[3];
    const float* emb_r   = (const float*)d_in[4];
    const float* uWih=(const float*)d_in[5],  *uWhh=(const float*)d_in[6];
    const float* ubih=(const float*)d_in[7],  *ubhh=(const float*)d_in[8];
    const float* cWih=(const float*)d_in[9],  *cWhh=(const float*)d_in[10];
    const float* cbih=(const float*)d_in[11], *cbhh=(const float*)d_in[12];
    const float* rWih=(const float*)d_in[13], *rWhh=(const float*)d_in[14];
    const float* rbih=(const float*)d_in[15], *rbhh=(const float*)d_in[16];
    const float* sWih=(const float*)d_in[17], *sWhh=(const float*)d_in[18];
    const float* sbih=(const float*)d_in[19], *sbhh=(const float*)d_in[20];
    float* out = (float*)d_out;

    void *pTab, *pTG, *pHu0, *pCIN, *pCGI, *pRGI, *pBar, *pTbar, *pHtab, *pBfA;
    void *pEbf, *pWubf, *pWcbf, *pCINbf;
    cudaGetSymbolAddress(&pTab, g_tables);
    cudaGetSymbolAddress(&pTG,  g_TG);
    cudaGetSymbolAddress(&pHu0, g_Hu0);
    cudaGetSymbolAddress(&pCIN, g_CIN);
    cudaGetSymbolAddress(&pCGI, g_CGI);
    cudaGetSymbolAddress(&pRGI, g_RGI);
    cudaGetSymbolAddress(&pBar, g_ubar);
    cudaGetSymbolAddress(&pTbar, g_tbar);
    cudaGetSymbolAddress(&pHtab, g_Htab);
    cudaGetSymbolAddress(&pBfA, g_HbfA);
    cudaGetSymbolAddress(&pEbf, g_Ebf);
    cudaGetSymbolAddress(&pWubf, g_Wubf);
    cudaGetSymbolAddress(&pWcbf, g_Wcbf);
    cudaGetSymbolAddress(&pCINbf, g_CINbf);

    cudaFuncSetAttribute(k_ustep_mma, cudaFuncAttributeMaxDynamicSharedMemorySize, USMEM2);
    cudaFuncSetAttribute(k_gemmtc,    cudaFuncAttributeMaxDynamicSharedMemorySize, GCSMEM);
    cudaFuncSetAttribute(k_tail,      cudaFuncAttributeMaxDynamicSharedMemorySize, TSMEM);

    cudaMemcpyAsync(pTab, h_tables, sizeof(h_tables), cudaMemcpyHostToDevice, 0);
    cudaMemsetAsync(pHu0, 0, (size_t)NB*NS*NH*sizeof(float), 0);
    cudaMemsetAsync(pBfA, 0, (size_t)2*PL*sizeof(__nv_bfloat16), 0);
    cudaMemsetAsync(pBar, 0, sizeof(unsigned), 0);
    cudaMemsetAsync(pTbar, 0, sizeof(unsigned), 0);
    cudaMemsetAsync(pHtab, 0, (size_t)NB*NA*NH*sizeof(float), 0);

    // fork: RGI gemm (independent) on s2
    cudaEventRecord(g_evFork, 0);
    cudaStreamWaitEvent(g_s2, g_evFork, 0);
    k_gemm128<<<dim3(50, 6), 256, 0, g_s2>>>(emb_r, response, NH, rWih, rbih, (float*)pRGI);
    cudaEventRecord(g_evJoin, g_s2);

    // TG = emb_u @ uWih^T + ubih on tensor cores (bf16 hi/lo)
    __nv_bfloat16* Ebf   = (__nv_bfloat16*)pEbf;
    __nv_bfloat16* Wubf  = (__nv_bfloat16*)pWubf;
    __nv_bfloat16* Wcbf  = (__nv_bfloat16*)pWcbf;
    __nv_bfloat16* CINbf = (__nv_bfloat16*)pCINbf;
    k_cvt<<<(NV*NH/4 + 255)/256, 256>>>(emb_u, Ebf, Ebf + (long)NV*NH, NV*NH/4);
    k_cvt<<<(G3*NH/4 + 255)/256, 256>>>(uWih, Wubf, Wubf + G3*NH, G3*NH/4);
    k_cvt<<<(G3*2*NH/4 + 255)/256, 256>>>(cWih, Wcbf, Wcbf + (long)G3*2*NH, G3*2*NH/4);
    k_gemmtc<<<dim3(12, NV/128), 128, GCSMEM>>>(Ebf, (long)NV*NH, Wubf, (long)G3*NH, ubih, (float*)pTG, NH);

    // persistent tensor-core utterance recurrence
    k_ustep_mma<<<dim3(25, 16), 128, USMEM2>>>(uWhh, ubhh, context);

    // ctx input + CGI gemm on tensor cores (K=512)
    k_cin<<<6400, 256>>>(spk);
    k_cvt<<<(NS*NB*2*NH/4 + 255)/256, 256>>>((const float*)pCIN, CINbf,
                                             CINbf + (long)NS*NB*2*NH, NS*NB*2*NH/4);
    k_gemmtc<<<dim3(12, 25), 128, GCSMEM>>>(CINbf, (long)NS*NB*2*NH, Wcbf, (long)G3*2*NH,
                                            cbih, (float*)pCGI, 2*NH);

    // fused tail (needs RGI)
    cudaStreamWaitEvent(0, g_evJoin, 0);
    k_tail<<<TBLOCKS, 256, TSMEM>>>(cWhh, cbhh, sWih, sbih, sWhh, sbhh, rWhh, rbhh, spk, out);
}